// round 3
// baseline (speedup 1.0000x reference)
#include <cuda_runtime.h>
#include <math.h>

// Problem constants (fixed shapes from setup_inputs)
#define NTOK 2048
#define CDIM 1024
#define HEADS 16
#define DH 64
#define FF 4096
#define NSRC 1024   // NTOK/2

// ---------------- scratch (device globals; no allocation allowed) ------------
__device__ float g_h   [NTOK*CDIM];
__device__ float g_qkv [NTOK*3*CDIM];
__device__ float g_nmet[NTOK*DH];
__device__ float g_xa  [NTOK*CDIM];
__device__ float g_x1  [NTOK*CDIM];
__device__ int   g_mask[NSRC];
__device__ int   g_node[NSRC];
__device__ int   g_pref[NSRC];
__device__ int   g_nUnm[1];
__device__ float g_outx[NTOK*CDIM];
__device__ float g_outs[NTOK];
__device__ float g_x2  [NTOK*CDIM];
__device__ float g_h2  [NTOK*CDIM];
__device__ float g_ff  [NTOK*FF];
__device__ float g_xout[NTOK*CDIM];

// ---------------- layernorm ------------------------------------------------
__global__ __launch_bounds__(256) void ln_kernel(
    const float* __restrict__ x, const float* __restrict__ g,
    const float* __restrict__ b, float* __restrict__ out, int M)
{
    int row = blockIdx.x;
    if (row >= M) return;
    const float* xr = x + (size_t)row * CDIM;
    int tid = threadIdx.x;
    float v[4];
    float s = 0.f, sq = 0.f;
#pragma unroll
    for (int t = 0; t < 4; t++) {
        float vv = xr[tid + t*256];
        v[t] = vv; s += vv; sq += vv*vv;
    }
    __shared__ float rs[256], rq[256];
    rs[tid] = s; rq[tid] = sq;
    __syncthreads();
    for (int off = 128; off > 0; off >>= 1) {
        if (tid < off) { rs[tid] += rs[tid+off]; rq[tid] += rq[tid+off]; }
        __syncthreads();
    }
    float mean = rs[0] * (1.f/CDIM);
    float var  = rq[0] * (1.f/CDIM) - mean*mean;
    float rstd = rsqrtf(var + 1e-5f);
    float* orow = out + (size_t)row * CDIM;
#pragma unroll
    for (int t = 0; t < 4; t++) {
        int c = tid + t*256;
        orow[c] = (v[t] - mean) * rstd * g[c] + b[c];
    }
}

// ---------------- generic 128x128x8 SGEMM with fused epilogues ---------------
// EPI: 0 = C = A@B ; 1 = +bias ; 2 = gelu(A@B + bias) ; 3 = A@B + bias + res
__device__ __forceinline__ float gelu_exact(float v) {
    return 0.5f * v * (1.0f + erff(v * 0.70710678118654752440f));
}

template <int EPI>
__global__ __launch_bounds__(256) void gemm_kernel(
    const float* __restrict__ A, const float* __restrict__ B,
    const float* __restrict__ bias, const float* __restrict__ res,
    float* __restrict__ C, int M, int N, int K)
{
    __shared__ float As[8][128];
    __shared__ float Bs[8][128];
    int tid = threadIdx.x;
    int tx = tid & 15, ty = tid >> 4;
    int m0 = blockIdx.y * 128, n0 = blockIdx.x * 128;
    float acc[8][8];
#pragma unroll
    for (int i = 0; i < 8; i++)
#pragma unroll
        for (int j = 0; j < 8; j++) acc[i][j] = 0.f;

    int aRow = tid >> 1;
    int aCol = (tid & 1) * 4;
    int bRow = tid >> 5;
    int bCol = (tid & 31) * 4;
    const bool aval = (m0 + aRow) < M;
    const float* aPtr = A + (size_t)(m0 + aRow) * K + aCol;
    const float* bPtr = B + (size_t)bRow * N + n0 + bCol;

    for (int k0 = 0; k0 < K; k0 += 8) {
        float4 av = make_float4(0.f, 0.f, 0.f, 0.f);
        if (aval) av = *(const float4*)(aPtr + k0);
        As[aCol+0][aRow] = av.x; As[aCol+1][aRow] = av.y;
        As[aCol+2][aRow] = av.z; As[aCol+3][aRow] = av.w;
        *(float4*)&Bs[bRow][bCol] = *(const float4*)(bPtr + (size_t)k0 * N);
        __syncthreads();
#pragma unroll
        for (int k = 0; k < 8; k++) {
            float a[8], bb[8];
            *(float4*)&a[0]  = *(float4*)&As[k][ty*8];
            *(float4*)&a[4]  = *(float4*)&As[k][ty*8+4];
            *(float4*)&bb[0] = *(float4*)&Bs[k][tx*8];
            *(float4*)&bb[4] = *(float4*)&Bs[k][tx*8+4];
#pragma unroll
            for (int i = 0; i < 8; i++)
#pragma unroll
                for (int j = 0; j < 8; j++)
                    acc[i][j] = fmaf(a[i], bb[j], acc[i][j]);
        }
        __syncthreads();
    }

#pragma unroll
    for (int i = 0; i < 8; i++) {
        int row = m0 + ty*8 + i;
        if (row >= M) continue;
#pragma unroll
        for (int j = 0; j < 8; j++) {
            int col = n0 + tx*8 + j;
            float v = acc[i][j];
            if (EPI >= 1) v += bias[col];
            if (EPI == 2) v = gelu_exact(v);
            if (EPI == 3) v += res[(size_t)row * N + col];
            C[(size_t)row * N + col] = v;
        }
    }
}

// ---------------- metric = mean_h(k), then L2-normalize ----------------------
__global__ __launch_bounds__(64) void metric_kernel()
{
    int n = blockIdx.x, d = threadIdx.x;
    const float* base = g_qkv + (size_t)n * (3*CDIM) + CDIM + d;
    float s = 0.f;
#pragma unroll
    for (int h = 0; h < HEADS; h++) s += base[h * DH];
    s *= (1.f / HEADS);
    __shared__ float sq[64];
    sq[d] = s * s;
    __syncthreads();
    if (d < 32) sq[d] += sq[d+32]; __syncthreads();
    if (d < 16) sq[d] += sq[d+16]; __syncthreads();
    if (d < 8)  sq[d] += sq[d+8];  __syncthreads();
    if (d < 4)  sq[d] += sq[d+4];  __syncthreads();
    if (d < 2)  sq[d] += sq[d+2];  __syncthreads();
    if (d < 1)  sq[d] += sq[d+1];  __syncthreads();
    float nrm = sqrtf(sq[0]);
    g_nmet[(size_t)n * DH + d] = s / nrm;
}

// ---------------- flash attention (64q x 64k tiles, dh=64) -------------------
#define AP 68   // smem pitch (floats); 68*4=272 B, 16B-aligned, conflict-breaking

__global__ __launch_bounds__(256) void attn_kernel(
    const float* __restrict__ qkv, const float* __restrict__ sizev,
    float* __restrict__ xa)
{
    extern __shared__ float sm[];
    float* QsT  = sm;               // [d][q]
    float* KsT  = sm + 64*AP;       // [d][k]
    float* Vs   = sm + 2*64*AP;     // [k][d]
    float* PT   = sm + 3*64*AP;     // [k][q]
    float* rowM = sm + 4*64*AP;
    float* rowL = rowM + 64;
    float* rowC = rowL + 64;
    float* logs = rowC + 64;

    int tid = threadIdx.x;
    int tx = tid & 15, ty = tid >> 4;
    int h = blockIdx.y;
    int q0 = blockIdx.x * 64;

    { // load Q tile transposed
        int q = tid & 63, chunk = tid >> 6;
        const float* src = qkv + (size_t)(q0 + q) * (3*CDIM) + h*DH + chunk*16;
#pragma unroll
        for (int f = 0; f < 4; f++) {
            float4 v = *(const float4*)(src + f*4);
            int d = chunk*16 + f*4;
            QsT[(d+0)*AP + q] = v.x; QsT[(d+1)*AP + q] = v.y;
            QsT[(d+2)*AP + q] = v.z; QsT[(d+3)*AP + q] = v.w;
        }
    }
    if (tid < 64) { rowM[tid] = -3.0e38f; rowL[tid] = 0.f; }

    float O[4][4];
#pragma unroll
    for (int i = 0; i < 4; i++)
#pragma unroll
        for (int j = 0; j < 4; j++) O[i][j] = 0.f;

    for (int kt = 0; kt < NTOK/64; kt++) {
        int k0 = kt * 64;
        __syncthreads();  // protect previous-iteration smem reads
        { // load K (transposed) and V tiles
            int kk = tid & 63, chunk = tid >> 6;
            const float* ksrc = qkv + (size_t)(k0 + kk)*(3*CDIM) + CDIM   + h*DH + chunk*16;
            const float* vsrc = qkv + (size_t)(k0 + kk)*(3*CDIM) + 2*CDIM + h*DH + chunk*16;
#pragma unroll
            for (int f = 0; f < 4; f++) {
                float4 kv = *(const float4*)(ksrc + f*4);
                int d = chunk*16 + f*4;
                KsT[(d+0)*AP + kk] = kv.x; KsT[(d+1)*AP + kk] = kv.y;
                KsT[(d+2)*AP + kk] = kv.z; KsT[(d+3)*AP + kk] = kv.w;
                *(float4*)&Vs[kk*AP + d] = *(const float4*)(vsrc + f*4);
            }
            if (tid < 64) logs[tid] = logf(sizev[k0 + tid]);
        }
        __syncthreads();

        // S = Q @ K^T
        float s[4][4];
#pragma unroll
        for (int i = 0; i < 4; i++)
#pragma unroll
            for (int j = 0; j < 4; j++) s[i][j] = 0.f;
#pragma unroll 8
        for (int d = 0; d < 64; d++) {
            float4 a = *(float4*)&QsT[d*AP + ty*4];
            float4 b = *(float4*)&KsT[d*AP + tx*4];
            float aa[4] = {a.x, a.y, a.z, a.w};
            float bb[4] = {b.x, b.y, b.z, b.w};
#pragma unroll
            for (int i = 0; i < 4; i++)
#pragma unroll
                for (int j = 0; j < 4; j++)
                    s[i][j] = fmaf(aa[i], bb[j], s[i][j]);
        }
        float lj[4];
#pragma unroll
        for (int j = 0; j < 4; j++) lj[j] = logs[tx*4 + j];
#pragma unroll
        for (int i = 0; i < 4; i++)
#pragma unroll
            for (int j = 0; j < 4; j++)
                PT[(tx*4 + j)*AP + (ty*4 + i)] = s[i][j] * 0.125f + lj[j];
        __syncthreads();

        // online softmax (row-wise), P stored back into PT
        if (tid < 64) {
            int r = tid;
            float m = rowM[r];
            float mx = m;
            for (int kk = 0; kk < 64; kk++) mx = fmaxf(mx, PT[kk*AP + r]);
            float c = expf(m - mx);
            float l = rowL[r] * c;
            for (int kk = 0; kk < 64; kk++) {
                float p = expf(PT[kk*AP + r] - mx);
                PT[kk*AP + r] = p;
                l += p;
            }
            rowM[r] = mx; rowL[r] = l; rowC[r] = c;
        }
        __syncthreads();

        // rescale and O += P @ V
#pragma unroll
        for (int i = 0; i < 4; i++) {
            float c = rowC[ty*4 + i];
#pragma unroll
            for (int j = 0; j < 4; j++) O[i][j] *= c;
        }
#pragma unroll 8
        for (int kk = 0; kk < 64; kk++) {
            float4 p = *(float4*)&PT[kk*AP + ty*4];
            float4 v = *(float4*)&Vs[kk*AP + tx*4];
            float pp[4] = {p.x, p.y, p.z, p.w};
            float vv[4] = {v.x, v.y, v.z, v.w};
#pragma unroll
            for (int i = 0; i < 4; i++)
#pragma unroll
                for (int j = 0; j < 4; j++)
                    O[i][j] = fmaf(pp[i], vv[j], O[i][j]);
        }
    }

#pragma unroll
    for (int i = 0; i < 4; i++) {
        int q = q0 + ty*4 + i;
        float inv = 1.f / rowL[ty*4 + i];
#pragma unroll
        for (int j = 0; j < 4; j++)
            xa[(size_t)q * CDIM + h*DH + tx*4 + j] = O[i][j] * inv;
    }
}

// ---------------- merge scoring: per-src max/argmax over dst -----------------
__global__ __launch_bounds__(256) void merge_score_kernel(const float* __restrict__ thr)
{
    int i = blockIdx.x, tid = threadIdx.x;
    __shared__ float srcv[64];
    if (tid < 64) srcv[tid] = g_nmet[(size_t)(2*i) * DH + tid];
    __syncthreads();
    float best = -3.0e38f; int bestj = 0;
    for (int j = tid; j < NSRC; j += 256) {
        const float* dv = g_nmet + (size_t)(2*j + 1) * DH;
        float dot = 0.f;
#pragma unroll
        for (int d = 0; d < 64; d++) dot = fmaf(srcv[d], dv[d], dot);
        if (dot > best) { best = dot; bestj = j; }   // ascending j => first-max kept
    }
    __shared__ float bm[256]; __shared__ int bi[256];
    bm[tid] = best; bi[tid] = bestj;
    __syncthreads();
    for (int off = 128; off > 0; off >>= 1) {
        if (tid < off) {
            if (bm[tid+off] > bm[tid] ||
                (bm[tid+off] == bm[tid] && bi[tid+off] < bi[tid])) {
                bm[tid] = bm[tid+off]; bi[tid] = bi[tid+off];
            }
        }
        __syncthreads();
    }
    if (tid == 0) {
        if (i == 0) { g_mask[0] = 0; g_node[0] = 0; }  // row 0 forced -inf
        else { g_mask[i] = (bm[0] > thr[0]) ? 1 : 0; g_node[i] = bi[0]; }
    }
}

// ---------------- exclusive prefix scan of !mask -----------------------------
__global__ __launch_bounds__(1024) void scan_kernel()
{
    __shared__ int s[NSRC];
    int tid = threadIdx.x;
    int f = g_mask[tid] ? 0 : 1;
    s[tid] = f;
    __syncthreads();
    for (int off = 1; off < NSRC; off <<= 1) {
        int v = 0;
        if (tid >= off) v = s[tid - off];
        __syncthreads();
        s[tid] += v;
        __syncthreads();
    }
    g_pref[tid] = s[tid] - f;
    if (tid == NSRC-1) g_nUnm[0] = s[NSRC-1];
}

// ---------------- build unmerged rows ----------------------------------------
__global__ __launch_bounds__(256) void unm_kernel(const float* __restrict__ sizev)
{
    int i = blockIdx.x;
    if (g_mask[i]) return;
    int r = g_pref[i];
    float s = sizev[2*i];
    const float* xr = g_x1 + (size_t)(2*i) * CDIM;
    float* orow = g_outx + (size_t)r * CDIM;
    for (int c = threadIdx.x; c < CDIM; c += 256) orow[c] = xr[c] * s;
    if (threadIdx.x == 0) g_outs[r] = s;
}

// ---------------- build dst rows (deterministic gather of merges) ------------
__global__ __launch_bounds__(256) void dst_build_kernel(const float* __restrict__ sizev)
{
    int j = blockIdx.x, tid = threadIdx.x;
    int nU = g_nUnm[0];
    float s0 = sizev[2*j + 1];
    const float* dr = g_x1 + (size_t)(2*j + 1) * CDIM;
    float a0 = dr[tid]       * s0;
    float a1 = dr[tid + 256] * s0;
    float a2 = dr[tid + 512] * s0;
    float a3 = dr[tid + 768] * s0;
    float stot = s0;
    for (int i = 0; i < NSRC; i++) {
        if (g_mask[i] && g_node[i] == j) {
            float si = sizev[2*i];
            const float* xr = g_x1 + (size_t)(2*i) * CDIM;
            a0 += xr[tid]       * si;
            a1 += xr[tid + 256] * si;
            a2 += xr[tid + 512] * si;
            a3 += xr[tid + 768] * si;
            stot += si;
        }
    }
    size_t r = (size_t)(nU + j) * CDIM;
    g_outx[r + tid]       = a0;
    g_outx[r + tid + 256] = a1;
    g_outx[r + tid + 512] = a2;
    g_outx[r + tid + 768] = a3;
    if (tid == 0) g_outs[nU + j] = stot;
}

// ---------------- x2 = outx / size -------------------------------------------
__global__ __launch_bounds__(256) void div_kernel()
{
    int r = blockIdx.x;
    float s = g_outs[r];
    for (int c = threadIdx.x; c < CDIM; c += 256)
        g_x2[(size_t)r * CDIM + c] = g_outx[(size_t)r * CDIM + c] / s;
}

// ---------------- pack output [x rows | size] --------------------------------
__global__ __launch_bounds__(256) void out_copy_kernel(float* __restrict__ out,
                                                       int Nout, int packSize)
{
    int idx = blockIdx.x * 256 + threadIdx.x;
    int totalx = Nout * CDIM;
    if (idx < totalx) out[idx] = g_xout[idx];
    else if (packSize && idx < totalx + Nout) out[idx] = g_outs[idx - totalx];
}

// ---------------- launcher ---------------------------------------------------
extern "C" void kernel_launch(void* const* d_in, const int* in_sizes, int n_in,
                              void* d_out, int out_size)
{
    const float* x      = (const float*)d_in[0];
    const float* sizev  = (const float*)d_in[1];
    const float* qkv_w  = (const float*)d_in[2];
    const float* proj_w = (const float*)d_in[3];
    const float* proj_b = (const float*)d_in[4];
    const float* ln1_g  = (const float*)d_in[5];
    const float* ln1_b  = (const float*)d_in[6];
    const float* ln2_g  = (const float*)d_in[7];
    const float* ln2_b  = (const float*)d_in[8];
    const float* fc1_w  = (const float*)d_in[9];
    const float* fc1_b  = (const float*)d_in[10];
    const float* fc2_w  = (const float*)d_in[11];
    const float* fc2_b  = (const float*)d_in[12];
    const float* thr    = (const float*)d_in[13];
    float* out = (float*)d_out;

    // Output token count from out_size: (x: Nout*1024) + (size: Nout)
    int Nout, packSize;
    if (out_size % (CDIM + 1) == 0) { Nout = out_size / (CDIM + 1); packSize = 1; }
    else                            { Nout = out_size / CDIM;       packSize = 0; }
    if (Nout > NTOK) Nout = NTOK;

    float *p_h, *p_qkv, *p_xa, *p_x1, *p_x2, *p_h2, *p_ff, *p_xout;
    cudaGetSymbolAddress((void**)&p_h,    g_h);
    cudaGetSymbolAddress((void**)&p_qkv,  g_qkv);
    cudaGetSymbolAddress((void**)&p_xa,   g_xa);
    cudaGetSymbolAddress((void**)&p_x1,   g_x1);
    cudaGetSymbolAddress((void**)&p_x2,   g_x2);
    cudaGetSymbolAddress((void**)&p_h2,   g_h2);
    cudaGetSymbolAddress((void**)&p_ff,   g_ff);
    cudaGetSymbolAddress((void**)&p_xout, g_xout);

    const int ATTN_SMEM = (4*64*AP + 4*64) * (int)sizeof(float);
    cudaFuncSetAttribute(attn_kernel, cudaFuncAttributeMaxDynamicSharedMemorySize, ATTN_SMEM);

    // 1. LN1
    ln_kernel<<<NTOK, 256>>>(x, ln1_g, ln1_b, p_h, NTOK);
    // 2. QKV = h @ qkv_w   (2048 x 3072 x 1024)
    gemm_kernel<0><<<dim3(3*CDIM/128, NTOK/128), 256>>>(
        p_h, qkv_w, nullptr, nullptr, p_qkv, NTOK, 3*CDIM, CDIM);
    // 3. metric = normalize(mean_h k)
    metric_kernel<<<NTOK, 64>>>();
    // 4. attention -> xa
    attn_kernel<<<dim3(NTOK/64, HEADS), 256, ATTN_SMEM>>>(p_qkv, sizev, p_xa);
    // 5. x1 = x + xa @ proj_w + proj_b
    gemm_kernel<3><<<dim3(CDIM/128, NTOK/128), 256>>>(
        p_xa, proj_w, proj_b, x, p_x1, NTOK, CDIM, CDIM);
    // 6. merge scores (max/argmax per src)
    merge_score_kernel<<<NSRC, 256>>>(thr);
    // 7. prefix scan of unmerged
    scan_kernel<<<1, 1024>>>();
    // 8. gather unmerged rows of xs = x1 * size
    unm_kernel<<<NSRC, 256>>>(sizev);
    // 9. build dst rows (+ merged adds, ascending-i deterministic)
    dst_build_kernel<<<NSRC, 256>>>(sizev);
    // 10. x2 = outx / size
    div_kernel<<<Nout, 256>>>();
    // 11. LN2
    ln_kernel<<<Nout, 256>>>(p_x2, ln2_g, ln2_b, p_h2, Nout);
    // 12. ff = gelu(h2 @ fc1_w + fc1_b)
    gemm_kernel<2><<<dim3(FF/128, (Nout + 127)/128), 256>>>(
        p_h2, fc1_w, fc1_b, nullptr, p_ff, Nout, FF, CDIM);
    // 13. xout = x2 + ff @ fc2_w + fc2_b
    gemm_kernel<3><<<dim3(CDIM/128, (Nout + 127)/128), 256>>>(
        p_ff, fc2_w, fc2_b, p_x2, p_xout, Nout, CDIM, FF);
    // 14. pack output
    int totalOut = Nout * CDIM + (packSize ? Nout : 0);
    out_copy_kernel<<<(totalOut + 255)/256, 256>>>(out, Nout, packSize);
}

// round 4
// speedup vs baseline: 1.0766x; 1.0766x over previous
#include <cuda_runtime.h>
#include <math.h>

// Problem constants (fixed shapes from setup_inputs)
#define NTOK 2048
#define CDIM 1024
#define HEADS 16
#define DH 64
#define FF 4096
#define NSRC 1024   // NTOK/2

// ---------------- scratch (device globals; no allocation allowed) ------------
__device__ float g_h   [NTOK*CDIM];
__device__ float g_qkv [NTOK*3*CDIM];
__device__ float g_nmet[NTOK*DH];
__device__ float g_xa  [NTOK*CDIM];
__device__ float g_x1  [NTOK*CDIM];
__device__ int   g_mask[NSRC];
__device__ int   g_node[NSRC];
__device__ int   g_pref[NSRC];
__device__ int   g_nUnm[1];
__device__ float g_outx[NTOK*CDIM];
__device__ float g_outs[NTOK];
__device__ float g_x2  [NTOK*CDIM];
__device__ float g_h2  [NTOK*CDIM];
__device__ float g_ff  [NTOK*FF];
__device__ float g_xout[NTOK*CDIM];

// ---------------- layernorm ------------------------------------------------
__global__ __launch_bounds__(256) void ln_kernel(
    const float* __restrict__ x, const float* __restrict__ g,
    const float* __restrict__ b, float* __restrict__ out, int M)
{
    int row = blockIdx.x;
    if (row >= M) return;
    const float* xr = x + (size_t)row * CDIM;
    int tid = threadIdx.x;
    float v[4];
    float s = 0.f, sq = 0.f;
#pragma unroll
    for (int t = 0; t < 4; t++) {
        float vv = xr[tid + t*256];
        v[t] = vv; s += vv; sq += vv*vv;
    }
    __shared__ float rs[256], rq[256];
    rs[tid] = s; rq[tid] = sq;
    __syncthreads();
    for (int off = 128; off > 0; off >>= 1) {
        if (tid < off) { rs[tid] += rs[tid+off]; rq[tid] += rq[tid+off]; }
        __syncthreads();
    }
    float mean = rs[0] * (1.f/CDIM);
    float var  = rq[0] * (1.f/CDIM) - mean*mean;
    float rstd = rsqrtf(var + 1e-5f);
    float* orow = out + (size_t)row * CDIM;
#pragma unroll
    for (int t = 0; t < 4; t++) {
        int c = tid + t*256;
        orow[c] = (v[t] - mean) * rstd * g[c] + b[c];
    }
}

// ---------------- generic 128x128x8 SGEMM, double-buffered -------------------
// EPI: 0 = C = A@B ; 1 = +bias ; 2 = gelu(A@B + bias) ; 3 = A@B + bias + res
__device__ __forceinline__ float gelu_exact(float v) {
    return 0.5f * v * (1.0f + erff(v * 0.70710678118654752440f));
}

template <int EPI>
__global__ __launch_bounds__(256) void gemm_kernel(
    const float* __restrict__ A, const float* __restrict__ B,
    const float* __restrict__ bias, const float* __restrict__ res,
    float* __restrict__ C, int M, int N, int K)
{
    __shared__ float As[2][8][128];
    __shared__ float Bs[2][8][128];
    int tid = threadIdx.x;
    int tx = tid & 15, ty = tid >> 4;
    int m0 = blockIdx.y * 128, n0 = blockIdx.x * 128;
    float acc[8][8];
#pragma unroll
    for (int i = 0; i < 8; i++)
#pragma unroll
        for (int j = 0; j < 8; j++) acc[i][j] = 0.f;

    int aRow = tid >> 1;
    int aCol = (tid & 1) * 4;
    int bRow = tid >> 5;
    int bCol = (tid & 31) * 4;
    const bool aval = (m0 + aRow) < M;
    const float* aPtr = A + (size_t)(m0 + aRow) * K + aCol;
    const float* bPtr = B + (size_t)bRow * N + n0 + bCol;

    const int nTiles = K >> 3;

    // prefetch tile 0
    float4 av = make_float4(0.f,0.f,0.f,0.f);
    if (aval) av = *(const float4*)(aPtr);
    float4 bv = *(const float4*)(bPtr);
    As[0][aCol+0][aRow] = av.x; As[0][aCol+1][aRow] = av.y;
    As[0][aCol+2][aRow] = av.z; As[0][aCol+3][aRow] = av.w;
    *(float4*)&Bs[0][bRow][bCol] = bv;
    __syncthreads();

    for (int t = 0; t < nTiles; t++) {
        int buf = t & 1;
        if (t + 1 < nTiles) {
            int k0 = (t + 1) * 8;
            av = make_float4(0.f,0.f,0.f,0.f);
            if (aval) av = *(const float4*)(aPtr + k0);
            bv = *(const float4*)(bPtr + (size_t)k0 * N);
        }
#pragma unroll
        for (int k = 0; k < 8; k++) {
            float a[8], bb[8];
            *(float4*)&a[0]  = *(float4*)&As[buf][k][ty*8];
            *(float4*)&a[4]  = *(float4*)&As[buf][k][ty*8+4];
            *(float4*)&bb[0] = *(float4*)&Bs[buf][k][tx*8];
            *(float4*)&bb[4] = *(float4*)&Bs[buf][k][tx*8+4];
#pragma unroll
            for (int i = 0; i < 8; i++)
#pragma unroll
                for (int j = 0; j < 8; j++)
                    acc[i][j] = fmaf(a[i], bb[j], acc[i][j]);
        }
        if (t + 1 < nTiles) {
            int nb = buf ^ 1;
            As[nb][aCol+0][aRow] = av.x; As[nb][aCol+1][aRow] = av.y;
            As[nb][aCol+2][aRow] = av.z; As[nb][aCol+3][aRow] = av.w;
            *(float4*)&Bs[nb][bRow][bCol] = bv;
        }
        __syncthreads();
    }

#pragma unroll
    for (int i = 0; i < 8; i++) {
        int row = m0 + ty*8 + i;
        if (row >= M) continue;
        float* crow = C + (size_t)row * N + n0 + tx*8;
#pragma unroll
        for (int half = 0; half < 2; half++) {
            float4 v;
            float* vp = &v.x;
#pragma unroll
            for (int j = 0; j < 4; j++) {
                int col = n0 + tx*8 + half*4 + j;
                float t = acc[i][half*4 + j];
                if (EPI >= 1) t += bias[col];
                if (EPI == 2) t = gelu_exact(t);
                if (EPI == 3) t += res[(size_t)row * N + col];
                vp[j] = t;
            }
            *(float4*)(crow + half*4) = v;
        }
    }
}

// ---------------- metric = mean_h(k), then L2-normalize ----------------------
__global__ __launch_bounds__(64) void metric_kernel()
{
    int n = blockIdx.x, d = threadIdx.x;
    const float* base = g_qkv + (size_t)n * (3*CDIM) + CDIM + d;
    float s = 0.f;
#pragma unroll
    for (int h = 0; h < HEADS; h++) s += base[h * DH];
    s *= (1.f / HEADS);
    __shared__ float sq[64];
    sq[d] = s * s;
    __syncthreads();
    if (d < 32) sq[d] += sq[d+32]; __syncthreads();
    if (d < 16) sq[d] += sq[d+16]; __syncthreads();
    if (d < 8)  sq[d] += sq[d+8];  __syncthreads();
    if (d < 4)  sq[d] += sq[d+4];  __syncthreads();
    if (d < 2)  sq[d] += sq[d+2];  __syncthreads();
    if (d < 1)  sq[d] += sq[d+1];  __syncthreads();
    float nrm = sqrtf(sq[0]);
    g_nmet[(size_t)n * DH + d] = s / nrm;
}

// ---------------- flash attention (64q x 64k tiles, dh=64) -------------------
// Register-resident online softmax: each thread owns rows ty*4..ty*4+3,
// columns tx*4..tx*4+3; row reductions via shfl_xor over the 16 tx lanes.
#define AP 68   // smem pitch (floats)

__global__ __launch_bounds__(256) void attn_kernel(
    const float* __restrict__ qkv, const float* __restrict__ sizev,
    float* __restrict__ xa)
{
    extern __shared__ float sm[];
    float* QsT  = sm;               // [d][q], pre-scaled by 0.125
    float* KsT  = sm + 64*AP;       // [d][k]
    float* Vs   = sm + 2*64*AP;     // [k][d]
    float* PT   = sm + 3*64*AP;     // [k][q]
    float* logs = sm + 4*64*AP;     // [64]

    int tid = threadIdx.x;
    int tx = tid & 15, ty = tid >> 4;
    int h = blockIdx.y;
    int q0 = blockIdx.x * 64;

    { // load Q tile transposed, fold in 1/sqrt(dh)=0.125
        int q = tid & 63, chunk = tid >> 6;
        const float* src = qkv + (size_t)(q0 + q) * (3*CDIM) + h*DH + chunk*16;
#pragma unroll
        for (int f = 0; f < 4; f++) {
            float4 v = *(const float4*)(src + f*4);
            int d = chunk*16 + f*4;
            QsT[(d+0)*AP + q] = v.x * 0.125f; QsT[(d+1)*AP + q] = v.y * 0.125f;
            QsT[(d+2)*AP + q] = v.z * 0.125f; QsT[(d+3)*AP + q] = v.w * 0.125f;
        }
    }

    float rowM[4], rowL[4];
#pragma unroll
    for (int i = 0; i < 4; i++) { rowM[i] = -3.0e38f; rowL[i] = 0.f; }

    float O[4][4];
#pragma unroll
    for (int i = 0; i < 4; i++)
#pragma unroll
        for (int j = 0; j < 4; j++) O[i][j] = 0.f;

    for (int kt = 0; kt < NTOK/64; kt++) {
        int k0 = kt * 64;
        __syncthreads();  // protect previous-iteration smem reads
        { // load K (transposed) and V tiles
            int kk = tid & 63, chunk = tid >> 6;
            const float* ksrc = qkv + (size_t)(k0 + kk)*(3*CDIM) + CDIM   + h*DH + chunk*16;
            const float* vsrc = qkv + (size_t)(k0 + kk)*(3*CDIM) + 2*CDIM + h*DH + chunk*16;
#pragma unroll
            for (int f = 0; f < 4; f++) {
                float4 kv = *(const float4*)(ksrc + f*4);
                int d = chunk*16 + f*4;
                KsT[(d+0)*AP + kk] = kv.x; KsT[(d+1)*AP + kk] = kv.y;
                KsT[(d+2)*AP + kk] = kv.z; KsT[(d+3)*AP + kk] = kv.w;
                *(float4*)&Vs[kk*AP + d] = *(const float4*)(vsrc + f*4);
            }
            if (tid < 64) logs[tid] = __logf(sizev[k0 + tid]);
        }
        __syncthreads();

        // S = (Q*0.125) @ K^T  + log(size_k)
        float s[4][4];
#pragma unroll
        for (int i = 0; i < 4; i++)
#pragma unroll
            for (int j = 0; j < 4; j++) s[i][j] = 0.f;
#pragma unroll 8
        for (int d = 0; d < 64; d++) {
            float4 a = *(float4*)&QsT[d*AP + ty*4];
            float4 b = *(float4*)&KsT[d*AP + tx*4];
            float aa[4] = {a.x, a.y, a.z, a.w};
            float bb[4] = {b.x, b.y, b.z, b.w};
#pragma unroll
            for (int i = 0; i < 4; i++)
#pragma unroll
                for (int j = 0; j < 4; j++)
                    s[i][j] = fmaf(aa[i], bb[j], s[i][j]);
        }
        float lj[4];
#pragma unroll
        for (int j = 0; j < 4; j++) lj[j] = logs[tx*4 + j];

        // --- register online softmax ---
        float p[4][4];
#pragma unroll
        for (int i = 0; i < 4; i++) {
            float mloc = -3.0e38f;
#pragma unroll
            for (int j = 0; j < 4; j++) {
                s[i][j] += lj[j];
                mloc = fmaxf(mloc, s[i][j]);
            }
            // max across the 16 tx lanes (same ty)
#pragma unroll
            for (int off = 1; off < 16; off <<= 1)
                mloc = fmaxf(mloc, __shfl_xor_sync(0xffffffffu, mloc, off));
            float mNew = fmaxf(rowM[i], mloc);
            float c = __expf(rowM[i] - mNew);
            float lsum = 0.f;
#pragma unroll
            for (int j = 0; j < 4; j++) {
                float pv = __expf(s[i][j] - mNew);
                p[i][j] = pv;
                lsum += pv;
            }
#pragma unroll
            for (int off = 1; off < 16; off <<= 1)
                lsum += __shfl_xor_sync(0xffffffffu, lsum, off);
            rowL[i] = rowL[i] * c + lsum;
            rowM[i] = mNew;
#pragma unroll
            for (int j = 0; j < 4; j++) O[i][j] *= c;
        }

        // stash P as [k][q] for the PV product
#pragma unroll
        for (int i = 0; i < 4; i++)
#pragma unroll
            for (int j = 0; j < 4; j++)
                PT[(tx*4 + j)*AP + (ty*4 + i)] = p[i][j];
        __syncthreads();

        // O += P @ V
#pragma unroll 8
        for (int kk = 0; kk < 64; kk++) {
            float4 pv = *(float4*)&PT[kk*AP + ty*4];
            float4 vv = *(float4*)&Vs[kk*AP + tx*4];
            float pp[4] = {pv.x, pv.y, pv.z, pv.w};
            float vb[4] = {vv.x, vv.y, vv.z, vv.w};
#pragma unroll
            for (int i = 0; i < 4; i++)
#pragma unroll
                for (int j = 0; j < 4; j++)
                    O[i][j] = fmaf(pp[i], vb[j], O[i][j]);
        }
    }

#pragma unroll
    for (int i = 0; i < 4; i++) {
        int q = q0 + ty*4 + i;
        float inv = 1.f / rowL[i];
#pragma unroll
        for (int j = 0; j < 4; j++)
            xa[(size_t)q * CDIM + h*DH + tx*4 + j] = O[i][j] * inv;
    }
}

// ---------------- merge scoring: per-src max/argmax over dst -----------------
__global__ __launch_bounds__(256) void merge_score_kernel(const float* __restrict__ thr)
{
    int i = blockIdx.x, tid = threadIdx.x;
    __shared__ float srcv[64];
    if (tid < 64) srcv[tid] = g_nmet[(size_t)(2*i) * DH + tid];
    __syncthreads();
    float best = -3.0e38f; int bestj = 0;
    for (int j = tid; j < NSRC; j += 256) {
        const float* dv = g_nmet + (size_t)(2*j + 1) * DH;
        float dot = 0.f;
#pragma unroll
        for (int d = 0; d < 64; d++) dot = fmaf(srcv[d], dv[d], dot);
        if (dot > best) { best = dot; bestj = j; }   // ascending j => first-max kept
    }
    __shared__ float bm[256]; __shared__ int bi[256];
    bm[tid] = best; bi[tid] = bestj;
    __syncthreads();
    for (int off = 128; off > 0; off >>= 1) {
        if (tid < off) {
            if (bm[tid+off] > bm[tid] ||
                (bm[tid+off] == bm[tid] && bi[tid+off] < bi[tid])) {
                bm[tid] = bm[tid+off]; bi[tid] = bi[tid+off];
            }
        }
        __syncthreads();
    }
    if (tid == 0) {
        if (i == 0) { g_mask[0] = 0; g_node[0] = 0; }  // row 0 forced -inf
        else { g_mask[i] = (bm[0] > thr[0]) ? 1 : 0; g_node[i] = bi[0]; }
    }
}

// ---------------- exclusive prefix scan of !mask -----------------------------
__global__ __launch_bounds__(1024) void scan_kernel()
{
    __shared__ int s[NSRC];
    int tid = threadIdx.x;
    int f = g_mask[tid] ? 0 : 1;
    s[tid] = f;
    __syncthreads();
    for (int off = 1; off < NSRC; off <<= 1) {
        int v = 0;
        if (tid >= off) v = s[tid - off];
        __syncthreads();
        s[tid] += v;
        __syncthreads();
    }
    g_pref[tid] = s[tid] - f;
    if (tid == NSRC-1) g_nUnm[0] = s[NSRC-1];
}

// ---------------- build unmerged rows ----------------------------------------
__global__ __launch_bounds__(256) void unm_kernel(const float* __restrict__ sizev)
{
    int i = blockIdx.x;
    if (g_mask[i]) return;
    int r = g_pref[i];
    float s = sizev[2*i];
    const float* xr = g_x1 + (size_t)(2*i) * CDIM;
    float* orow = g_outx + (size_t)r * CDIM;
    for (int c = threadIdx.x; c < CDIM; c += 256) orow[c] = xr[c] * s;
    if (threadIdx.x == 0) g_outs[r] = s;
}

// ---------------- build dst rows (deterministic gather of merges) ------------
__global__ __launch_bounds__(256) void dst_build_kernel(const float* __restrict__ sizev)
{
    int j = blockIdx.x, tid = threadIdx.x;
    int nU = g_nUnm[0];
    float s0 = sizev[2*j + 1];
    const float* dr = g_x1 + (size_t)(2*j + 1) * CDIM;
    float a0 = dr[tid]       * s0;
    float a1 = dr[tid + 256] * s0;
    float a2 = dr[tid + 512] * s0;
    float a3 = dr[tid + 768] * s0;
    float stot = s0;
    for (int i = 0; i < NSRC; i++) {
        if (g_mask[i] && g_node[i] == j) {
            float si = sizev[2*i];
            const float* xr = g_x1 + (size_t)(2*i) * CDIM;
            a0 += xr[tid]       * si;
            a1 += xr[tid + 256] * si;
            a2 += xr[tid + 512] * si;
            a3 += xr[tid + 768] * si;
            stot += si;
        }
    }
    size_t r = (size_t)(nU + j) * CDIM;
    g_outx[r + tid]       = a0;
    g_outx[r + tid + 256] = a1;
    g_outx[r + tid + 512] = a2;
    g_outx[r + tid + 768] = a3;
    if (tid == 0) g_outs[nU + j] = stot;
}

// ---------------- x2 = outx / size -------------------------------------------
__global__ __launch_bounds__(256) void div_kernel()
{
    int r = blockIdx.x;
    float s = g_outs[r];
    for (int c = threadIdx.x; c < CDIM; c += 256)
        g_x2[(size_t)r * CDIM + c] = g_outx[(size_t)r * CDIM + c] / s;
}

// ---------------- pack output [x rows | size] --------------------------------
__global__ __launch_bounds__(256) void out_copy_kernel(float* __restrict__ out,
                                                       int Nout, int packSize)
{
    int idx = blockIdx.x * 256 + threadIdx.x;
    int totalx = Nout * CDIM;
    if (idx < totalx) out[idx] = g_xout[idx];
    else if (packSize && idx < totalx + Nout) out[idx] = g_outs[idx - totalx];
}

// ---------------- launcher ---------------------------------------------------
extern "C" void kernel_launch(void* const* d_in, const int* in_sizes, int n_in,
                              void* d_out, int out_size)
{
    const float* x      = (const float*)d_in[0];
    const float* sizev  = (const float*)d_in[1];
    const float* qkv_w  = (const float*)d_in[2];
    const float* proj_w = (const float*)d_in[3];
    const float* proj_b = (const float*)d_in[4];
    const float* ln1_g  = (const float*)d_in[5];
    const float* ln1_b  = (const float*)d_in[6];
    const float* ln2_g  = (const float*)d_in[7];
    const float* ln2_b  = (const float*)d_in[8];
    const float* fc1_w  = (const float*)d_in[9];
    const float* fc1_b  = (const float*)d_in[10];
    const float* fc2_w  = (const float*)d_in[11];
    const float* fc2_b  = (const float*)d_in[12];
    const float* thr    = (const float*)d_in[13];
    float* out = (float*)d_out;

    // Output token count from out_size: (x: Nout*1024) + (size: Nout)
    int Nout, packSize;
    if (out_size % (CDIM + 1) == 0) { Nout = out_size / (CDIM + 1); packSize = 1; }
    else                            { Nout = out_size / CDIM;       packSize = 0; }
    if (Nout > NTOK) Nout = NTOK;

    float *p_h, *p_qkv, *p_xa, *p_x1, *p_x2, *p_h2, *p_ff, *p_xout;
    cudaGetSymbolAddress((void**)&p_h,    g_h);
    cudaGetSymbolAddress((void**)&p_qkv,  g_qkv);
    cudaGetSymbolAddress((void**)&p_xa,   g_xa);
    cudaGetSymbolAddress((void**)&p_x1,   g_x1);
    cudaGetSymbolAddress((void**)&p_x2,   g_x2);
    cudaGetSymbolAddress((void**)&p_h2,   g_h2);
    cudaGetSymbolAddress((void**)&p_ff,   g_ff);
    cudaGetSymbolAddress((void**)&p_xout, g_xout);

    const int ATTN_SMEM = (4*64*AP + 64) * (int)sizeof(float);
    cudaFuncSetAttribute(attn_kernel, cudaFuncAttributeMaxDynamicSharedMemorySize, ATTN_SMEM);

    // 1. LN1
    ln_kernel<<<NTOK, 256>>>(x, ln1_g, ln1_b, p_h, NTOK);
    // 2. QKV = h @ qkv_w   (2048 x 3072 x 1024)
    gemm_kernel<0><<<dim3(3*CDIM/128, NTOK/128), 256>>>(
        p_h, qkv_w, nullptr, nullptr, p_qkv, NTOK, 3*CDIM, CDIM);
    // 3. metric = normalize(mean_h k)
    metric_kernel<<<NTOK, 64>>>();
    // 4. attention -> xa
    attn_kernel<<<dim3(NTOK/64, HEADS), 256, ATTN_SMEM>>>(p_qkv, sizev, p_xa);
    // 5. x1 = x + xa @ proj_w + proj_b
    gemm_kernel<3><<<dim3(CDIM/128, NTOK/128), 256>>>(
        p_xa, proj_w, proj_b, x, p_x1, NTOK, CDIM, CDIM);
    // 6. merge scores (max/argmax per src)
    merge_score_kernel<<<NSRC, 256>>>(thr);
    // 7. prefix scan of unmerged
    scan_kernel<<<1, 1024>>>();
    // 8. gather unmerged rows of xs = x1 * size
    unm_kernel<<<NSRC, 256>>>(sizev);
    // 9. build dst rows (+ merged adds, ascending-i deterministic)
    dst_build_kernel<<<NSRC, 256>>>(sizev);
    // 10. x2 = outx / size
    div_kernel<<<Nout, 256>>>();
    // 11. LN2
    ln_kernel<<<Nout, 256>>>(p_x2, ln2_g, ln2_b, p_h2, Nout);
    // 12. ff = gelu(h2 @ fc1_w + fc1_b)
    gemm_kernel<2><<<dim3(FF/128, (Nout + 127)/128), 256>>>(
        p_h2, fc1_w, fc1_b, nullptr, p_ff, Nout, FF, CDIM);
    // 13. xout = x2 + ff @ fc2_w + fc2_b
    gemm_kernel<3><<<dim3(CDIM/128, (Nout + 127)/128), 256>>>(
        p_ff, fc2_w, fc2_b, p_x2, p_xout, Nout, CDIM, FF);
    // 14. pack output
    int totalOut = Nout * CDIM + (packSize ? Nout : 0);
    out_copy_kernel<<<(totalOut + 255)/256, 256>>>(out, Nout, packSize);
}

// round 5
// speedup vs baseline: 1.6526x; 1.5350x over previous
#include <cuda_runtime.h>
#include <math.h>
#include <stdint.h>

// Problem constants (fixed shapes from setup_inputs)
#define NTOK 2048
#define CDIM 1024
#define HEADS 16
#define DH 64
#define FF 4096
#define NSRC 1024   // NTOK/2

// ---------------- scratch (device globals; no allocation allowed) ------------
__device__ float g_h    [NTOK*CDIM];
__device__ float g_qkv  [NTOK*3*CDIM];
__device__ float g_wkavg[CDIM*DH];
__device__ float g_nmet [NTOK*DH];
__device__ float g_xa   [NTOK*CDIM];
__device__ float g_x1   [NTOK*CDIM];
__device__ int   g_mask [NSRC];
__device__ int   g_node [NSRC];
__device__ int   g_pref [NSRC];
__device__ int   g_nUnm [1];
__device__ float g_outx [NTOK*CDIM];
__device__ float g_outs [NTOK];
__device__ float g_x2   [NTOK*CDIM];
__device__ float g_h2   [NTOK*CDIM];
__device__ float g_ff   [NTOK*FF];
__device__ float g_xout [NTOK*CDIM];

// ---------------- helpers ----------------------------------------------------
__device__ __forceinline__ uint32_t f2tf32(float v) {
    uint32_t r;
    asm("cvt.rna.tf32.f32 %0, %1;" : "=r"(r) : "f"(v));
    return r;
}

__device__ __forceinline__ void mma_tf32(float c[4], const uint32_t a[4],
                                         const uint32_t b[2]) {
    asm volatile(
        "mma.sync.aligned.m16n8k8.row.col.f32.tf32.tf32.f32 "
        "{%0,%1,%2,%3}, {%4,%5,%6,%7}, {%8,%9}, {%0,%1,%2,%3};\n"
        : "+f"(c[0]), "+f"(c[1]), "+f"(c[2]), "+f"(c[3])
        : "r"(a[0]), "r"(a[1]), "r"(a[2]), "r"(a[3]), "r"(b[0]), "r"(b[1]));
}

__device__ __forceinline__ float gelu_exact(float v) {
    return 0.5f * v * (1.0f + erff(v * 0.70710678118654752440f));
}

// ---------------- layernorm ------------------------------------------------
__global__ __launch_bounds__(256) void ln_kernel(
    const float* __restrict__ x, const float* __restrict__ g,
    const float* __restrict__ b, float* __restrict__ out, int M)
{
    int row = blockIdx.x;
    if (row >= M) return;
    const float* xr = x + (size_t)row * CDIM;
    int tid = threadIdx.x;
    float v[4];
    float s = 0.f, sq = 0.f;
#pragma unroll
    for (int t = 0; t < 4; t++) {
        float vv = xr[tid + t*256];
        v[t] = vv; s += vv; sq += vv*vv;
    }
    __shared__ float rs[256], rq[256];
    rs[tid] = s; rq[tid] = sq;
    __syncthreads();
    for (int off = 128; off > 0; off >>= 1) {
        if (tid < off) { rs[tid] += rs[tid+off]; rq[tid] += rq[tid+off]; }
        __syncthreads();
    }
    float mean = rs[0] * (1.f/CDIM);
    float var  = rq[0] * (1.f/CDIM) - mean*mean;
    float rstd = rsqrtf(var + 1e-5f);
    float* orow = out + (size_t)row * CDIM;
#pragma unroll
    for (int t = 0; t < 4; t++) {
        int c = tid + t*256;
        orow[c] = (v[t] - mean) * rstd * g[c] + b[c];
    }
}

// ---------------- TF32 tensor-core GEMM (128x128x16 tiles) -------------------
// 256 threads = 8 warps in 2(m) x 4(n); each warp computes 64x32 via
// 4x4 grid of m16n8k8 mma, two k8 substeps per 16-wide k-tile.
// EPI: 0 = A@B ; 1 = +bias ; 2 = gelu(+bias) ; 3 = +bias +res
template <int EPI>
__global__ __launch_bounds__(256) void gemm_tf32(
    const float* __restrict__ A, const float* __restrict__ B,
    const float* __restrict__ bias, const float* __restrict__ res,
    float* __restrict__ C, int M, int N, int K)
{
    __shared__ uint32_t As[2][128][20];   // [m][k], pitch 20 -> conflict-free frags
    __shared__ uint32_t Bs[2][16][136];   // [k][n], pitch 136 -> conflict-free frags

    int tid  = threadIdx.x;
    int lane = tid & 31, wid = tid >> 5;
    int wm = wid >> 2, wn = wid & 3;
    int g  = lane >> 2, qd = lane & 3;
    int m0 = blockIdx.y * 128, n0 = blockIdx.x * 128;

    float acc[4][4][4];
#pragma unroll
    for (int i = 0; i < 4; i++)
#pragma unroll
        for (int j = 0; j < 4; j++)
#pragma unroll
            for (int r = 0; r < 4; r++) acc[i][j][r] = 0.f;

    const int nT = K >> 4;

    // per-thread global-load coordinates (2 float4 each for A and B per tile)
    int ar[2], ac[2], br[2], bc[2];
#pragma unroll
    for (int u = 0; u < 2; u++) {
        int idx = tid*2 + u;
        ar[u] = idx >> 2;  ac[u] = (idx & 3) * 4;
        br[u] = idx >> 5;  bc[u] = (idx & 31) * 4;
    }

    float4 pa[2], pb[2];
    // prefetch tile 0
#pragma unroll
    for (int u = 0; u < 2; u++) {
        pa[u] = make_float4(0.f,0.f,0.f,0.f);
        if (m0 + ar[u] < M)
            pa[u] = *(const float4*)(A + (size_t)(m0 + ar[u]) * K + ac[u]);
        pb[u] = *(const float4*)(B + (size_t)br[u] * N + n0 + bc[u]);
    }
#pragma unroll
    for (int u = 0; u < 2; u++) {
        As[0][ar[u]][ac[u]+0] = f2tf32(pa[u].x);
        As[0][ar[u]][ac[u]+1] = f2tf32(pa[u].y);
        As[0][ar[u]][ac[u]+2] = f2tf32(pa[u].z);
        As[0][ar[u]][ac[u]+3] = f2tf32(pa[u].w);
        Bs[0][br[u]][bc[u]+0] = f2tf32(pb[u].x);
        Bs[0][br[u]][bc[u]+1] = f2tf32(pb[u].y);
        Bs[0][br[u]][bc[u]+2] = f2tf32(pb[u].z);
        Bs[0][br[u]][bc[u]+3] = f2tf32(pb[u].w);
    }
    __syncthreads();

    for (int t = 0; t < nT; t++) {
        int buf = t & 1;
        if (t + 1 < nT) {
            int k0 = (t + 1) * 16;
#pragma unroll
            for (int u = 0; u < 2; u++) {
                pa[u] = make_float4(0.f,0.f,0.f,0.f);
                if (m0 + ar[u] < M)
                    pa[u] = *(const float4*)(A + (size_t)(m0 + ar[u]) * K + k0 + ac[u]);
                pb[u] = *(const float4*)(B + (size_t)(k0 + br[u]) * N + n0 + bc[u]);
            }
        }
#pragma unroll
        for (int ks = 0; ks < 2; ks++) {
            int kb = ks * 8;
            uint32_t af[4][4], bf[4][2];
#pragma unroll
            for (int mf = 0; mf < 4; mf++) {
                int r = wm*64 + mf*16 + g;
                af[mf][0] = As[buf][r    ][kb + qd];
                af[mf][1] = As[buf][r + 8][kb + qd];
                af[mf][2] = As[buf][r    ][kb + qd + 4];
                af[mf][3] = As[buf][r + 8][kb + qd + 4];
            }
#pragma unroll
            for (int nf = 0; nf < 4; nf++) {
                int c = wn*32 + nf*8 + g;
                bf[nf][0] = Bs[buf][kb + qd    ][c];
                bf[nf][1] = Bs[buf][kb + qd + 4][c];
            }
#pragma unroll
            for (int mf = 0; mf < 4; mf++)
#pragma unroll
                for (int nf = 0; nf < 4; nf++)
                    mma_tf32(acc[mf][nf], af[mf], bf[nf]);
        }
        if (t + 1 < nT) {
            int nb = buf ^ 1;
#pragma unroll
            for (int u = 0; u < 2; u++) {
                As[nb][ar[u]][ac[u]+0] = f2tf32(pa[u].x);
                As[nb][ar[u]][ac[u]+1] = f2tf32(pa[u].y);
                As[nb][ar[u]][ac[u]+2] = f2tf32(pa[u].z);
                As[nb][ar[u]][ac[u]+3] = f2tf32(pa[u].w);
                Bs[nb][br[u]][bc[u]+0] = f2tf32(pb[u].x);
                Bs[nb][br[u]][bc[u]+1] = f2tf32(pb[u].y);
                Bs[nb][br[u]][bc[u]+2] = f2tf32(pb[u].z);
                Bs[nb][br[u]][bc[u]+3] = f2tf32(pb[u].w);
            }
        }
        __syncthreads();
    }

    // epilogue: c0,c1 -> (row g, cols 2qd,2qd+1); c2,c3 -> row g+8
#pragma unroll
    for (int mf = 0; mf < 4; mf++) {
        int rbase = m0 + wm*64 + mf*16 + g;
#pragma unroll
        for (int half = 0; half < 2; half++) {
            int row = rbase + half*8;
            if (row >= M) continue;
#pragma unroll
            for (int nf = 0; nf < 4; nf++) {
                int col = n0 + wn*32 + nf*8 + 2*qd;
                float v0 = acc[mf][nf][half*2 + 0];
                float v1 = acc[mf][nf][half*2 + 1];
                if (EPI >= 1) { v0 += bias[col]; v1 += bias[col+1]; }
                if (EPI == 2) { v0 = gelu_exact(v0); v1 = gelu_exact(v1); }
                if (EPI == 3) {
                    v0 += res[(size_t)row * N + col];
                    v1 += res[(size_t)row * N + col + 1];
                }
                float2 o; o.x = v0; o.y = v1;
                *(float2*)(C + (size_t)row * N + col) = o;
            }
        }
    }
}

// ---------------- fp32 merge-metric path (exactness firewall) ----------------
// wkavg[c][d] = mean_h qkv_w[c][CDIM + h*DH + d]
__global__ __launch_bounds__(256) void wkavg_kernel(const float* __restrict__ qkv_w)
{
    int idx = blockIdx.x * 256 + threadIdx.x;   // 1024*64 total
    if (idx >= CDIM*DH) return;
    int c = idx >> 6, d = idx & 63;
    const float* base = qkv_w + (size_t)c * (3*CDIM) + CDIM + d;
    float s = 0.f;
#pragma unroll
    for (int h = 0; h < HEADS; h++) s += base[h * DH];
    g_wkavg[idx] = s * (1.f / HEADS);
}

// metric[n][:] = normalize( h[n][:] @ wkavg )   -- pure fp32
__global__ __launch_bounds__(64) void metric2_kernel()
{
    int n = blockIdx.x, d = threadIdx.x;
    __shared__ float hrow[CDIM];
    for (int c = d; c < CDIM; c += 64) hrow[c] = g_h[(size_t)n * CDIM + c];
    __syncthreads();
    float s = 0.f;
    for (int c = 0; c < CDIM; c++)
        s = fmaf(hrow[c], g_wkavg[c * DH + d], s);
    __shared__ float sq[64];
    sq[d] = s * s;
    __syncthreads();
    if (d < 32) sq[d] += sq[d+32]; __syncthreads();
    if (d < 16) sq[d] += sq[d+16]; __syncthreads();
    if (d < 8)  sq[d] += sq[d+8];  __syncthreads();
    if (d < 4)  sq[d] += sq[d+4];  __syncthreads();
    if (d < 2)  sq[d] += sq[d+2];  __syncthreads();
    if (d < 1)  sq[d] += sq[d+1];  __syncthreads();
    float nrm = sqrtf(sq[0]);
    g_nmet[(size_t)n * DH + d] = s / nrm;
}

// ---------------- flash attention (64q x 64k tiles, dh=64) -------------------
#define AP 68   // smem pitch (floats)

__global__ __launch_bounds__(256) void attn_kernel(
    const float* __restrict__ qkv, const float* __restrict__ sizev,
    float* __restrict__ xa)
{
    extern __shared__ float sm[];
    float* QsT  = sm;               // [d][q], pre-scaled by 0.125
    float* KsT  = sm + 64*AP;       // [d][k]
    float* Vs   = sm + 2*64*AP;     // [k][d]
    float* PT   = sm + 3*64*AP;     // [k][q]
    float* logs = sm + 4*64*AP;     // [64]

    int tid = threadIdx.x;
    int tx = tid & 15, ty = tid >> 4;
    int h = blockIdx.y;
    int q0 = blockIdx.x * 64;

    { // load Q tile transposed, fold in 1/sqrt(dh)=0.125
        int q = tid & 63, chunk = tid >> 6;
        const float* src = qkv + (size_t)(q0 + q) * (3*CDIM) + h*DH + chunk*16;
#pragma unroll
        for (int f = 0; f < 4; f++) {
            float4 v = *(const float4*)(src + f*4);
            int d = chunk*16 + f*4;
            QsT[(d+0)*AP + q] = v.x * 0.125f; QsT[(d+1)*AP + q] = v.y * 0.125f;
            QsT[(d+2)*AP + q] = v.z * 0.125f; QsT[(d+3)*AP + q] = v.w * 0.125f;
        }
    }

    float rowM[4], rowL[4];
#pragma unroll
    for (int i = 0; i < 4; i++) { rowM[i] = -3.0e38f; rowL[i] = 0.f; }

    float O[4][4];
#pragma unroll
    for (int i = 0; i < 4; i++)
#pragma unroll
        for (int j = 0; j < 4; j++) O[i][j] = 0.f;

    for (int kt = 0; kt < NTOK/64; kt++) {
        int k0 = kt * 64;
        __syncthreads();
        { // load K (transposed) and V tiles
            int kk = tid & 63, chunk = tid >> 6;
            const float* ksrc = qkv + (size_t)(k0 + kk)*(3*CDIM) + CDIM   + h*DH + chunk*16;
            const float* vsrc = qkv + (size_t)(k0 + kk)*(3*CDIM) + 2*CDIM + h*DH + chunk*16;
#pragma unroll
            for (int f = 0; f < 4; f++) {
                float4 kv = *(const float4*)(ksrc + f*4);
                int d = chunk*16 + f*4;
                KsT[(d+0)*AP + kk] = kv.x; KsT[(d+1)*AP + kk] = kv.y;
                KsT[(d+2)*AP + kk] = kv.z; KsT[(d+3)*AP + kk] = kv.w;
                *(float4*)&Vs[kk*AP + d] = *(const float4*)(vsrc + f*4);
            }
            if (tid < 64) logs[tid] = __logf(sizev[k0 + tid]);
        }
        __syncthreads();

        float s[4][4];
#pragma unroll
        for (int i = 0; i < 4; i++)
#pragma unroll
            for (int j = 0; j < 4; j++) s[i][j] = 0.f;
#pragma unroll 8
        for (int d = 0; d < 64; d++) {
            float4 a = *(float4*)&QsT[d*AP + ty*4];
            float4 b = *(float4*)&KsT[d*AP + tx*4];
            float aa[4] = {a.x, a.y, a.z, a.w};
            float bb[4] = {b.x, b.y, b.z, b.w};
#pragma unroll
            for (int i = 0; i < 4; i++)
#pragma unroll
                for (int j = 0; j < 4; j++)
                    s[i][j] = fmaf(aa[i], bb[j], s[i][j]);
        }
        float lj[4];
#pragma unroll
        for (int j = 0; j < 4; j++) lj[j] = logs[tx*4 + j];

        float p[4][4];
#pragma unroll
        for (int i = 0; i < 4; i++) {
            float mloc = -3.0e38f;
#pragma unroll
            for (int j = 0; j < 4; j++) {
                s[i][j] += lj[j];
                mloc = fmaxf(mloc, s[i][j]);
            }
#pragma unroll
            for (int off = 1; off < 16; off <<= 1)
                mloc = fmaxf(mloc, __shfl_xor_sync(0xffffffffu, mloc, off));
            float mNew = fmaxf(rowM[i], mloc);
            float c = __expf(rowM[i] - mNew);
            float lsum = 0.f;
#pragma unroll
            for (int j = 0; j < 4; j++) {
                float pv = __expf(s[i][j] - mNew);
                p[i][j] = pv;
                lsum += pv;
            }
#pragma unroll
            for (int off = 1; off < 16; off <<= 1)
                lsum += __shfl_xor_sync(0xffffffffu, lsum, off);
            rowL[i] = rowL[i] * c + lsum;
            rowM[i] = mNew;
#pragma unroll
            for (int j = 0; j < 4; j++) O[i][j] *= c;
        }

#pragma unroll
        for (int i = 0; i < 4; i++)
#pragma unroll
            for (int j = 0; j < 4; j++)
                PT[(tx*4 + j)*AP + (ty*4 + i)] = p[i][j];
        __syncthreads();

#pragma unroll 8
        for (int kk = 0; kk < 64; kk++) {
            float4 pv = *(float4*)&PT[kk*AP + ty*4];
            float4 vv = *(float4*)&Vs[kk*AP + tx*4];
            float pp[4] = {pv.x, pv.y, pv.z, pv.w};
            float vb[4] = {vv.x, vv.y, vv.z, vv.w};
#pragma unroll
            for (int i = 0; i < 4; i++)
#pragma unroll
                for (int j = 0; j < 4; j++)
                    O[i][j] = fmaf(pp[i], vb[j], O[i][j]);
        }
    }

#pragma unroll
    for (int i = 0; i < 4; i++) {
        int q = q0 + ty*4 + i;
        float inv = 1.f / rowL[i];
#pragma unroll
        for (int j = 0; j < 4; j++)
            xa[(size_t)q * CDIM + h*DH + tx*4 + j] = O[i][j] * inv;
    }
}

// ---------------- merge scoring: per-src max/argmax over dst -----------------
__global__ __launch_bounds__(256) void merge_score_kernel(const float* __restrict__ thr)
{
    int i = blockIdx.x, tid = threadIdx.x;
    __shared__ float srcv[64];
    if (tid < 64) srcv[tid] = g_nmet[(size_t)(2*i) * DH + tid];
    __syncthreads();
    float best = -3.0e38f; int bestj = 0;
    for (int j = tid; j < NSRC; j += 256) {
        const float* dv = g_nmet + (size_t)(2*j + 1) * DH;
        float dot = 0.f;
#pragma unroll
        for (int d = 0; d < 64; d++) dot = fmaf(srcv[d], dv[d], dot);
        if (dot > best) { best = dot; bestj = j; }
    }
    __shared__ float bm[256]; __shared__ int bi[256];
    bm[tid] = best; bi[tid] = bestj;
    __syncthreads();
    for (int off = 128; off > 0; off >>= 1) {
        if (tid < off) {
            if (bm[tid+off] > bm[tid] ||
                (bm[tid+off] == bm[tid] && bi[tid+off] < bi[tid])) {
                bm[tid] = bm[tid+off]; bi[tid] = bi[tid+off];
            }
        }
        __syncthreads();
    }
    if (tid == 0) {
        if (i == 0) { g_mask[0] = 0; g_node[0] = 0; }
        else { g_mask[i] = (bm[0] > thr[0]) ? 1 : 0; g_node[i] = bi[0]; }
    }
}

// ---------------- exclusive prefix scan of !mask -----------------------------
__global__ __launch_bounds__(1024) void scan_kernel()
{
    __shared__ int s[NSRC];
    int tid = threadIdx.x;
    int f = g_mask[tid] ? 0 : 1;
    s[tid] = f;
    __syncthreads();
    for (int off = 1; off < NSRC; off <<= 1) {
        int v = 0;
        if (tid >= off) v = s[tid - off];
        __syncthreads();
        s[tid] += v;
        __syncthreads();
    }
    g_pref[tid] = s[tid] - f;
    if (tid == NSRC-1) g_nUnm[0] = s[NSRC-1];
}

// ---------------- build unmerged rows ----------------------------------------
__global__ __launch_bounds__(256) void unm_kernel(const float* __restrict__ sizev)
{
    int i = blockIdx.x;
    if (g_mask[i]) return;
    int r = g_pref[i];
    float s = sizev[2*i];
    const float* xr = g_x1 + (size_t)(2*i) * CDIM;
    float* orow = g_outx + (size_t)r * CDIM;
    for (int c = threadIdx.x; c < CDIM; c += 256) orow[c] = xr[c] * s;
    if (threadIdx.x == 0) g_outs[r] = s;
}

// ---------------- build dst rows (deterministic gather of merges) ------------
__global__ __launch_bounds__(256) void dst_build_kernel(const float* __restrict__ sizev)
{
    int j = blockIdx.x, tid = threadIdx.x;
    int nU = g_nUnm[0];
    float s0 = sizev[2*j + 1];
    const float* dr = g_x1 + (size_t)(2*j + 1) * CDIM;
    float a0 = dr[tid]       * s0;
    float a1 = dr[tid + 256] * s0;
    float a2 = dr[tid + 512] * s0;
    float a3 = dr[tid + 768] * s0;
    float stot = s0;
    for (int i = 0; i < NSRC; i++) {
        if (g_mask[i] && g_node[i] == j) {
            float si = sizev[2*i];
            const float* xr = g_x1 + (size_t)(2*i) * CDIM;
            a0 += xr[tid]       * si;
            a1 += xr[tid + 256] * si;
            a2 += xr[tid + 512] * si;
            a3 += xr[tid + 768] * si;
            stot += si;
        }
    }
    size_t r = (size_t)(nU + j) * CDIM;
    g_outx[r + tid]       = a0;
    g_outx[r + tid + 256] = a1;
    g_outx[r + tid + 512] = a2;
    g_outx[r + tid + 768] = a3;
    if (tid == 0) g_outs[nU + j] = stot;
}

// ---------------- x2 = outx / size -------------------------------------------
__global__ __launch_bounds__(256) void div_kernel()
{
    int r = blockIdx.x;
    float s = g_outs[r];
    for (int c = threadIdx.x; c < CDIM; c += 256)
        g_x2[(size_t)r * CDIM + c] = g_outx[(size_t)r * CDIM + c] / s;
}

// ---------------- pack output [x rows | size] --------------------------------
__global__ __launch_bounds__(256) void out_copy_kernel(float* __restrict__ out,
                                                       int Nout, int packSize)
{
    int idx = blockIdx.x * 256 + threadIdx.x;
    int totalx = Nout * CDIM;
    if (idx < totalx) out[idx] = g_xout[idx];
    else if (packSize && idx < totalx + Nout) out[idx] = g_outs[idx - totalx];
}

// ---------------- launcher ---------------------------------------------------
extern "C" void kernel_launch(void* const* d_in, const int* in_sizes, int n_in,
                              void* d_out, int out_size)
{
    const float* x      = (const float*)d_in[0];
    const float* sizev  = (const float*)d_in[1];
    const float* qkv_w  = (const float*)d_in[2];
    const float* proj_w = (const float*)d_in[3];
    const float* proj_b = (const float*)d_in[4];
    const float* ln1_g  = (const float*)d_in[5];
    const float* ln1_b  = (const float*)d_in[6];
    const float* ln2_g  = (const float*)d_in[7];
    const float* ln2_b  = (const float*)d_in[8];
    const float* fc1_w  = (const float*)d_in[9];
    const float* fc1_b  = (const float*)d_in[10];
    const float* fc2_w  = (const float*)d_in[11];
    const float* fc2_b  = (const float*)d_in[12];
    const float* thr    = (const float*)d_in[13];
    float* out = (float*)d_out;

    int Nout, packSize;
    if (out_size % (CDIM + 1) == 0) { Nout = out_size / (CDIM + 1); packSize = 1; }
    else                            { Nout = out_size / CDIM;       packSize = 0; }
    if (Nout > NTOK) Nout = NTOK;

    float *p_h, *p_qkv, *p_xa, *p_x1, *p_x2, *p_h2, *p_ff, *p_xout;
    cudaGetSymbolAddress((void**)&p_h,    g_h);
    cudaGetSymbolAddress((void**)&p_qkv,  g_qkv);
    cudaGetSymbolAddress((void**)&p_xa,   g_xa);
    cudaGetSymbolAddress((void**)&p_x1,   g_x1);
    cudaGetSymbolAddress((void**)&p_x2,   g_x2);
    cudaGetSymbolAddress((void**)&p_h2,   g_h2);
    cudaGetSymbolAddress((void**)&p_ff,   g_ff);
    cudaGetSymbolAddress((void**)&p_xout, g_xout);

    const int ATTN_SMEM = (4*64*AP + 64) * (int)sizeof(float);
    cudaFuncSetAttribute(attn_kernel, cudaFuncAttributeMaxDynamicSharedMemorySize, ATTN_SMEM);

    // 1. LN1
    ln_kernel<<<NTOK, 256>>>(x, ln1_g, ln1_b, p_h, NTOK);
    // 2a. averaged K-weights (fp32 merge-metric firewall)
    wkavg_kernel<<<(CDIM*DH + 255)/256, 256>>>(qkv_w);
    // 2b. QKV = h @ qkv_w   (tf32 tensor cores)
    gemm_tf32<0><<<dim3(3*CDIM/128, NTOK/128), 256>>>(
        p_h, qkv_w, nullptr, nullptr, p_qkv, NTOK, 3*CDIM, CDIM);
    // 3. metric = normalize(h @ wkavg)  (fp32, exact mask decisions)
    metric2_kernel<<<NTOK, 64>>>();
    // 4. attention -> xa
    attn_kernel<<<dim3(NTOK/64, HEADS), 256, ATTN_SMEM>>>(p_qkv, sizev, p_xa);
    // 5. x1 = x + xa @ proj_w + proj_b  (tf32)
    gemm_tf32<3><<<dim3(CDIM/128, NTOK/128), 256>>>(
        p_xa, proj_w, proj_b, x, p_x1, NTOK, CDIM, CDIM);
    // 6. merge scores
    merge_score_kernel<<<NSRC, 256>>>(thr);
    // 7. prefix scan
    scan_kernel<<<1, 1024>>>();
    // 8. unmerged rows
    unm_kernel<<<NSRC, 256>>>(sizev);
    // 9. dst rows
    dst_build_kernel<<<NSRC, 256>>>(sizev);
    // 10. x2 = outx / size
    div_kernel<<<Nout, 256>>>();
    // 11. LN2
    ln_kernel<<<Nout, 256>>>(p_x2, ln2_g, ln2_b, p_h2, Nout);
    // 12. ff = gelu(h2 @ fc1_w + fc1_b)  (tf32)
    gemm_tf32<2><<<dim3(FF/128, (Nout + 127)/128), 256>>>(
        p_h2, fc1_w, fc1_b, nullptr, p_ff, Nout, FF, CDIM);
    // 13. xout = x2 + ff @ fc2_w + fc2_b  (tf32)
    gemm_tf32<3><<<dim3(CDIM/128, (Nout + 127)/128), 256>>>(
        p_ff, fc2_w, fc2_b, p_x2, p_xout, Nout, CDIM, FF);
    // 14. pack output
    int totalOut = Nout * CDIM + (packSize ? Nout : 0);
    out_copy_kernel<<<(totalOut + 255)/256, 256>>>(out, Nout, packSize);
}

// round 6
// speedup vs baseline: 2.0452x; 1.2375x over previous
#include <cuda_runtime.h>
#include <math.h>
#include <stdint.h>

// Problem constants (fixed shapes from setup_inputs)
#define NTOK 2048
#define CDIM 1024
#define HEADS 16
#define DH 64
#define FF 4096
#define NSRC 1024   // NTOK/2

// ---------------- scratch (device globals; no allocation allowed) ------------
__device__ float g_h    [NTOK*CDIM];
__device__ float g_qkv  [NTOK*3*CDIM];
__device__ float g_wkavg[CDIM*DH];
__device__ float g_nmet [NTOK*DH];
__device__ float g_xa   [NTOK*CDIM];
__device__ float g_x1   [NTOK*CDIM];
__device__ int   g_mask [NSRC];
__device__ int   g_node [NSRC];
__device__ int   g_pref [NSRC];
__device__ int   g_nUnm [1];
__device__ float g_outx [NTOK*CDIM];
__device__ float g_outs [NTOK];
__device__ float g_x2   [NTOK*CDIM];
__device__ float g_h2   [NTOK*CDIM];
__device__ float g_ff   [NTOK*FF];
__device__ float g_xout [NTOK*CDIM];

// ---------------- helpers ----------------------------------------------------
__device__ __forceinline__ uint32_t f2tf32(float v) {
    uint32_t r;
    asm("cvt.rna.tf32.f32 %0, %1;" : "=r"(r) : "f"(v));
    return r;
}

__device__ __forceinline__ void mma_tf32(float c[4], const uint32_t a[4],
                                         const uint32_t b[2]) {
    asm volatile(
        "mma.sync.aligned.m16n8k8.row.col.f32.tf32.tf32.f32 "
        "{%0,%1,%2,%3}, {%4,%5,%6,%7}, {%8,%9}, {%0,%1,%2,%3};\n"
        : "+f"(c[0]), "+f"(c[1]), "+f"(c[2]), "+f"(c[3])
        : "r"(a[0]), "r"(a[1]), "r"(a[2]), "r"(a[3]), "r"(b[0]), "r"(b[1]));
}

__device__ __forceinline__ float gelu_exact(float v) {
    return 0.5f * v * (1.0f + erff(v * 0.70710678118654752440f));
}

// ---------------- layernorm ------------------------------------------------
__global__ __launch_bounds__(256) void ln_kernel(
    const float* __restrict__ x, const float* __restrict__ g,
    const float* __restrict__ b, float* __restrict__ out, int M)
{
    int row = blockIdx.x;
    if (row >= M) return;
    const float* xr = x + (size_t)row * CDIM;
    int tid = threadIdx.x;
    float v[4];
    float s = 0.f, sq = 0.f;
#pragma unroll
    for (int t = 0; t < 4; t++) {
        float vv = xr[tid + t*256];
        v[t] = vv; s += vv; sq += vv*vv;
    }
    __shared__ float rs[256], rq[256];
    rs[tid] = s; rq[tid] = sq;
    __syncthreads();
    for (int off = 128; off > 0; off >>= 1) {
        if (tid < off) { rs[tid] += rs[tid+off]; rq[tid] += rq[tid+off]; }
        __syncthreads();
    }
    float mean = rs[0] * (1.f/CDIM);
    float var  = rq[0] * (1.f/CDIM) - mean*mean;
    float rstd = rsqrtf(var + 1e-5f);
    float* orow = out + (size_t)row * CDIM;
#pragma unroll
    for (int t = 0; t < 4; t++) {
        int c = tid + t*256;
        orow[c] = (v[t] - mean) * rstd * g[c] + b[c];
    }
}

// ---------------- TF32 tensor-core GEMM (128x128x16 tiles) -------------------
// EPI: 0 = A@B ; 1 = +bias ; 2 = gelu(+bias) ; 3 = +bias +res
template <int EPI>
__global__ __launch_bounds__(256) void gemm_tf32(
    const float* __restrict__ A, const float* __restrict__ B,
    const float* __restrict__ bias, const float* __restrict__ res,
    float* __restrict__ C, int M, int N, int K)
{
    __shared__ uint32_t As[2][128][20];
    __shared__ uint32_t Bs[2][16][136];

    int tid  = threadIdx.x;
    int lane = tid & 31, wid = tid >> 5;
    int wm = wid >> 2, wn = wid & 3;
    int g  = lane >> 2, qd = lane & 3;
    int m0 = blockIdx.y * 128, n0 = blockIdx.x * 128;

    float acc[4][4][4];
#pragma unroll
    for (int i = 0; i < 4; i++)
#pragma unroll
        for (int j = 0; j < 4; j++)
#pragma unroll
            for (int r = 0; r < 4; r++) acc[i][j][r] = 0.f;

    const int nT = K >> 4;

    int ar[2], ac[2], br[2], bc[2];
#pragma unroll
    for (int u = 0; u < 2; u++) {
        int idx = tid*2 + u;
        ar[u] = idx >> 2;  ac[u] = (idx & 3) * 4;
        br[u] = idx >> 5;  bc[u] = (idx & 31) * 4;
    }

    float4 pa[2], pb[2];
#pragma unroll
    for (int u = 0; u < 2; u++) {
        pa[u] = make_float4(0.f,0.f,0.f,0.f);
        if (m0 + ar[u] < M)
            pa[u] = *(const float4*)(A + (size_t)(m0 + ar[u]) * K + ac[u]);
        pb[u] = *(const float4*)(B + (size_t)br[u] * N + n0 + bc[u]);
    }
#pragma unroll
    for (int u = 0; u < 2; u++) {
        As[0][ar[u]][ac[u]+0] = f2tf32(pa[u].x);
        As[0][ar[u]][ac[u]+1] = f2tf32(pa[u].y);
        As[0][ar[u]][ac[u]+2] = f2tf32(pa[u].z);
        As[0][ar[u]][ac[u]+3] = f2tf32(pa[u].w);
        Bs[0][br[u]][bc[u]+0] = f2tf32(pb[u].x);
        Bs[0][br[u]][bc[u]+1] = f2tf32(pb[u].y);
        Bs[0][br[u]][bc[u]+2] = f2tf32(pb[u].z);
        Bs[0][br[u]][bc[u]+3] = f2tf32(pb[u].w);
    }
    __syncthreads();

    for (int t = 0; t < nT; t++) {
        int buf = t & 1;
        if (t + 1 < nT) {
            int k0 = (t + 1) * 16;
#pragma unroll
            for (int u = 0; u < 2; u++) {
                pa[u] = make_float4(0.f,0.f,0.f,0.f);
                if (m0 + ar[u] < M)
                    pa[u] = *(const float4*)(A + (size_t)(m0 + ar[u]) * K + k0 + ac[u]);
                pb[u] = *(const float4*)(B + (size_t)(k0 + br[u]) * N + n0 + bc[u]);
            }
        }
#pragma unroll
        for (int ks = 0; ks < 2; ks++) {
            int kb = ks * 8;
            uint32_t af[4][4], bf[4][2];
#pragma unroll
            for (int mf = 0; mf < 4; mf++) {
                int r = wm*64 + mf*16 + g;
                af[mf][0] = As[buf][r    ][kb + qd];
                af[mf][1] = As[buf][r + 8][kb + qd];
                af[mf][2] = As[buf][r    ][kb + qd + 4];
                af[mf][3] = As[buf][r + 8][kb + qd + 4];
            }
#pragma unroll
            for (int nf = 0; nf < 4; nf++) {
                int c = wn*32 + nf*8 + g;
                bf[nf][0] = Bs[buf][kb + qd    ][c];
                bf[nf][1] = Bs[buf][kb + qd + 4][c];
            }
#pragma unroll
            for (int mf = 0; mf < 4; mf++)
#pragma unroll
                for (int nf = 0; nf < 4; nf++)
                    mma_tf32(acc[mf][nf], af[mf], bf[nf]);
        }
        if (t + 1 < nT) {
            int nb = buf ^ 1;
#pragma unroll
            for (int u = 0; u < 2; u++) {
                As[nb][ar[u]][ac[u]+0] = f2tf32(pa[u].x);
                As[nb][ar[u]][ac[u]+1] = f2tf32(pa[u].y);
                As[nb][ar[u]][ac[u]+2] = f2tf32(pa[u].z);
                As[nb][ar[u]][ac[u]+3] = f2tf32(pa[u].w);
                Bs[nb][br[u]][bc[u]+0] = f2tf32(pb[u].x);
                Bs[nb][br[u]][bc[u]+1] = f2tf32(pb[u].y);
                Bs[nb][br[u]][bc[u]+2] = f2tf32(pb[u].z);
                Bs[nb][br[u]][bc[u]+3] = f2tf32(pb[u].w);
            }
        }
        __syncthreads();
    }

#pragma unroll
    for (int mf = 0; mf < 4; mf++) {
        int rbase = m0 + wm*64 + mf*16 + g;
#pragma unroll
        for (int half = 0; half < 2; half++) {
            int row = rbase + half*8;
            if (row >= M) continue;
#pragma unroll
            for (int nf = 0; nf < 4; nf++) {
                int col = n0 + wn*32 + nf*8 + 2*qd;
                float v0 = acc[mf][nf][half*2 + 0];
                float v1 = acc[mf][nf][half*2 + 1];
                if (EPI >= 1) { v0 += bias[col]; v1 += bias[col+1]; }
                if (EPI == 2) { v0 = gelu_exact(v0); v1 = gelu_exact(v1); }
                if (EPI == 3) {
                    v0 += res[(size_t)row * N + col];
                    v1 += res[(size_t)row * N + col + 1];
                }
                float2 o; o.x = v0; o.y = v1;
                *(float2*)(C + (size_t)row * N + col) = o;
            }
        }
    }
}

// ---------------- fp32 merge-metric path (exactness firewall) ----------------
// wkavg[c][d] = mean_h qkv_w[c][CDIM + h*DH + d]
__global__ __launch_bounds__(256) void wkavg_kernel(const float* __restrict__ qkv_w)
{
    int idx = blockIdx.x * 256 + threadIdx.x;
    if (idx >= CDIM*DH) return;
    int c = idx >> 6, d = idx & 63;
    const float* base = qkv_w + (size_t)c * (3*CDIM) + CDIM + d;
    float s = 0.f;
#pragma unroll
    for (int h = 0; h < HEADS; h++) s += base[h * DH];
    g_wkavg[idx] = s * (1.f / HEADS);
}

// metric (unnormalized) = h @ wkavg -- fp32 SIMT GEMM, 64tok x 64d tiles
__global__ __launch_bounds__(256) void metric_gemm_kernel()
{
    __shared__ float AsT[32][68];   // [k][tok]
    __shared__ float Bs [32][68];   // [k][d]
    int tid = threadIdx.x;
    int tx = tid & 15, ty = tid >> 4;
    int m0 = blockIdx.x * 64;

    float acc[4][4];
#pragma unroll
    for (int i = 0; i < 4; i++)
#pragma unroll
        for (int j = 0; j < 4; j++) acc[i][j] = 0.f;

    for (int k0 = 0; k0 < CDIM; k0 += 32) {
        __syncthreads();
#pragma unroll
        for (int u = 0; u < 2; u++) {
            int idx = tid*2 + u;
            int tok = idx >> 3, kc = (idx & 7) * 4;
            float4 v = *(const float4*)(g_h + (size_t)(m0 + tok) * CDIM + k0 + kc);
            AsT[kc+0][tok] = v.x; AsT[kc+1][tok] = v.y;
            AsT[kc+2][tok] = v.z; AsT[kc+3][tok] = v.w;
            int kr = idx >> 4, d = (idx & 15) * 4;
            *(float4*)&Bs[kr][d] = *(const float4*)(g_wkavg + (size_t)(k0 + kr) * DH + d);
        }
        __syncthreads();
#pragma unroll
        for (int k = 0; k < 32; k++) {
            float4 a = *(float4*)&AsT[k][ty*4];
            float4 b = *(float4*)&Bs[k][tx*4];
            float aa[4] = {a.x, a.y, a.z, a.w};
            float bb[4] = {b.x, b.y, b.z, b.w};
#pragma unroll
            for (int i = 0; i < 4; i++)
#pragma unroll
                for (int j = 0; j < 4; j++)
                    acc[i][j] = fmaf(aa[i], bb[j], acc[i][j]);
        }
    }
#pragma unroll
    for (int i = 0; i < 4; i++)
#pragma unroll
        for (int j = 0; j < 4; j++)
            g_nmet[(size_t)(m0 + ty*4 + i) * DH + tx*4 + j] = acc[i][j];
}

// row-normalize g_nmet in place (one warp per row)
__global__ __launch_bounds__(256) void metric_norm_kernel()
{
    int row = blockIdx.x * 8 + (threadIdx.x >> 5);
    int lane = threadIdx.x & 31;
    float2 v = *(float2*)&g_nmet[(size_t)row * DH + lane*2];
    float sq = v.x*v.x + v.y*v.y;
#pragma unroll
    for (int off = 16; off > 0; off >>= 1)
        sq += __shfl_xor_sync(0xffffffffu, sq, off);
    float nrm = sqrtf(sq);
    v.x /= nrm; v.y /= nrm;
    *(float2*)&g_nmet[(size_t)row * DH + lane*2] = v;
}

// ---------------- tensor-core flash attention (64q x 64k, dh=64) -------------
// 128 threads / 4 warps; warp w owns q rows [w*16, w*16+16).
// S = QK^T and O += P V via m16n8k8 tf32 mma; softmax in registers.
#define ATP 68   // smem pitch (words): addr%32 = g*4+qd -> conflict-free frags

__global__ __launch_bounds__(128) void attn_tc_kernel(
    const float* __restrict__ qkv, const float* __restrict__ sizev,
    float* __restrict__ xa)
{
    extern __shared__ uint32_t smu[];
    uint32_t* Qs   = smu;                    // [64][ATP] tf32 (scaled by 0.125)
    uint32_t* Ks   = smu + 64*ATP;           // [64][ATP] tf32 (token-major)
    uint32_t* VsT  = smu + 2*64*ATP;         // [64][ATP] tf32 (d-major)
    uint32_t* Ps   = smu + 3*64*ATP;         // [64][ATP] tf32
    float*    logs = (float*)(smu + 4*64*ATP); // [64]

    int tid  = threadIdx.x;
    int lane = tid & 31, w = tid >> 5;
    int g = lane >> 2, qd = lane & 3;
    int h = blockIdx.y;
    int q0 = blockIdx.x * 64;
    int wq = w * 16;
    int qrow0 = (wq + g) * ATP, qrow1 = (wq + g + 8) * ATP;

    { // load Q tile (tf32, pre-scaled)
        int tok = tid & 63, chunk = tid >> 6;   // chunk 0/1 -> 32 d each
        const float* src = qkv + (size_t)(q0 + tok) * (3*CDIM) + h*DH + chunk*32;
#pragma unroll
        for (int f = 0; f < 8; f++) {
            float4 v = *(const float4*)(src + f*4);
            uint4 u;
            u.x = f2tf32(v.x * 0.125f); u.y = f2tf32(v.y * 0.125f);
            u.z = f2tf32(v.z * 0.125f); u.w = f2tf32(v.w * 0.125f);
            *(uint4*)&Qs[tok*ATP + chunk*32 + f*4] = u;
        }
    }

    float O[8][4];
#pragma unroll
    for (int dt = 0; dt < 8; dt++)
#pragma unroll
        for (int r = 0; r < 4; r++) O[dt][r] = 0.f;
    float rm0 = -3.0e38f, rm1 = -3.0e38f, rl0 = 0.f, rl1 = 0.f;

    for (int kt = 0; kt < NTOK/64; kt++) {
        int k0 = kt * 64;
        __syncthreads();   // prior tile's reads of Ks/VsT complete
        {
            int tok = tid & 63, chunk = tid >> 6;
            const float* ksrc = qkv + (size_t)(k0 + tok)*(3*CDIM) + CDIM + h*DH + chunk*32;
            const float* vsrc = ksrc + CDIM;
#pragma unroll
            for (int f = 0; f < 8; f++) {
                float4 kv = *(const float4*)(ksrc + f*4);
                uint4 u;
                u.x = f2tf32(kv.x); u.y = f2tf32(kv.y);
                u.z = f2tf32(kv.z); u.w = f2tf32(kv.w);
                *(uint4*)&Ks[tok*ATP + chunk*32 + f*4] = u;
                float4 vv = *(const float4*)(vsrc + f*4);
                int d = chunk*32 + f*4;
                VsT[(d+0)*ATP + tok] = f2tf32(vv.x);
                VsT[(d+1)*ATP + tok] = f2tf32(vv.y);
                VsT[(d+2)*ATP + tok] = f2tf32(vv.z);
                VsT[(d+3)*ATP + tok] = f2tf32(vv.w);
            }
            if (tid < 64) logs[tid] = __logf(sizev[k0 + tid]);
        }
        __syncthreads();   // tiles visible

        // ---- S = Q @ K^T ----
        float S[8][4];
#pragma unroll
        for (int nt = 0; nt < 8; nt++)
#pragma unroll
            for (int r = 0; r < 4; r++) S[nt][r] = 0.f;
#pragma unroll
        for (int kb = 0; kb < 8; kb++) {
            uint32_t a[4];
            a[0] = Qs[qrow0 + kb*8 + qd];
            a[1] = Qs[qrow1 + kb*8 + qd];
            a[2] = Qs[qrow0 + kb*8 + qd + 4];
            a[3] = Qs[qrow1 + kb*8 + qd + 4];
#pragma unroll
            for (int nt = 0; nt < 8; nt++) {
                uint32_t b[2];
                b[0] = Ks[(nt*8 + g)*ATP + kb*8 + qd];
                b[1] = Ks[(nt*8 + g)*ATP + kb*8 + qd + 4];
                mma_tf32(S[nt], a, b);
            }
        }

        // ---- register online softmax ----
        float m0 = -3.0e38f, m1 = -3.0e38f;
#pragma unroll
        for (int nt = 0; nt < 8; nt++) {
            float l0 = logs[nt*8 + 2*qd], l1 = logs[nt*8 + 2*qd + 1];
            S[nt][0] += l0; S[nt][1] += l1;
            S[nt][2] += l0; S[nt][3] += l1;
            m0 = fmaxf(m0, fmaxf(S[nt][0], S[nt][1]));
            m1 = fmaxf(m1, fmaxf(S[nt][2], S[nt][3]));
        }
#pragma unroll
        for (int off = 1; off < 4; off <<= 1) {
            m0 = fmaxf(m0, __shfl_xor_sync(0xffffffffu, m0, off));
            m1 = fmaxf(m1, __shfl_xor_sync(0xffffffffu, m1, off));
        }
        float n0 = fmaxf(rm0, m0), n1 = fmaxf(rm1, m1);
        float c0 = __expf(rm0 - n0), c1 = __expf(rm1 - n1);
        float s0 = 0.f, s1 = 0.f;
#pragma unroll
        for (int nt = 0; nt < 8; nt++) {
            S[nt][0] = __expf(S[nt][0] - n0);
            S[nt][1] = __expf(S[nt][1] - n0);
            S[nt][2] = __expf(S[nt][2] - n1);
            S[nt][3] = __expf(S[nt][3] - n1);
            s0 += S[nt][0] + S[nt][1];
            s1 += S[nt][2] + S[nt][3];
        }
#pragma unroll
        for (int off = 1; off < 4; off <<= 1) {
            s0 += __shfl_xor_sync(0xffffffffu, s0, off);
            s1 += __shfl_xor_sync(0xffffffffu, s1, off);
        }
        rl0 = rl0 * c0 + s0;  rl1 = rl1 * c1 + s1;
        rm0 = n0; rm1 = n1;
#pragma unroll
        for (int dt = 0; dt < 8; dt++) {
            O[dt][0] *= c0; O[dt][1] *= c0;
            O[dt][2] *= c1; O[dt][3] *= c1;
        }

        // stash P (tf32); consumed only by own warp -> syncwarp suffices
#pragma unroll
        for (int nt = 0; nt < 8; nt++) {
            uint2 u01, u23;
            u01.x = f2tf32(S[nt][0]); u01.y = f2tf32(S[nt][1]);
            u23.x = f2tf32(S[nt][2]); u23.y = f2tf32(S[nt][3]);
            *(uint2*)&Ps[qrow0 + nt*8 + 2*qd] = u01;
            *(uint2*)&Ps[qrow1 + nt*8 + 2*qd] = u23;
        }
        __syncwarp();

        // ---- O += P @ V ----
#pragma unroll
        for (int kb = 0; kb < 8; kb++) {
            uint32_t a[4];
            a[0] = Ps[qrow0 + kb*8 + qd];
            a[1] = Ps[qrow1 + kb*8 + qd];
            a[2] = Ps[qrow0 + kb*8 + qd + 4];
            a[3] = Ps[qrow1 + kb*8 + qd + 4];
#pragma unroll
            for (int dt = 0; dt < 8; dt++) {
                uint32_t b[2];
                b[0] = VsT[(dt*8 + g)*ATP + kb*8 + qd];
                b[1] = VsT[(dt*8 + g)*ATP + kb*8 + qd + 4];
                mma_tf32(O[dt], a, b);
            }
        }
    }

    // epilogue
    float i0 = 1.f / rl0, i1 = 1.f / rl1;
    int row0 = q0 + wq + g, row1 = row0 + 8;
#pragma unroll
    for (int dt = 0; dt < 8; dt++) {
        int col = h*DH + dt*8 + 2*qd;
        float2 o0; o0.x = O[dt][0]*i0; o0.y = O[dt][1]*i0;
        float2 o1; o1.x = O[dt][2]*i1; o1.y = O[dt][3]*i1;
        *(float2*)&xa[(size_t)row0 * CDIM + col] = o0;
        *(float2*)&xa[(size_t)row1 * CDIM + col] = o1;
    }
}

// ---------------- merge scoring: per-src max/argmax over dst -----------------
__global__ __launch_bounds__(256) void merge_score_kernel(const float* __restrict__ thr)
{
    int i = blockIdx.x, tid = threadIdx.x;
    __shared__ float srcv[64];
    if (tid < 64) srcv[tid] = g_nmet[(size_t)(2*i) * DH + tid];
    __syncthreads();
    float best = -3.0e38f; int bestj = 0;
    for (int j = tid; j < NSRC; j += 256) {
        const float* dv = g_nmet + (size_t)(2*j + 1) * DH;
        float dot = 0.f;
#pragma unroll
        for (int d = 0; d < 64; d++) dot = fmaf(srcv[d], dv[d], dot);
        if (dot > best) { best = dot; bestj = j; }
    }
    __shared__ float bm[256]; __shared__ int bi[256];
    bm[tid] = best; bi[tid] = bestj;
    __syncthreads();
    for (int off = 128; off > 0; off >>= 1) {
        if (tid < off) {
            if (bm[tid+off] > bm[tid] ||
                (bm[tid+off] == bm[tid] && bi[tid+off] < bi[tid])) {
                bm[tid] = bm[tid+off]; bi[tid] = bi[tid+off];
            }
        }
        __syncthreads();
    }
    if (tid == 0) {
        if (i == 0) { g_mask[0] = 0; g_node[0] = 0; }
        else { g_mask[i] = (bm[0] > thr[0]) ? 1 : 0; g_node[i] = bi[0]; }
    }
}

// ---------------- exclusive prefix scan of !mask -----------------------------
__global__ __launch_bounds__(1024) void scan_kernel()
{
    __shared__ int s[NSRC];
    int tid = threadIdx.x;
    int f = g_mask[tid] ? 0 : 1;
    s[tid] = f;
    __syncthreads();
    for (int off = 1; off < NSRC; off <<= 1) {
        int v = 0;
        if (tid >= off) v = s[tid - off];
        __syncthreads();
        s[tid] += v;
        __syncthreads();
    }
    g_pref[tid] = s[tid] - f;
    if (tid == NSRC-1) g_nUnm[0] = s[NSRC-1];
}

// ---------------- build unmerged rows ----------------------------------------
__global__ __launch_bounds__(256) void unm_kernel(const float* __restrict__ sizev)
{
    int i = blockIdx.x;
    if (g_mask[i]) return;
    int r = g_pref[i];
    float s = sizev[2*i];
    const float* xr = g_x1 + (size_t)(2*i) * CDIM;
    float* orow = g_outx + (size_t)r * CDIM;
    for (int c = threadIdx.x; c < CDIM; c += 256) orow[c] = xr[c] * s;
    if (threadIdx.x == 0) g_outs[r] = s;
}

// ---------------- build dst rows (deterministic gather of merges) ------------
__global__ __launch_bounds__(256) void dst_build_kernel(const float* __restrict__ sizev)
{
    int j = blockIdx.x, tid = threadIdx.x;
    int nU = g_nUnm[0];
    float s0 = sizev[2*j + 1];
    const float* dr = g_x1 + (size_t)(2*j + 1) * CDIM;
    float a0 = dr[tid]       * s0;
    float a1 = dr[tid + 256] * s0;
    float a2 = dr[tid + 512] * s0;
    float a3 = dr[tid + 768] * s0;
    float stot = s0;
    for (int i = 0; i < NSRC; i++) {
        if (g_mask[i] && g_node[i] == j) {
            float si = sizev[2*i];
            const float* xr = g_x1 + (size_t)(2*i) * CDIM;
            a0 += xr[tid]       * si;
            a1 += xr[tid + 256] * si;
            a2 += xr[tid + 512] * si;
            a3 += xr[tid + 768] * si;
            stot += si;
        }
    }
    size_t r = (size_t)(nU + j) * CDIM;
    g_outx[r + tid]       = a0;
    g_outx[r + tid + 256] = a1;
    g_outx[r + tid + 512] = a2;
    g_outx[r + tid + 768] = a3;
    if (tid == 0) g_outs[nU + j] = stot;
}

// ---------------- x2 = outx / size -------------------------------------------
__global__ __launch_bounds__(256) void div_kernel()
{
    int r = blockIdx.x;
    float s = g_outs[r];
    for (int c = threadIdx.x; c < CDIM; c += 256)
        g_x2[(size_t)r * CDIM + c] = g_outx[(size_t)r * CDIM + c] / s;
}

// ---------------- pack output [x rows | size] --------------------------------
__global__ __launch_bounds__(256) void out_copy_kernel(float* __restrict__ out,
                                                       int Nout, int packSize)
{
    int idx = blockIdx.x * 256 + threadIdx.x;
    int totalx = Nout * CDIM;
    if (idx < totalx) out[idx] = g_xout[idx];
    else if (packSize && idx < totalx + Nout) out[idx] = g_outs[idx - totalx];
}

// ---------------- launcher ---------------------------------------------------
extern "C" void kernel_launch(void* const* d_in, const int* in_sizes, int n_in,
                              void* d_out, int out_size)
{
    const float* x      = (const float*)d_in[0];
    const float* sizev  = (const float*)d_in[1];
    const float* qkv_w  = (const float*)d_in[2];
    const float* proj_w = (const float*)d_in[3];
    const float* proj_b = (const float*)d_in[4];
    const float* ln1_g  = (const float*)d_in[5];
    const float* ln1_b  = (const float*)d_in[6];
    const float* ln2_g  = (const float*)d_in[7];
    const float* ln2_b  = (const float*)d_in[8];
    const float* fc1_w  = (const float*)d_in[9];
    const float* fc1_b  = (const float*)d_in[10];
    const float* fc2_w  = (const float*)d_in[11];
    const float* fc2_b  = (const float*)d_in[12];
    const float* thr    = (const float*)d_in[13];
    float* out = (float*)d_out;

    int Nout, packSize;
    if (out_size % (CDIM + 1) == 0) { Nout = out_size / (CDIM + 1); packSize = 1; }
    else                            { Nout = out_size / CDIM;       packSize = 0; }
    if (Nout > NTOK) Nout = NTOK;

    float *p_h, *p_qkv, *p_xa, *p_x1, *p_x2, *p_h2, *p_ff, *p_xout;
    cudaGetSymbolAddress((void**)&p_h,    g_h);
    cudaGetSymbolAddress((void**)&p_qkv,  g_qkv);
    cudaGetSymbolAddress((void**)&p_xa,   g_xa);
    cudaGetSymbolAddress((void**)&p_x1,   g_x1);
    cudaGetSymbolAddress((void**)&p_x2,   g_x2);
    cudaGetSymbolAddress((void**)&p_h2,   g_h2);
    cudaGetSymbolAddress((void**)&p_ff,   g_ff);
    cudaGetSymbolAddress((void**)&p_xout, g_xout);

    const int ATTN_SMEM = (4*64*ATP + 64) * (int)sizeof(uint32_t);
    cudaFuncSetAttribute(attn_tc_kernel, cudaFuncAttributeMaxDynamicSharedMemorySize, ATTN_SMEM);

    // 1. LN1
    ln_kernel<<<NTOK, 256>>>(x, ln1_g, ln1_b, p_h, NTOK);
    // 2a. averaged K-weights (fp32 merge-metric firewall)
    wkavg_kernel<<<(CDIM*DH + 255)/256, 256>>>(qkv_w);
    // 2b. QKV = h @ qkv_w   (tf32 tensor cores)
    gemm_tf32<0><<<dim3(3*CDIM/128, NTOK/128), 256>>>(
        p_h, qkv_w, nullptr, nullptr, p_qkv, NTOK, 3*CDIM, CDIM);
    // 3. metric = normalize(h @ wkavg)  (fp32, exact mask decisions)
    metric_gemm_kernel<<<NTOK/64, 256>>>();
    metric_norm_kernel<<<NTOK/8, 256>>>();
    // 4. attention -> xa  (tf32 tensor cores)
    attn_tc_kernel<<<dim3(NTOK/64, HEADS), 128, ATTN_SMEM>>>(p_qkv, sizev, p_xa);
    // 5. x1 = x + xa @ proj_w + proj_b  (tf32)
    gemm_tf32<3><<<dim3(CDIM/128, NTOK/128), 256>>>(
        p_xa, proj_w, proj_b, x, p_x1, NTOK, CDIM, CDIM);
    // 6. merge scores
    merge_score_kernel<<<NSRC, 256>>>(thr);
    // 7. prefix scan
    scan_kernel<<<1, 1024>>>();
    // 8. unmerged rows
    unm_kernel<<<NSRC, 256>>>(sizev);
    // 9. dst rows
    dst_build_kernel<<<NSRC, 256>>>(sizev);
    // 10. x2 = outx / size
    div_kernel<<<Nout, 256>>>();
    // 11. LN2
    ln_kernel<<<Nout, 256>>>(p_x2, ln2_g, ln2_b, p_h2, Nout);
    // 12. ff = gelu(h2 @ fc1_w + fc1_b)  (tf32)
    gemm_tf32<2><<<dim3(FF/128, (Nout + 127)/128), 256>>>(
        p_h2, fc1_w, fc1_b, nullptr, p_ff, Nout, FF, CDIM);
    // 13. xout = x2 + ff @ fc2_w + fc2_b  (tf32)
    gemm_tf32<3><<<dim3(CDIM/128, (Nout + 127)/128), 256>>>(
        p_ff, fc2_w, fc2_b, p_x2, p_xout, Nout, CDIM, FF);
    // 14. pack output
    int totalOut = Nout * CDIM + (packSize ? Nout : 0);
    out_copy_kernel<<<(totalOut + 255)/256, 256>>>(out, Nout, packSize);
}

// round 7
// speedup vs baseline: 2.2949x; 1.1221x over previous
#include <cuda_runtime.h>
#include <math.h>
#include <stdint.h>

// Problem constants (fixed shapes from setup_inputs)
#define NTOK 2048
#define CDIM 1024
#define HEADS 16
#define DH 64
#define FF 4096
#define NSRC 1024   // NTOK/2

// ---------------- scratch (device globals; no allocation allowed) ------------
__device__ float g_h    [NTOK*CDIM];
__device__ float g_qkv  [NTOK*3*CDIM];
__device__ float g_wkavg[CDIM*DH];
__device__ float g_mpart[4*NTOK*DH];
__device__ float g_nmet [NTOK*DH];
__device__ float g_xa   [NTOK*CDIM];
__device__ float g_x1   [NTOK*CDIM];
__device__ int   g_mask [NSRC];
__device__ int   g_node [NSRC];
__device__ int   g_pref [NSRC];
__device__ int   g_nUnm [1];
__device__ float g_outx [NTOK*CDIM];
__device__ float g_outs [NTOK];
__device__ float g_x2   [NTOK*CDIM];
__device__ float g_h2   [NTOK*CDIM];
__device__ float g_ff   [NTOK*FF];
__device__ float g_xout [NTOK*CDIM];

// ---------------- helpers ----------------------------------------------------
__device__ __forceinline__ uint32_t f2tf32(float v) {
    uint32_t r;
    asm("cvt.rna.tf32.f32 %0, %1;" : "=r"(r) : "f"(v));
    return r;
}

__device__ __forceinline__ void mma_tf32(float c[4], const uint32_t a[4],
                                         const uint32_t b[2]) {
    asm volatile(
        "mma.sync.aligned.m16n8k8.row.col.f32.tf32.tf32.f32 "
        "{%0,%1,%2,%3}, {%4,%5,%6,%7}, {%8,%9}, {%0,%1,%2,%3};\n"
        : "+f"(c[0]), "+f"(c[1]), "+f"(c[2]), "+f"(c[3])
        : "r"(a[0]), "r"(a[1]), "r"(a[2]), "r"(a[3]), "r"(b[0]), "r"(b[1]));
}

__device__ __forceinline__ void cp_async16(uint32_t dst, const void* src, int szbytes) {
    asm volatile("cp.async.cg.shared.global [%0], [%1], 16, %2;\n"
                 :: "r"(dst), "l"(src), "r"(szbytes));
}
__device__ __forceinline__ void cp_commit() {
    asm volatile("cp.async.commit_group;\n");
}
template <int N>
__device__ __forceinline__ void cp_wait() {
    asm volatile("cp.async.wait_group %0;\n" :: "n"(N));
}

__device__ __forceinline__ float gelu_exact(float v) {
    return 0.5f * v * (1.0f + erff(v * 0.70710678118654752440f));
}

// ---------------- layernorm ------------------------------------------------
__global__ __launch_bounds__(256) void ln_kernel(
    const float* __restrict__ x, const float* __restrict__ g,
    const float* __restrict__ b, float* __restrict__ out, int M)
{
    int row = blockIdx.x;
    if (row >= M) return;
    const float* xr = x + (size_t)row * CDIM;
    int tid = threadIdx.x;
    float v[4];
    float s = 0.f, sq = 0.f;
#pragma unroll
    for (int t = 0; t < 4; t++) {
        float vv = xr[tid + t*256];
        v[t] = vv; s += vv; sq += vv*vv;
    }
    __shared__ float rs[256], rq[256];
    rs[tid] = s; rq[tid] = sq;
    __syncthreads();
    for (int off = 128; off > 0; off >>= 1) {
        if (tid < off) { rs[tid] += rs[tid+off]; rq[tid] += rq[tid+off]; }
        __syncthreads();
    }
    float mean = rs[0] * (1.f/CDIM);
    float var  = rq[0] * (1.f/CDIM) - mean*mean;
    float rstd = rsqrtf(var + 1e-5f);
    float* orow = out + (size_t)row * CDIM;
#pragma unroll
    for (int t = 0; t < 4; t++) {
        int c = tid + t*256;
        orow[c] = (v[t] - mean) * rstd * g[c] + b[c];
    }
}

// ---------------- TF32 tensor-core GEMM, cp.async 3-stage --------------------
// 128x128x16 CTA tiles; raw fp32 bits in smem (HMMA.TF32 truncates mantissa).
// EPI: 0 = A@B ; 1 = +bias ; 2 = gelu(+bias) ; 3 = +bias +res
#define GSTAGES 3
#define AS_WORDS (GSTAGES*128*20)
#define BS_WORDS (GSTAGES*16*136)
#define GEMM_SMEM ((AS_WORDS + BS_WORDS) * 4)

template <int EPI>
__global__ __launch_bounds__(256) void gemm_tf32(
    const float* __restrict__ A, const float* __restrict__ B,
    const float* __restrict__ bias, const float* __restrict__ res,
    float* __restrict__ C, int M, int N, int K)
{
    extern __shared__ uint32_t gsm[];
    uint32_t* As = gsm;              // [s][128][20]
    uint32_t* Bs = gsm + AS_WORDS;   // [s][16][136]

    int tid  = threadIdx.x;
    int lane = tid & 31, wid = tid >> 5;
    int wm = wid >> 2, wn = wid & 3;
    int g  = lane >> 2, qd = lane & 3;
    int m0 = blockIdx.y * 128, n0 = blockIdx.x * 128;

    float acc[4][4][4];
#pragma unroll
    for (int i = 0; i < 4; i++)
#pragma unroll
        for (int j = 0; j < 4; j++)
#pragma unroll
            for (int r = 0; r < 4; r++) acc[i][j][r] = 0.f;

    const int nT = K >> 4;

    int ar[2], ac[2], br[2], bc[2];
#pragma unroll
    for (int u = 0; u < 2; u++) {
        int idx = tid*2 + u;
        ar[u] = idx >> 2;  ac[u] = (idx & 3) * 4;
        br[u] = idx >> 5;  bc[u] = (idx & 31) * 4;
    }
    uint32_t asBase = (uint32_t)__cvta_generic_to_shared(As);
    uint32_t bsBase = (uint32_t)__cvta_generic_to_shared(Bs);
    int aSz[2];
#pragma unroll
    for (int u = 0; u < 2; u++) aSz[u] = (m0 + ar[u] < M) ? 16 : 0;

    // prologue: issue tiles 0 and 1
#pragma unroll
    for (int t = 0; t < 2; t++) {
        int k0 = t * 16;
#pragma unroll
        for (int u = 0; u < 2; u++) {
            cp_async16(asBase + (uint32_t)(((t*128 + ar[u])*20 + ac[u]) * 4),
                       A + (size_t)(m0 + ar[u]) * K + k0 + ac[u], aSz[u]);
            cp_async16(bsBase + (uint32_t)(((t*16 + br[u])*136 + bc[u]) * 4),
                       B + (size_t)(k0 + br[u]) * N + n0 + bc[u], 16);
        }
        cp_commit();
    }

    for (int t = 0; t < nT; t++) {
        cp_wait<GSTAGES-2>();
        __syncthreads();

        int nxt = t + GSTAGES - 1;
        if (nxt < nT) {
            int s  = nxt % GSTAGES;
            int k0 = nxt * 16;
#pragma unroll
            for (int u = 0; u < 2; u++) {
                cp_async16(asBase + (uint32_t)(((s*128 + ar[u])*20 + ac[u]) * 4),
                           A + (size_t)(m0 + ar[u]) * K + k0 + ac[u], aSz[u]);
                cp_async16(bsBase + (uint32_t)(((s*16 + br[u])*136 + bc[u]) * 4),
                           B + (size_t)(k0 + br[u]) * N + n0 + bc[u], 16);
            }
        }
        cp_commit();

        const uint32_t* Ab = As + (t % GSTAGES) * 128 * 20;
        const uint32_t* Bb = Bs + (t % GSTAGES) * 16 * 136;
#pragma unroll
        for (int ks = 0; ks < 2; ks++) {
            int kb = ks * 8;
            uint32_t af[4][4], bf[4][2];
#pragma unroll
            for (int mf = 0; mf < 4; mf++) {
                int r = wm*64 + mf*16 + g;
                af[mf][0] = Ab[(r    )*20 + kb + qd];
                af[mf][1] = Ab[(r + 8)*20 + kb + qd];
                af[mf][2] = Ab[(r    )*20 + kb + qd + 4];
                af[mf][3] = Ab[(r + 8)*20 + kb + qd + 4];
            }
#pragma unroll
            for (int nf = 0; nf < 4; nf++) {
                int c = wn*32 + nf*8 + g;
                bf[nf][0] = Bb[(kb + qd    )*136 + c];
                bf[nf][1] = Bb[(kb + qd + 4)*136 + c];
            }
#pragma unroll
            for (int mf = 0; mf < 4; mf++)
#pragma unroll
                for (int nf = 0; nf < 4; nf++)
                    mma_tf32(acc[mf][nf], af[mf], bf[nf]);
        }
    }

#pragma unroll
    for (int mf = 0; mf < 4; mf++) {
        int rbase = m0 + wm*64 + mf*16 + g;
#pragma unroll
        for (int half = 0; half < 2; half++) {
            int row = rbase + half*8;
            if (row >= M) continue;
#pragma unroll
            for (int nf = 0; nf < 4; nf++) {
                int col = n0 + wn*32 + nf*8 + 2*qd;
                float v0 = acc[mf][nf][half*2 + 0];
                float v1 = acc[mf][nf][half*2 + 1];
                if (EPI >= 1) { v0 += bias[col]; v1 += bias[col+1]; }
                if (EPI == 2) { v0 = gelu_exact(v0); v1 = gelu_exact(v1); }
                if (EPI == 3) {
                    v0 += res[(size_t)row * N + col];
                    v1 += res[(size_t)row * N + col + 1];
                }
                float2 o; o.x = v0; o.y = v1;
                *(float2*)(C + (size_t)row * N + col) = o;
            }
        }
    }
}

// ---------------- fp32 merge-metric path (exactness firewall) ----------------
// wkavg[c][d] = mean_h qkv_w[c][CDIM + h*DH + d]
__global__ __launch_bounds__(256) void wkavg_kernel(const float* __restrict__ qkv_w)
{
    int idx = blockIdx.x * 256 + threadIdx.x;
    if (idx >= CDIM*DH) return;
    int c = idx >> 6, d = idx & 63;
    const float* base = qkv_w + (size_t)c * (3*CDIM) + CDIM + d;
    float s = 0.f;
#pragma unroll
    for (int h = 0; h < HEADS; h++) s += base[h * DH];
    g_wkavg[idx] = s * (1.f / HEADS);
}

// partial metric = h @ wkavg over K chunk of 256  (split-K, fp32 SIMT)
__global__ __launch_bounds__(256) void metric_gemm_kernel()
{
    __shared__ float AsT[32][68];   // [k][tok]
    __shared__ float Bs [32][68];   // [k][d]
    int tid = threadIdx.x;
    int tx = tid & 15, ty = tid >> 4;
    int m0 = blockIdx.x * 64;
    int kb = blockIdx.y * 256;

    float acc[4][4];
#pragma unroll
    for (int i = 0; i < 4; i++)
#pragma unroll
        for (int j = 0; j < 4; j++) acc[i][j] = 0.f;

    for (int k0 = kb; k0 < kb + 256; k0 += 32) {
        __syncthreads();
#pragma unroll
        for (int u = 0; u < 2; u++) {
            int idx = tid*2 + u;
            int tok = idx >> 3, kc = (idx & 7) * 4;
            float4 v = *(const float4*)(g_h + (size_t)(m0 + tok) * CDIM + k0 + kc);
            AsT[kc+0][tok] = v.x; AsT[kc+1][tok] = v.y;
            AsT[kc+2][tok] = v.z; AsT[kc+3][tok] = v.w;
            int kr = idx >> 4, d = (idx & 15) * 4;
            *(float4*)&Bs[kr][d] = *(const float4*)(g_wkavg + (size_t)(k0 + kr) * DH + d);
        }
        __syncthreads();
#pragma unroll
        for (int k = 0; k < 32; k++) {
            float4 a = *(float4*)&AsT[k][ty*4];
            float4 b = *(float4*)&Bs[k][tx*4];
            float aa[4] = {a.x, a.y, a.z, a.w};
            float bb[4] = {b.x, b.y, b.z, b.w};
#pragma unroll
            for (int i = 0; i < 4; i++)
#pragma unroll
                for (int j = 0; j < 4; j++)
                    acc[i][j] = fmaf(aa[i], bb[j], acc[i][j]);
        }
    }
    float* dst = g_mpart + (size_t)blockIdx.y * NTOK * DH;
#pragma unroll
    for (int i = 0; i < 4; i++)
#pragma unroll
        for (int j = 0; j < 4; j++)
            dst[(size_t)(m0 + ty*4 + i) * DH + tx*4 + j] = acc[i][j];
}

// sum 4 partials (fixed order) + row-normalize -> g_nmet
__global__ __launch_bounds__(256) void metric_norm_kernel()
{
    int row = blockIdx.x * 8 + (threadIdx.x >> 5);
    int lane = threadIdx.x & 31;
    size_t off = (size_t)row * DH + lane*2;
    float2 v = *(float2*)&g_mpart[off];
#pragma unroll
    for (int p = 1; p < 4; p++) {
        float2 u = *(float2*)&g_mpart[(size_t)p * NTOK * DH + off];
        v.x += u.x; v.y += u.y;
    }
    float sq = v.x*v.x + v.y*v.y;
#pragma unroll
    for (int o = 16; o > 0; o >>= 1)
        sq += __shfl_xor_sync(0xffffffffu, sq, o);
    float nrm = sqrtf(sq);
    v.x /= nrm; v.y /= nrm;
    *(float2*)&g_nmet[off] = v;
}

// ---------------- tensor-core flash attention (64q x 64k, dh=64) -------------
#define ATP 68   // smem pitch (words): addr%32 = g*4+qd -> conflict-free frags

__global__ __launch_bounds__(128) void attn_tc_kernel(
    const float* __restrict__ qkv, const float* __restrict__ sizev,
    float* __restrict__ xa)
{
    extern __shared__ uint32_t smu[];
    uint32_t* Qs   = smu;                    // [64][ATP] tf32 (scaled by 0.125)
    uint32_t* Ks   = smu + 64*ATP;           // [64][ATP] tf32 (token-major)
    uint32_t* VsT  = smu + 2*64*ATP;         // [64][ATP] tf32 (d-major)
    uint32_t* Ps   = smu + 3*64*ATP;         // [64][ATP] tf32
    float*    logs = (float*)(smu + 4*64*ATP); // [64]

    int tid  = threadIdx.x;
    int lane = tid & 31, w = tid >> 5;
    int g = lane >> 2, qd = lane & 3;
    int h = blockIdx.y;
    int q0 = blockIdx.x * 64;
    int wq = w * 16;
    int qrow0 = (wq + g) * ATP, qrow1 = (wq + g + 8) * ATP;

    { // load Q tile (tf32, pre-scaled)
        int tok = tid & 63, chunk = tid >> 6;
        const float* src = qkv + (size_t)(q0 + tok) * (3*CDIM) + h*DH + chunk*32;
#pragma unroll
        for (int f = 0; f < 8; f++) {
            float4 v = *(const float4*)(src + f*4);
            uint4 u;
            u.x = f2tf32(v.x * 0.125f); u.y = f2tf32(v.y * 0.125f);
            u.z = f2tf32(v.z * 0.125f); u.w = f2tf32(v.w * 0.125f);
            *(uint4*)&Qs[tok*ATP + chunk*32 + f*4] = u;
        }
    }

    float O[8][4];
#pragma unroll
    for (int dt = 0; dt < 8; dt++)
#pragma unroll
        for (int r = 0; r < 4; r++) O[dt][r] = 0.f;
    float rm0 = -3.0e38f, rm1 = -3.0e38f, rl0 = 0.f, rl1 = 0.f;

    for (int kt = 0; kt < NTOK/64; kt++) {
        int k0 = kt * 64;
        __syncthreads();
        {
            int tok = tid & 63, chunk = tid >> 6;
            const float* ksrc = qkv + (size_t)(k0 + tok)*(3*CDIM) + CDIM + h*DH + chunk*32;
            const float* vsrc = ksrc + CDIM;
#pragma unroll
            for (int f = 0; f < 8; f++) {
                float4 kv = *(const float4*)(ksrc + f*4);
                uint4 u;
                u.x = f2tf32(kv.x); u.y = f2tf32(kv.y);
                u.z = f2tf32(kv.z); u.w = f2tf32(kv.w);
                *(uint4*)&Ks[tok*ATP + chunk*32 + f*4] = u;
                float4 vv = *(const float4*)(vsrc + f*4);
                int d = chunk*32 + f*4;
                VsT[(d+0)*ATP + tok] = f2tf32(vv.x);
                VsT[(d+1)*ATP + tok] = f2tf32(vv.y);
                VsT[(d+2)*ATP + tok] = f2tf32(vv.z);
                VsT[(d+3)*ATP + tok] = f2tf32(vv.w);
            }
            if (tid < 64) logs[tid] = __logf(sizev[k0 + tid]);
        }
        __syncthreads();

        float S[8][4];
#pragma unroll
        for (int nt = 0; nt < 8; nt++)
#pragma unroll
            for (int r = 0; r < 4; r++) S[nt][r] = 0.f;
#pragma unroll
        for (int kb = 0; kb < 8; kb++) {
            uint32_t a[4];
            a[0] = Qs[qrow0 + kb*8 + qd];
            a[1] = Qs[qrow1 + kb*8 + qd];
            a[2] = Qs[qrow0 + kb*8 + qd + 4];
            a[3] = Qs[qrow1 + kb*8 + qd + 4];
#pragma unroll
            for (int nt = 0; nt < 8; nt++) {
                uint32_t b[2];
                b[0] = Ks[(nt*8 + g)*ATP + kb*8 + qd];
                b[1] = Ks[(nt*8 + g)*ATP + kb*8 + qd + 4];
                mma_tf32(S[nt], a, b);
            }
        }

        float m0 = -3.0e38f, m1 = -3.0e38f;
#pragma unroll
        for (int nt = 0; nt < 8; nt++) {
            float l0 = logs[nt*8 + 2*qd], l1 = logs[nt*8 + 2*qd + 1];
            S[nt][0] += l0; S[nt][1] += l1;
            S[nt][2] += l0; S[nt][3] += l1;
            m0 = fmaxf(m0, fmaxf(S[nt][0], S[nt][1]));
            m1 = fmaxf(m1, fmaxf(S[nt][2], S[nt][3]));
        }
#pragma unroll
        for (int off = 1; off < 4; off <<= 1) {
            m0 = fmaxf(m0, __shfl_xor_sync(0xffffffffu, m0, off));
            m1 = fmaxf(m1, __shfl_xor_sync(0xffffffffu, m1, off));
        }
        float n0 = fmaxf(rm0, m0), n1 = fmaxf(rm1, m1);
        float c0 = __expf(rm0 - n0), c1 = __expf(rm1 - n1);
        float s0 = 0.f, s1 = 0.f;
#pragma unroll
        for (int nt = 0; nt < 8; nt++) {
            S[nt][0] = __expf(S[nt][0] - n0);
            S[nt][1] = __expf(S[nt][1] - n0);
            S[nt][2] = __expf(S[nt][2] - n1);
            S[nt][3] = __expf(S[nt][3] - n1);
            s0 += S[nt][0] + S[nt][1];
            s1 += S[nt][2] + S[nt][3];
        }
#pragma unroll
        for (int off = 1; off < 4; off <<= 1) {
            s0 += __shfl_xor_sync(0xffffffffu, s0, off);
            s1 += __shfl_xor_sync(0xffffffffu, s1, off);
        }
        rl0 = rl0 * c0 + s0;  rl1 = rl1 * c1 + s1;
        rm0 = n0; rm1 = n1;
#pragma unroll
        for (int dt = 0; dt < 8; dt++) {
            O[dt][0] *= c0; O[dt][1] *= c0;
            O[dt][2] *= c1; O[dt][3] *= c1;
        }

#pragma unroll
        for (int nt = 0; nt < 8; nt++) {
            uint2 u01, u23;
            u01.x = f2tf32(S[nt][0]); u01.y = f2tf32(S[nt][1]);
            u23.x = f2tf32(S[nt][2]); u23.y = f2tf32(S[nt][3]);
            *(uint2*)&Ps[qrow0 + nt*8 + 2*qd] = u01;
            *(uint2*)&Ps[qrow1 + nt*8 + 2*qd] = u23;
        }
        __syncwarp();

#pragma unroll
        for (int kb = 0; kb < 8; kb++) {
            uint32_t a[4];
            a[0] = Ps[qrow0 + kb*8 + qd];
            a[1] = Ps[qrow1 + kb*8 + qd];
            a[2] = Ps[qrow0 + kb*8 + qd + 4];
            a[3] = Ps[qrow1 + kb*8 + qd + 4];
#pragma unroll
            for (int dt = 0; dt < 8; dt++) {
                uint32_t b[2];
                b[0] = VsT[(dt*8 + g)*ATP + kb*8 + qd];
                b[1] = VsT[(dt*8 + g)*ATP + kb*8 + qd + 4];
                mma_tf32(O[dt], a, b);
            }
        }
    }

    float i0 = 1.f / rl0, i1 = 1.f / rl1;
    int row0 = q0 + wq + g, row1 = row0 + 8;
#pragma unroll
    for (int dt = 0; dt < 8; dt++) {
        int col = h*DH + dt*8 + 2*qd;
        float2 o0; o0.x = O[dt][0]*i0; o0.y = O[dt][1]*i0;
        float2 o1; o1.x = O[dt][2]*i1; o1.y = O[dt][3]*i1;
        *(float2*)&xa[(size_t)row0 * CDIM + col] = o0;
        *(float2*)&xa[(size_t)row1 * CDIM + col] = o1;
    }
}

// ---------------- merge scoring: per-src max/argmax over dst -----------------
__global__ __launch_bounds__(256) void merge_score_kernel(const float* __restrict__ thr)
{
    int i = blockIdx.x, tid = threadIdx.x;
    __shared__ float srcv[64];
    if (tid < 64) srcv[tid] = g_nmet[(size_t)(2*i) * DH + tid];
    __syncthreads();
    float best = -3.0e38f; int bestj = 0;
    for (int j = tid; j < NSRC; j += 256) {
        const float* dv = g_nmet + (size_t)(2*j + 1) * DH;
        float dot = 0.f;
#pragma unroll
        for (int d = 0; d < 64; d++) dot = fmaf(srcv[d], dv[d], dot);
        if (dot > best) { best = dot; bestj = j; }
    }
    __shared__ float bm[256]; __shared__ int bi[256];
    bm[tid] = best; bi[tid] = bestj;
    __syncthreads();
    for (int off = 128; off > 0; off >>= 1) {
        if (tid < off) {
            if (bm[tid+off] > bm[tid] ||
                (bm[tid+off] == bm[tid] && bi[tid+off] < bi[tid])) {
                bm[tid] = bm[tid+off]; bi[tid] = bi[tid+off];
            }
        }
        __syncthreads();
    }
    if (tid == 0) {
        if (i == 0) { g_mask[0] = 0; g_node[0] = 0; }
        else { g_mask[i] = (bm[0] > thr[0]) ? 1 : 0; g_node[i] = bi[0]; }
    }
}

// ---------------- exclusive prefix scan of !mask -----------------------------
__global__ __launch_bounds__(1024) void scan_kernel()
{
    __shared__ int s[NSRC];
    int tid = threadIdx.x;
    int f = g_mask[tid] ? 0 : 1;
    s[tid] = f;
    __syncthreads();
    for (int off = 1; off < NSRC; off <<= 1) {
        int v = 0;
        if (tid >= off) v = s[tid - off];
        __syncthreads();
        s[tid] += v;
        __syncthreads();
    }
    g_pref[tid] = s[tid] - f;
    if (tid == NSRC-1) g_nUnm[0] = s[NSRC-1];
}

// ---------------- build unmerged rows ----------------------------------------
__global__ __launch_bounds__(256) void unm_kernel(const float* __restrict__ sizev)
{
    int i = blockIdx.x;
    if (g_mask[i]) return;
    int r = g_pref[i];
    float s = sizev[2*i];
    const float* xr = g_x1 + (size_t)(2*i) * CDIM;
    float* orow = g_outx + (size_t)r * CDIM;
    for (int c = threadIdx.x; c < CDIM; c += 256) orow[c] = xr[c] * s;
    if (threadIdx.x == 0) g_outs[r] = s;
}

// ---------------- build dst rows (deterministic gather of merges) ------------
__global__ __launch_bounds__(256) void dst_build_kernel(const float* __restrict__ sizev)
{
    int j = blockIdx.x, tid = threadIdx.x;
    int nU = g_nUnm[0];
    float s0 = sizev[2*j + 1];
    const float* dr = g_x1 + (size_t)(2*j + 1) * CDIM;
    float a0 = dr[tid]       * s0;
    float a1 = dr[tid + 256] * s0;
    float a2 = dr[tid + 512] * s0;
    float a3 = dr[tid + 768] * s0;
    float stot = s0;
    for (int i = 0; i < NSRC; i++) {
        if (g_mask[i] && g_node[i] == j) {
            float si = sizev[2*i];
            const float* xr = g_x1 + (size_t)(2*i) * CDIM;
            a0 += xr[tid]       * si;
            a1 += xr[tid + 256] * si;
            a2 += xr[tid + 512] * si;
            a3 += xr[tid + 768] * si;
            stot += si;
        }
    }
    size_t r = (size_t)(nU + j) * CDIM;
    g_outx[r + tid]       = a0;
    g_outx[r + tid + 256] = a1;
    g_outx[r + tid + 512] = a2;
    g_outx[r + tid + 768] = a3;
    if (tid == 0) g_outs[nU + j] = stot;
}

// ---------------- x2 = outx / size -------------------------------------------
__global__ __launch_bounds__(256) void div_kernel()
{
    int r = blockIdx.x;
    float s = g_outs[r];
    for (int c = threadIdx.x; c < CDIM; c += 256)
        g_x2[(size_t)r * CDIM + c] = g_outx[(size_t)r * CDIM + c] / s;
}

// ---------------- pack output [x rows | size] --------------------------------
__global__ __launch_bounds__(256) void out_copy_kernel(float* __restrict__ out,
                                                       int Nout, int packSize)
{
    int idx = blockIdx.x * 256 + threadIdx.x;
    int totalx = Nout * CDIM;
    if (idx < totalx) out[idx] = g_xout[idx];
    else if (packSize && idx < totalx + Nout) out[idx] = g_outs[idx - totalx];
}

// ---------------- launcher ---------------------------------------------------
extern "C" void kernel_launch(void* const* d_in, const int* in_sizes, int n_in,
                              void* d_out, int out_size)
{
    const float* x      = (const float*)d_in[0];
    const float* sizev  = (const float*)d_in[1];
    const float* qkv_w  = (const float*)d_in[2];
    const float* proj_w = (const float*)d_in[3];
    const float* proj_b = (const float*)d_in[4];
    const float* ln1_g  = (const float*)d_in[5];
    const float* ln1_b  = (const float*)d_in[6];
    const float* ln2_g  = (const float*)d_in[7];
    const float* ln2_b  = (const float*)d_in[8];
    const float* fc1_w  = (const float*)d_in[9];
    const float* fc1_b  = (const float*)d_in[10];
    const float* fc2_w  = (const float*)d_in[11];
    const float* fc2_b  = (const float*)d_in[12];
    const float* thr    = (const float*)d_in[13];
    float* out = (float*)d_out;

    int Nout, packSize;
    if (out_size % (CDIM + 1) == 0) { Nout = out_size / (CDIM + 1); packSize = 1; }
    else                            { Nout = out_size / CDIM;       packSize = 0; }
    if (Nout > NTOK) Nout = NTOK;

    float *p_h, *p_qkv, *p_xa, *p_x1, *p_x2, *p_h2, *p_ff, *p_xout;
    cudaGetSymbolAddress((void**)&p_h,    g_h);
    cudaGetSymbolAddress((void**)&p_qkv,  g_qkv);
    cudaGetSymbolAddress((void**)&p_xa,   g_xa);
    cudaGetSymbolAddress((void**)&p_x1,   g_x1);
    cudaGetSymbolAddress((void**)&p_x2,   g_x2);
    cudaGetSymbolAddress((void**)&p_h2,   g_h2);
    cudaGetSymbolAddress((void**)&p_ff,   g_ff);
    cudaGetSymbolAddress((void**)&p_xout, g_xout);

    const int ATTN_SMEM = (4*64*ATP + 64) * (int)sizeof(uint32_t);
    cudaFuncSetAttribute(attn_tc_kernel, cudaFuncAttributeMaxDynamicSharedMemorySize, ATTN_SMEM);
    cudaFuncSetAttribute(gemm_tf32<0>, cudaFuncAttributeMaxDynamicSharedMemorySize, GEMM_SMEM);
    cudaFuncSetAttribute(gemm_tf32<2>, cudaFuncAttributeMaxDynamicSharedMemorySize, GEMM_SMEM);
    cudaFuncSetAttribute(gemm_tf32<3>, cudaFuncAttributeMaxDynamicSharedMemorySize, GEMM_SMEM);

    // 1. LN1
    ln_kernel<<<NTOK, 256>>>(x, ln1_g, ln1_b, p_h, NTOK);
    // 2a. averaged K-weights (fp32 merge-metric firewall)
    wkavg_kernel<<<(CDIM*DH + 255)/256, 256>>>(qkv_w);
    // 2b. QKV = h @ qkv_w   (tf32 tensor cores, cp.async pipeline)
    gemm_tf32<0><<<dim3(3*CDIM/128, NTOK/128), 256, GEMM_SMEM>>>(
        p_h, qkv_w, nullptr, nullptr, p_qkv, NTOK, 3*CDIM, CDIM);
    // 3. metric = normalize(h @ wkavg)  (fp32 split-K, exact mask decisions)
    metric_gemm_kernel<<<dim3(NTOK/64, 4), 256>>>();
    metric_norm_kernel<<<NTOK/8, 256>>>();
    // 4. attention -> xa  (tf32 tensor cores)
    attn_tc_kernel<<<dim3(NTOK/64, HEADS), 128, ATTN_SMEM>>>(p_qkv, sizev, p_xa);
    // 5. x1 = x + xa @ proj_w + proj_b  (tf32)
    gemm_tf32<3><<<dim3(CDIM/128, NTOK/128), 256, GEMM_SMEM>>>(
        p_xa, proj_w, proj_b, x, p_x1, NTOK, CDIM, CDIM);
    // 6. merge scores
    merge_score_kernel<<<NSRC, 256>>>(thr);
    // 7. prefix scan
    scan_kernel<<<1, 1024>>>();
    // 8. unmerged rows
    unm_kernel<<<NSRC, 256>>>(sizev);
    // 9. dst rows
    dst_build_kernel<<<NSRC, 256>>>(sizev);
    // 10. x2 = outx / size
    div_kernel<<<Nout, 256>>>();
    // 11. LN2
    ln_kernel<<<Nout, 256>>>(p_x2, ln2_g, ln2_b, p_h2, Nout);
    // 12. ff = gelu(h2 @ fc1_w + fc1_b)  (tf32)
    gemm_tf32<2><<<dim3(FF/128, (Nout + 127)/128), 256, GEMM_SMEM>>>(
        p_h2, fc1_w, fc1_b, nullptr, p_ff, Nout, FF, CDIM);
    // 13. xout = x2 + ff @ fc2_w + fc2_b  (tf32)
    gemm_tf32<3><<<dim3(CDIM/128, (Nout + 127)/128), 256, GEMM_SMEM>>>(
        p_ff, fc2_w, fc2_b, p_x2, p_xout, Nout, CDIM, FF);
    // 14. pack output
    int totalOut = Nout * CDIM + (packSize ? Nout : 0);
    out_copy_kernel<<<(totalOut + 255)/256, 256>>>(out, Nout, packSize);
}

// round 8
// speedup vs baseline: 2.4490x; 1.0671x over previous
#include <cuda_runtime.h>
#include <math.h>
#include <stdint.h>

// Problem constants (fixed shapes from setup_inputs)
#define NTOK 2048
#define CDIM 1024
#define HEADS 16
#define DH 64
#define FF 4096
#define NSRC 1024   // NTOK/2

// ---------------- scratch (device globals; no allocation allowed) ------------
__device__ float g_h    [NTOK*CDIM];
__device__ float g_hr   [NTOK*CDIM];    // tf32-rounded h (GEMM input)
__device__ float g_qkv  [NTOK*3*CDIM];
__device__ float g_wkavg[CDIM*DH];
__device__ float g_mpart[8*NTOK*DH];
__device__ float g_nmet [NTOK*DH];
__device__ float g_xa   [NTOK*CDIM];    // rounded at attn epilogue
__device__ float g_x1   [NTOK*CDIM];
__device__ int   g_mask [NSRC];
__device__ int   g_node [NSRC];
__device__ int   g_pref [NSRC];
__device__ int   g_nUnm [1];
__device__ float g_outx [NTOK*CDIM];
__device__ float g_outs [NTOK];
__device__ float g_x2   [NTOK*CDIM];
__device__ float g_h2   [NTOK*CDIM];    // rounded at LN2
__device__ float g_ff   [NTOK*FF];      // rounded at fc1 epilogue
__device__ float g_xout [NTOK*CDIM];
// tf32-rounded weight copies
__device__ float g_wqkv [CDIM*3*CDIM];
__device__ float g_wproj[CDIM*CDIM];
__device__ float g_wfc1 [CDIM*FF];
__device__ float g_wfc2 [FF*CDIM];

// ---------------- helpers ----------------------------------------------------
__device__ __forceinline__ uint32_t f2tf32(float v) {
    uint32_t r;
    asm("cvt.rna.tf32.f32 %0, %1;" : "=r"(r) : "f"(v));
    return r;
}
__device__ __forceinline__ float rnd_tf32(float v) {
    return __uint_as_float(f2tf32(v));
}

__device__ __forceinline__ void mma_tf32(float c[4], const uint32_t a[4],
                                         const uint32_t b[2]) {
    asm volatile(
        "mma.sync.aligned.m16n8k8.row.col.f32.tf32.tf32.f32 "
        "{%0,%1,%2,%3}, {%4,%5,%6,%7}, {%8,%9}, {%0,%1,%2,%3};\n"
        : "+f"(c[0]), "+f"(c[1]), "+f"(c[2]), "+f"(c[3])
        : "r"(a[0]), "r"(a[1]), "r"(a[2]), "r"(a[3]), "r"(b[0]), "r"(b[1]));
}

__device__ __forceinline__ void cp_async16(uint32_t dst, const void* src, int szbytes) {
    asm volatile("cp.async.cg.shared.global [%0], [%1], 16, %2;\n"
                 :: "r"(dst), "l"(src), "r"(szbytes));
}
__device__ __forceinline__ void cp_commit() {
    asm volatile("cp.async.commit_group;\n");
}
template <int N>
__device__ __forceinline__ void cp_wait() {
    asm volatile("cp.async.wait_group %0;\n" :: "n"(N));
}

__device__ __forceinline__ float gelu_exact(float v) {
    return 0.5f * v * (1.0f + erff(v * 0.70710678118654752440f));
}

// ---------------- tf32 pre-rounding of a buffer ------------------------------
__global__ __launch_bounds__(256) void round_kernel(
    const float* __restrict__ in, float* __restrict__ out, int n4)
{
    int i = blockIdx.x * 256 + threadIdx.x;
    if (i >= n4) return;
    float4 v = ((const float4*)in)[i];
    v.x = rnd_tf32(v.x); v.y = rnd_tf32(v.y);
    v.z = rnd_tf32(v.z); v.w = rnd_tf32(v.w);
    ((float4*)out)[i] = v;
}

// ---------------- layernorm (optional exact + rounded outputs) ---------------
__global__ __launch_bounds__(256) void ln_kernel(
    const float* __restrict__ x, const float* __restrict__ g,
    const float* __restrict__ b, float* __restrict__ out,
    float* __restrict__ out_r, int M)
{
    int row = blockIdx.x;
    if (row >= M) return;
    const float* xr = x + (size_t)row * CDIM;
    int tid = threadIdx.x;
    float v[4];
    float s = 0.f, sq = 0.f;
#pragma unroll
    for (int t = 0; t < 4; t++) {
        float vv = xr[tid + t*256];
        v[t] = vv; s += vv; sq += vv*vv;
    }
    __shared__ float rs[256], rq[256];
    rs[tid] = s; rq[tid] = sq;
    __syncthreads();
    for (int off = 128; off > 0; off >>= 1) {
        if (tid < off) { rs[tid] += rs[tid+off]; rq[tid] += rq[tid+off]; }
        __syncthreads();
    }
    float mean = rs[0] * (1.f/CDIM);
    float var  = rq[0] * (1.f/CDIM) - mean*mean;
    float rstd = rsqrtf(var + 1e-5f);
#pragma unroll
    for (int t = 0; t < 4; t++) {
        int c = tid + t*256;
        float o = (v[t] - mean) * rstd * g[c] + b[c];
        if (out)   out  [(size_t)row * CDIM + c] = o;
        if (out_r) out_r[(size_t)row * CDIM + c] = rnd_tf32(o);
    }
}

// ---------------- TF32 tensor-core GEMM, cp.async 4-stage --------------------
// Inputs must be tf32-representable fp32 (pre-rounded) -> truncation is exact.
// EPI: 0 = A@B ; 1 = +bias ; 2 = gelu(+bias) ; 3 = +bias +res
// RND: round output to tf32 (when it feeds another GEMM)
#define GSTAGES 4
#define AS_WORDS (GSTAGES*128*20)
#define BS_WORDS (GSTAGES*16*136)
#define GEMM_SMEM ((AS_WORDS + BS_WORDS) * 4)

template <int EPI, int RND>
__global__ __launch_bounds__(256) void gemm_tf32(
    const float* __restrict__ A, const float* __restrict__ B,
    const float* __restrict__ bias, const float* __restrict__ res,
    float* __restrict__ C, int M, int N, int K)
{
    extern __shared__ uint32_t gsm[];
    uint32_t* As = gsm;              // [s][128][20]
    uint32_t* Bs = gsm + AS_WORDS;   // [s][16][136]

    int tid  = threadIdx.x;
    int lane = tid & 31, wid = tid >> 5;
    int wm = wid >> 2, wn = wid & 3;
    int g  = lane >> 2, qd = lane & 3;
    int m0 = blockIdx.y * 128, n0 = blockIdx.x * 128;

    float acc[4][4][4];
#pragma unroll
    for (int i = 0; i < 4; i++)
#pragma unroll
        for (int j = 0; j < 4; j++)
#pragma unroll
            for (int r = 0; r < 4; r++) acc[i][j][r] = 0.f;

    const int nT = K >> 4;

    int ar[2], ac[2], br[2], bc[2];
#pragma unroll
    for (int u = 0; u < 2; u++) {
        int idx = tid*2 + u;
        ar[u] = idx >> 2;  ac[u] = (idx & 3) * 4;
        br[u] = idx >> 5;  bc[u] = (idx & 31) * 4;
    }
    uint32_t asBase = (uint32_t)__cvta_generic_to_shared(As);
    uint32_t bsBase = (uint32_t)__cvta_generic_to_shared(Bs);
    int aSz[2];
#pragma unroll
    for (int u = 0; u < 2; u++) aSz[u] = (m0 + ar[u] < M) ? 16 : 0;

    // prologue: issue first GSTAGES-1 tiles
#pragma unroll
    for (int t = 0; t < GSTAGES-1; t++) {
        int k0 = t * 16;
#pragma unroll
        for (int u = 0; u < 2; u++) {
            cp_async16(asBase + (uint32_t)(((t*128 + ar[u])*20 + ac[u]) * 4),
                       A + (size_t)(m0 + ar[u]) * K + k0 + ac[u], aSz[u]);
            cp_async16(bsBase + (uint32_t)(((t*16 + br[u])*136 + bc[u]) * 4),
                       B + (size_t)(k0 + br[u]) * N + n0 + bc[u], 16);
        }
        cp_commit();
    }

    for (int t = 0; t < nT; t++) {
        cp_wait<GSTAGES-2>();
        __syncthreads();

        int nxt = t + GSTAGES - 1;
        if (nxt < nT) {
            int s  = nxt % GSTAGES;
            int k0 = nxt * 16;
#pragma unroll
            for (int u = 0; u < 2; u++) {
                cp_async16(asBase + (uint32_t)(((s*128 + ar[u])*20 + ac[u]) * 4),
                           A + (size_t)(m0 + ar[u]) * K + k0 + ac[u], aSz[u]);
                cp_async16(bsBase + (uint32_t)(((s*16 + br[u])*136 + bc[u]) * 4),
                           B + (size_t)(k0 + br[u]) * N + n0 + bc[u], 16);
            }
        }
        cp_commit();

        const uint32_t* Ab = As + (t % GSTAGES) * 128 * 20;
        const uint32_t* Bb = Bs + (t % GSTAGES) * 16 * 136;
#pragma unroll
        for (int ks = 0; ks < 2; ks++) {
            int kb = ks * 8;
            uint32_t af[4][4], bf[4][2];
#pragma unroll
            for (int mf = 0; mf < 4; mf++) {
                int r = wm*64 + mf*16 + g;
                af[mf][0] = Ab[(r    )*20 + kb + qd];
                af[mf][1] = Ab[(r + 8)*20 + kb + qd];
                af[mf][2] = Ab[(r    )*20 + kb + qd + 4];
                af[mf][3] = Ab[(r + 8)*20 + kb + qd + 4];
            }
#pragma unroll
            for (int nf = 0; nf < 4; nf++) {
                int c = wn*32 + nf*8 + g;
                bf[nf][0] = Bb[(kb + qd    )*136 + c];
                bf[nf][1] = Bb[(kb + qd + 4)*136 + c];
            }
#pragma unroll
            for (int mf = 0; mf < 4; mf++)
#pragma unroll
                for (int nf = 0; nf < 4; nf++)
                    mma_tf32(acc[mf][nf], af[mf], bf[nf]);
        }
    }

#pragma unroll
    for (int mf = 0; mf < 4; mf++) {
        int rbase = m0 + wm*64 + mf*16 + g;
#pragma unroll
        for (int half = 0; half < 2; half++) {
            int row = rbase + half*8;
            if (row >= M) continue;
#pragma unroll
            for (int nf = 0; nf < 4; nf++) {
                int col = n0 + wn*32 + nf*8 + 2*qd;
                float v0 = acc[mf][nf][half*2 + 0];
                float v1 = acc[mf][nf][half*2 + 1];
                if (EPI >= 1) { v0 += bias[col]; v1 += bias[col+1]; }
                if (EPI == 2) { v0 = gelu_exact(v0); v1 = gelu_exact(v1); }
                if (EPI == 3) {
                    v0 += res[(size_t)row * N + col];
                    v1 += res[(size_t)row * N + col + 1];
                }
                if (RND) { v0 = rnd_tf32(v0); v1 = rnd_tf32(v1); }
                float2 o; o.x = v0; o.y = v1;
                *(float2*)(C + (size_t)row * N + col) = o;
            }
        }
    }
}

// ---------------- fp32 merge-metric path (exactness firewall) ----------------
// wkavg[c][d] = mean_h qkv_w[c][CDIM + h*DH + d]
__global__ __launch_bounds__(256) void wkavg_kernel(const float* __restrict__ qkv_w)
{
    int idx = blockIdx.x * 256 + threadIdx.x;
    if (idx >= CDIM*DH) return;
    int c = idx >> 6, d = idx & 63;
    const float* base = qkv_w + (size_t)c * (3*CDIM) + CDIM + d;
    float s = 0.f;
#pragma unroll
    for (int h = 0; h < HEADS; h++) s += base[h * DH];
    g_wkavg[idx] = s * (1.f / HEADS);
}

// partial metric = h @ wkavg over K chunk of 128  (split-K x8, fp32 SIMT)
__global__ __launch_bounds__(256) void metric_gemm_kernel()
{
    __shared__ float AsT[32][68];   // [k][tok]
    __shared__ float Bs [32][68];   // [k][d]
    int tid = threadIdx.x;
    int tx = tid & 15, ty = tid >> 4;
    int m0 = blockIdx.x * 64;
    int kb = blockIdx.y * 128;

    float acc[4][4];
#pragma unroll
    for (int i = 0; i < 4; i++)
#pragma unroll
        for (int j = 0; j < 4; j++) acc[i][j] = 0.f;

    for (int k0 = kb; k0 < kb + 128; k0 += 32) {
        __syncthreads();
#pragma unroll
        for (int u = 0; u < 2; u++) {
            int idx = tid*2 + u;
            int tok = idx >> 3, kc = (idx & 7) * 4;
            float4 v = *(const float4*)(g_h + (size_t)(m0 + tok) * CDIM + k0 + kc);
            AsT[kc+0][tok] = v.x; AsT[kc+1][tok] = v.y;
            AsT[kc+2][tok] = v.z; AsT[kc+3][tok] = v.w;
            int kr = idx >> 4, d = (idx & 15) * 4;
            *(float4*)&Bs[kr][d] = *(const float4*)(g_wkavg + (size_t)(k0 + kr) * DH + d);
        }
        __syncthreads();
#pragma unroll
        for (int k = 0; k < 32; k++) {
            float4 a = *(float4*)&AsT[k][ty*4];
            float4 b = *(float4*)&Bs[k][tx*4];
            float aa[4] = {a.x, a.y, a.z, a.w};
            float bb[4] = {b.x, b.y, b.z, b.w};
#pragma unroll
            for (int i = 0; i < 4; i++)
#pragma unroll
                for (int j = 0; j < 4; j++)
                    acc[i][j] = fmaf(aa[i], bb[j], acc[i][j]);
        }
    }
    float* dst = g_mpart + (size_t)blockIdx.y * NTOK * DH;
#pragma unroll
    for (int i = 0; i < 4; i++)
#pragma unroll
        for (int j = 0; j < 4; j++)
            dst[(size_t)(m0 + ty*4 + i) * DH + tx*4 + j] = acc[i][j];
}

// sum 8 partials (fixed order) + row-normalize -> g_nmet
__global__ __launch_bounds__(256) void metric_norm_kernel()
{
    int row = blockIdx.x * 8 + (threadIdx.x >> 5);
    int lane = threadIdx.x & 31;
    size_t off = (size_t)row * DH + lane*2;
    float2 v = *(float2*)&g_mpart[off];
#pragma unroll
    for (int p = 1; p < 8; p++) {
        float2 u = *(float2*)&g_mpart[(size_t)p * NTOK * DH + off];
        v.x += u.x; v.y += u.y;
    }
    float sq = v.x*v.x + v.y*v.y;
#pragma unroll
    for (int o = 16; o > 0; o >>= 1)
        sq += __shfl_xor_sync(0xffffffffu, sq, o);
    float nrm = sqrtf(sq);
    v.x /= nrm; v.y /= nrm;
    *(float2*)&g_nmet[off] = v;
}

// ---------------- tensor-core flash attention (64q x 64k, dh=64) -------------
#define ATP 68   // smem pitch (words): addr%32 = g*4+qd -> conflict-free frags

__global__ __launch_bounds__(128) void attn_tc_kernel(
    const float* __restrict__ qkv, const float* __restrict__ sizev,
    float* __restrict__ xa)
{
    extern __shared__ uint32_t smu[];
    uint32_t* Qs   = smu;                    // [64][ATP] tf32 (scaled by 0.125)
    uint32_t* Ks   = smu + 64*ATP;           // [64][ATP] tf32 (token-major)
    uint32_t* VsT  = smu + 2*64*ATP;         // [64][ATP] tf32 (d-major)
    uint32_t* Ps   = smu + 3*64*ATP;         // [64][ATP] tf32
    float*    logs = (float*)(smu + 4*64*ATP); // [64]

    int tid  = threadIdx.x;
    int lane = tid & 31, w = tid >> 5;
    int g = lane >> 2, qd = lane & 3;
    int h = blockIdx.y;
    int q0 = blockIdx.x * 64;
    int wq = w * 16;
    int qrow0 = (wq + g) * ATP, qrow1 = (wq + g + 8) * ATP;

    { // load Q tile (tf32, pre-scaled)
        int tok = tid & 63, chunk = tid >> 6;
        const float* src = qkv + (size_t)(q0 + tok) * (3*CDIM) + h*DH + chunk*32;
#pragma unroll
        for (int f = 0; f < 8; f++) {
            float4 v = *(const float4*)(src + f*4);
            uint4 u;
            u.x = f2tf32(v.x * 0.125f); u.y = f2tf32(v.y * 0.125f);
            u.z = f2tf32(v.z * 0.125f); u.w = f2tf32(v.w * 0.125f);
            *(uint4*)&Qs[tok*ATP + chunk*32 + f*4] = u;
        }
    }

    float O[8][4];
#pragma unroll
    for (int dt = 0; dt < 8; dt++)
#pragma unroll
        for (int r = 0; r < 4; r++) O[dt][r] = 0.f;
    float rm0 = -3.0e38f, rm1 = -3.0e38f, rl0 = 0.f, rl1 = 0.f;

    for (int kt = 0; kt < NTOK/64; kt++) {
        int k0 = kt * 64;
        __syncthreads();
        {
            int tok = tid & 63, chunk = tid >> 6;
            const float* ksrc = qkv + (size_t)(k0 + tok)*(3*CDIM) + CDIM + h*DH + chunk*32;
            const float* vsrc = ksrc + CDIM;
#pragma unroll
            for (int f = 0; f < 8; f++) {
                float4 kv = *(const float4*)(ksrc + f*4);
                uint4 u;
                u.x = f2tf32(kv.x); u.y = f2tf32(kv.y);
                u.z = f2tf32(kv.z); u.w = f2tf32(kv.w);
                *(uint4*)&Ks[tok*ATP + chunk*32 + f*4] = u;
                float4 vv = *(const float4*)(vsrc + f*4);
                int d = chunk*32 + f*4;
                VsT[(d+0)*ATP + tok] = f2tf32(vv.x);
                VsT[(d+1)*ATP + tok] = f2tf32(vv.y);
                VsT[(d+2)*ATP + tok] = f2tf32(vv.z);
                VsT[(d+3)*ATP + tok] = f2tf32(vv.w);
            }
            if (tid < 64) logs[tid] = __logf(sizev[k0 + tid]);
        }
        __syncthreads();

        float S[8][4];
#pragma unroll
        for (int nt = 0; nt < 8; nt++)
#pragma unroll
            for (int r = 0; r < 4; r++) S[nt][r] = 0.f;
#pragma unroll
        for (int kb = 0; kb < 8; kb++) {
            uint32_t a[4];
            a[0] = Qs[qrow0 + kb*8 + qd];
            a[1] = Qs[qrow1 + kb*8 + qd];
            a[2] = Qs[qrow0 + kb*8 + qd + 4];
            a[3] = Qs[qrow1 + kb*8 + qd + 4];
#pragma unroll
            for (int nt = 0; nt < 8; nt++) {
                uint32_t b[2];
                b[0] = Ks[(nt*8 + g)*ATP + kb*8 + qd];
                b[1] = Ks[(nt*8 + g)*ATP + kb*8 + qd + 4];
                mma_tf32(S[nt], a, b);
            }
        }

        float m0 = -3.0e38f, m1 = -3.0e38f;
#pragma unroll
        for (int nt = 0; nt < 8; nt++) {
            float l0 = logs[nt*8 + 2*qd], l1 = logs[nt*8 + 2*qd + 1];
            S[nt][0] += l0; S[nt][1] += l1;
            S[nt][2] += l0; S[nt][3] += l1;
            m0 = fmaxf(m0, fmaxf(S[nt][0], S[nt][1]));
            m1 = fmaxf(m1, fmaxf(S[nt][2], S[nt][3]));
        }
#pragma unroll
        for (int off = 1; off < 4; off <<= 1) {
            m0 = fmaxf(m0, __shfl_xor_sync(0xffffffffu, m0, off));
            m1 = fmaxf(m1, __shfl_xor_sync(0xffffffffu, m1, off));
        }
        float n0 = fmaxf(rm0, m0), n1 = fmaxf(rm1, m1);
        float c0 = __expf(rm0 - n0), c1 = __expf(rm1 - n1);
        float s0 = 0.f, s1 = 0.f;
#pragma unroll
        for (int nt = 0; nt < 8; nt++) {
            S[nt][0] = __expf(S[nt][0] - n0);
            S[nt][1] = __expf(S[nt][1] - n0);
            S[nt][2] = __expf(S[nt][2] - n1);
            S[nt][3] = __expf(S[nt][3] - n1);
            s0 += S[nt][0] + S[nt][1];
            s1 += S[nt][2] + S[nt][3];
        }
#pragma unroll
        for (int off = 1; off < 4; off <<= 1) {
            s0 += __shfl_xor_sync(0xffffffffu, s0, off);
            s1 += __shfl_xor_sync(0xffffffffu, s1, off);
        }
        rl0 = rl0 * c0 + s0;  rl1 = rl1 * c1 + s1;
        rm0 = n0; rm1 = n1;
#pragma unroll
        for (int dt = 0; dt < 8; dt++) {
            O[dt][0] *= c0; O[dt][1] *= c0;
            O[dt][2] *= c1; O[dt][3] *= c1;
        }

#pragma unroll
        for (int nt = 0; nt < 8; nt++) {
            uint2 u01, u23;
            u01.x = f2tf32(S[nt][0]); u01.y = f2tf32(S[nt][1]);
            u23.x = f2tf32(S[nt][2]); u23.y = f2tf32(S[nt][3]);
            *(uint2*)&Ps[qrow0 + nt*8 + 2*qd] = u01;
            *(uint2*)&Ps[qrow1 + nt*8 + 2*qd] = u23;
        }
        __syncwarp();

#pragma unroll
        for (int kb = 0; kb < 8; kb++) {
            uint32_t a[4];
            a[0] = Ps[qrow0 + kb*8 + qd];
            a[1] = Ps[qrow1 + kb*8 + qd];
            a[2] = Ps[qrow0 + kb*8 + qd + 4];
            a[3] = Ps[qrow1 + kb*8 + qd + 4];
#pragma unroll
            for (int dt = 0; dt < 8; dt++) {
                uint32_t b[2];
                b[0] = VsT[(dt*8 + g)*ATP + kb*8 + qd];
                b[1] = VsT[(dt*8 + g)*ATP + kb*8 + qd + 4];
                mma_tf32(O[dt], a, b);
            }
        }
    }

    // epilogue: write tf32-rounded xa (feeds proj GEMM)
    float i0 = 1.f / rl0, i1 = 1.f / rl1;
    int row0 = q0 + wq + g, row1 = row0 + 8;
#pragma unroll
    for (int dt = 0; dt < 8; dt++) {
        int col = h*DH + dt*8 + 2*qd;
        float2 o0; o0.x = rnd_tf32(O[dt][0]*i0); o0.y = rnd_tf32(O[dt][1]*i0);
        float2 o1; o1.x = rnd_tf32(O[dt][2]*i1); o1.y = rnd_tf32(O[dt][3]*i1);
        *(float2*)&xa[(size_t)row0 * CDIM + col] = o0;
        *(float2*)&xa[(size_t)row1 * CDIM + col] = o1;
    }
}

// ---------------- merge scoring: per-src max/argmax over dst -----------------
__global__ __launch_bounds__(256) void merge_score_kernel(const float* __restrict__ thr)
{
    int i = blockIdx.x, tid = threadIdx.x;
    __shared__ float srcv[64];
    if (tid < 64) srcv[tid] = g_nmet[(size_t)(2*i) * DH + tid];
    __syncthreads();
    float best = -3.0e38f; int bestj = 0;
    for (int j = tid; j < NSRC; j += 256) {
        const float* dv = g_nmet + (size_t)(2*j + 1) * DH;
        float dot = 0.f;
#pragma unroll
        for (int d = 0; d < 64; d++) dot = fmaf(srcv[d], dv[d], dot);
        if (dot > best) { best = dot; bestj = j; }
    }
    __shared__ float bm[256]; __shared__ int bi[256];
    bm[tid] = best; bi[tid] = bestj;
    __syncthreads();
    for (int off = 128; off > 0; off >>= 1) {
        if (tid < off) {
            if (bm[tid+off] > bm[tid] ||
                (bm[tid+off] == bm[tid] && bi[tid+off] < bi[tid])) {
                bm[tid] = bm[tid+off]; bi[tid] = bi[tid+off];
            }
        }
        __syncthreads();
    }
    if (tid == 0) {
        if (i == 0) { g_mask[0] = 0; g_node[0] = 0; }
        else { g_mask[i] = (bm[0] > thr[0]) ? 1 : 0; g_node[i] = bi[0]; }
    }
}

// ---------------- exclusive prefix scan of !mask -----------------------------
__global__ __launch_bounds__(1024) void scan_kernel()
{
    __shared__ int s[NSRC];
    int tid = threadIdx.x;
    int f = g_mask[tid] ? 0 : 1;
    s[tid] = f;
    __syncthreads();
    for (int off = 1; off < NSRC; off <<= 1) {
        int v = 0;
        if (tid >= off) v = s[tid - off];
        __syncthreads();
        s[tid] += v;
        __syncthreads();
    }
    g_pref[tid] = s[tid] - f;
    if (tid == NSRC-1) g_nUnm[0] = s[NSRC-1];
}

// ---------------- build unmerged rows ----------------------------------------
__global__ __launch_bounds__(256) void unm_kernel(const float* __restrict__ sizev)
{
    int i = blockIdx.x;
    if (g_mask[i]) return;
    int r = g_pref[i];
    float s = sizev[2*i];
    const float* xr = g_x1 + (size_t)(2*i) * CDIM;
    float* orow = g_outx + (size_t)r * CDIM;
    for (int c = threadIdx.x; c < CDIM; c += 256) orow[c] = xr[c] * s;
    if (threadIdx.x == 0) g_outs[r] = s;
}

// ---------------- build dst rows (deterministic gather of merges) ------------
__global__ __launch_bounds__(256) void dst_build_kernel(const float* __restrict__ sizev)
{
    __shared__ int smask[NSRC];
    __shared__ int snode[NSRC];
    int j = blockIdx.x, tid = threadIdx.x;
    for (int i = tid; i < NSRC; i += 256) {
        smask[i] = g_mask[i];
        snode[i] = g_node[i];
    }
    __syncthreads();

    int nU = g_nUnm[0];
    float s0 = sizev[2*j + 1];
    const float* dr = g_x1 + (size_t)(2*j + 1) * CDIM;
    float a0 = dr[tid]       * s0;
    float a1 = dr[tid + 256] * s0;
    float a2 = dr[tid + 512] * s0;
    float a3 = dr[tid + 768] * s0;
    float stot = s0;
    for (int i = 0; i < NSRC; i++) {
        if (smask[i] && snode[i] == j) {
            float si = sizev[2*i];
            const float* xr = g_x1 + (size_t)(2*i) * CDIM;
            a0 += xr[tid]       * si;
            a1 += xr[tid + 256] * si;
            a2 += xr[tid + 512] * si;
            a3 += xr[tid + 768] * si;
            stot += si;
        }
    }
    size_t r = (size_t)(nU + j) * CDIM;
    g_outx[r + tid]       = a0;
    g_outx[r + tid + 256] = a1;
    g_outx[r + tid + 512] = a2;
    g_outx[r + tid + 768] = a3;
    if (tid == 0) g_outs[nU + j] = stot;
}

// ---------------- x2 = outx / size -------------------------------------------
__global__ __launch_bounds__(256) void div_kernel()
{
    int r = blockIdx.x;
    float s = g_outs[r];
    for (int c = threadIdx.x; c < CDIM; c += 256)
        g_x2[(size_t)r * CDIM + c] = g_outx[(size_t)r * CDIM + c] / s;
}

// ---------------- pack output [x rows | size] --------------------------------
__global__ __launch_bounds__(256) void out_copy_kernel(float* __restrict__ out,
                                                       int Nout, int packSize)
{
    int idx = blockIdx.x * 256 + threadIdx.x;
    int totalx = Nout * CDIM;
    if (idx < totalx) out[idx] = g_xout[idx];
    else if (packSize && idx < totalx + Nout) out[idx] = g_outs[idx - totalx];
}

// ---------------- launcher ---------------------------------------------------
extern "C" void kernel_launch(void* const* d_in, const int* in_sizes, int n_in,
                              void* d_out, int out_size)
{
    const float* x      = (const float*)d_in[0];
    const float* sizev  = (const float*)d_in[1];
    const float* qkv_w  = (const float*)d_in[2];
    const float* proj_w = (const float*)d_in[3];
    const float* proj_b = (const float*)d_in[4];
    const float* ln1_g  = (const float*)d_in[5];
    const float* ln1_b  = (const float*)d_in[6];
    const float* ln2_g  = (const float*)d_in[7];
    const float* ln2_b  = (const float*)d_in[8];
    const float* fc1_w  = (const float*)d_in[9];
    const float* fc1_b  = (const float*)d_in[10];
    const float* fc2_w  = (const float*)d_in[11];
    const float* fc2_b  = (const float*)d_in[12];
    const float* thr    = (const float*)d_in[13];
    float* out = (float*)d_out;

    int Nout, packSize;
    if (out_size % (CDIM + 1) == 0) { Nout = out_size / (CDIM + 1); packSize = 1; }
    else                            { Nout = out_size / CDIM;       packSize = 0; }
    if (Nout > NTOK) Nout = NTOK;

    float *p_h, *p_hr, *p_qkv, *p_xa, *p_x1, *p_x2, *p_h2, *p_ff, *p_xout;
    float *p_wqkv, *p_wproj, *p_wfc1, *p_wfc2;
    cudaGetSymbolAddress((void**)&p_h,    g_h);
    cudaGetSymbolAddress((void**)&p_hr,   g_hr);
    cudaGetSymbolAddress((void**)&p_qkv,  g_qkv);
    cudaGetSymbolAddress((void**)&p_xa,   g_xa);
    cudaGetSymbolAddress((void**)&p_x1,   g_x1);
    cudaGetSymbolAddress((void**)&p_x2,   g_x2);
    cudaGetSymbolAddress((void**)&p_h2,   g_h2);
    cudaGetSymbolAddress((void**)&p_ff,   g_ff);
    cudaGetSymbolAddress((void**)&p_xout, g_xout);
    cudaGetSymbolAddress((void**)&p_wqkv, g_wqkv);
    cudaGetSymbolAddress((void**)&p_wproj,g_wproj);
    cudaGetSymbolAddress((void**)&p_wfc1, g_wfc1);
    cudaGetSymbolAddress((void**)&p_wfc2, g_wfc2);

    const int ATTN_SMEM = (4*64*ATP + 64) * (int)sizeof(uint32_t);
    cudaFuncSetAttribute(attn_tc_kernel, cudaFuncAttributeMaxDynamicSharedMemorySize, ATTN_SMEM);
    cudaFuncSetAttribute(gemm_tf32<0,0>, cudaFuncAttributeMaxDynamicSharedMemorySize, GEMM_SMEM);
    cudaFuncSetAttribute(gemm_tf32<2,1>, cudaFuncAttributeMaxDynamicSharedMemorySize, GEMM_SMEM);
    cudaFuncSetAttribute(gemm_tf32<3,0>, cudaFuncAttributeMaxDynamicSharedMemorySize, GEMM_SMEM);

    // 0. pre-round weights to tf32-representable fp32
    round_kernel<<<(CDIM*3*CDIM/4 + 255)/256, 256>>>(qkv_w,  p_wqkv,  CDIM*3*CDIM/4);
    round_kernel<<<(CDIM*CDIM/4   + 255)/256, 256>>>(proj_w, p_wproj, CDIM*CDIM/4);
    round_kernel<<<(CDIM*FF/4     + 255)/256, 256>>>(fc1_w,  p_wfc1,  CDIM*FF/4);
    round_kernel<<<(FF*CDIM/4     + 255)/256, 256>>>(fc2_w,  p_wfc2,  FF*CDIM/4);
    // 1. LN1: exact h (metric) + rounded hr (GEMM)
    ln_kernel<<<NTOK, 256>>>(x, ln1_g, ln1_b, p_h, p_hr, NTOK);
    // 2a. averaged K-weights (fp32 merge-metric firewall, from exact weights)
    wkavg_kernel<<<(CDIM*DH + 255)/256, 256>>>(qkv_w);
    // 2b. QKV = hr @ wqkv  (tf32 tensor cores, cp.async pipeline)
    gemm_tf32<0,0><<<dim3(3*CDIM/128, NTOK/128), 256, GEMM_SMEM>>>(
        p_hr, p_wqkv, nullptr, nullptr, p_qkv, NTOK, 3*CDIM, CDIM);
    // 3. metric = normalize(h @ wkavg)  (fp32 split-K x8, exact mask decisions)
    metric_gemm_kernel<<<dim3(NTOK/64, 8), 256>>>();
    metric_norm_kernel<<<NTOK/8, 256>>>();
    // 4. attention -> xa (rounded)  (tf32 tensor cores)
    attn_tc_kernel<<<dim3(NTOK/64, HEADS), 128, ATTN_SMEM>>>(p_qkv, sizev, p_xa);
    // 5. x1 = x + xa @ wproj + proj_b  (tf32)
    gemm_tf32<3,0><<<dim3(CDIM/128, NTOK/128), 256, GEMM_SMEM>>>(
        p_xa, p_wproj, proj_b, x, p_x1, NTOK, CDIM, CDIM);
    // 6. merge scores
    merge_score_kernel<<<NSRC, 256>>>(thr);
    // 7. prefix scan
    scan_kernel<<<1, 1024>>>();
    // 8. unmerged rows
    unm_kernel<<<NSRC, 256>>>(sizev);
    // 9. dst rows
    dst_build_kernel<<<NSRC, 256>>>(sizev);
    // 10. x2 = outx / size
    div_kernel<<<Nout, 256>>>();
    // 11. LN2 -> rounded h2 (feeds fc1 only)
    ln_kernel<<<Nout, 256>>>(p_x2, ln2_g, ln2_b, nullptr, p_h2, Nout);
    // 12. ff = round(gelu(h2 @ wfc1 + fc1_b))  (tf32)
    gemm_tf32<2,1><<<dim3(FF/128, (Nout + 127)/128), 256, GEMM_SMEM>>>(
        p_h2, p_wfc1, fc1_b, nullptr, p_ff, Nout, FF, CDIM);
    // 13. xout = x2 + ff @ wfc2 + fc2_b  (tf32)
    gemm_tf32<3,0><<<dim3(CDIM/128, (Nout + 127)/128), 256, GEMM_SMEM>>>(
        p_ff, p_wfc2, fc2_b, p_x2, p_xout, Nout, CDIM, FF);
    // 14. pack output
    int totalOut = Nout * CDIM + (packSize ? Nout : 0);
    out_copy_kernel<<<(totalOut + 255)/256, 256>>>(out, Nout, packSize);
}

// round 9
// speedup vs baseline: 3.7064x; 1.5134x over previous
#include <cuda_runtime.h>
#include <math.h>
#include <stdint.h>

// Problem constants (fixed shapes from setup_inputs)
#define NTOK 2048
#define CDIM 1024
#define HEADS 16
#define DH 64
#define FF 4096
#define NSRC 1024   // NTOK/2

// ---------------- scratch (device globals; no allocation allowed) ------------
__device__ float g_h    [NTOK*CDIM];
__device__ float g_hr   [NTOK*CDIM];    // tf32-rounded h (GEMM input)
__device__ float g_qkv  [NTOK*3*CDIM];
__device__ float g_wkavg[CDIM*DH];
__device__ float g_mpart[8*NTOK*DH];
__device__ float g_nmet [NTOK*DH];
__device__ float g_xa   [NTOK*CDIM];    // rounded at attn epilogue
__device__ float g_x1   [NTOK*CDIM];
__device__ int   g_mask [NSRC];
__device__ int   g_node [NSRC];
__device__ int   g_pref [NSRC];
__device__ int   g_nUnm [1];
__device__ float g_outx [NTOK*CDIM];
__device__ float g_outs [NTOK];
__device__ float g_x2   [NTOK*CDIM];
__device__ float g_h2   [NTOK*CDIM];    // rounded at fused div+LN2
__device__ float g_ff   [NTOK*FF];      // rounded at fc1 epilogue
// tf32-rounded weight copies
__device__ float g_wqkv [CDIM*3*CDIM];
__device__ float g_wproj[CDIM*CDIM];
__device__ float g_wfc1 [CDIM*FF];
__device__ float g_wfc2 [FF*CDIM];

// ---------------- helpers ----------------------------------------------------
__device__ __forceinline__ uint32_t f2tf32(float v) {
    uint32_t r;
    asm("cvt.rna.tf32.f32 %0, %1;" : "=r"(r) : "f"(v));
    return r;
}
__device__ __forceinline__ float rnd_tf32(float v) {
    return __uint_as_float(f2tf32(v));
}

__device__ __forceinline__ void mma_tf32(float c[4], const uint32_t a[4],
                                         const uint32_t b[2]) {
    asm volatile(
        "mma.sync.aligned.m16n8k8.row.col.f32.tf32.tf32.f32 "
        "{%0,%1,%2,%3}, {%4,%5,%6,%7}, {%8,%9}, {%0,%1,%2,%3};\n"
        : "+f"(c[0]), "+f"(c[1]), "+f"(c[2]), "+f"(c[3])
        : "r"(a[0]), "r"(a[1]), "r"(a[2]), "r"(a[3]), "r"(b[0]), "r"(b[1]));
}

__device__ __forceinline__ void cp_async16(uint32_t dst, const void* src, int szbytes) {
    asm volatile("cp.async.cg.shared.global [%0], [%1], 16, %2;\n"
                 :: "r"(dst), "l"(src), "r"(szbytes));
}
__device__ __forceinline__ void cp_commit() {
    asm volatile("cp.async.commit_group;\n");
}
template <int N>
__device__ __forceinline__ void cp_wait() {
    asm volatile("cp.async.wait_group %0;\n" :: "n"(N));
}

__device__ __forceinline__ float gelu_exact(float v) {
    return 0.5f * v * (1.0f + erff(v * 0.70710678118654752440f));
}

// ---------------- tf32 pre-rounding of a buffer ------------------------------
__global__ __launch_bounds__(256) void round_kernel(
    const float* __restrict__ in, float* __restrict__ out, int n4)
{
    int i = blockIdx.x * 256 + threadIdx.x;
    if (i >= n4) return;
    float4 v = ((const float4*)in)[i];
    v.x = rnd_tf32(v.x); v.y = rnd_tf32(v.y);
    v.z = rnd_tf32(v.z); v.w = rnd_tf32(v.w);
    ((float4*)out)[i] = v;
}

// ---------------- layernorm (exact + rounded outputs) ------------------------
__global__ __launch_bounds__(256) void ln_kernel(
    const float* __restrict__ x, const float* __restrict__ g,
    const float* __restrict__ b, float* __restrict__ out,
    float* __restrict__ out_r, int M)
{
    int row = blockIdx.x;
    if (row >= M) return;
    const float* xr = x + (size_t)row * CDIM;
    int tid = threadIdx.x;
    float v[4];
    float s = 0.f, sq = 0.f;
#pragma unroll
    for (int t = 0; t < 4; t++) {
        float vv = xr[tid + t*256];
        v[t] = vv; s += vv; sq += vv*vv;
    }
    __shared__ float rs[256], rq[256];
    rs[tid] = s; rq[tid] = sq;
    __syncthreads();
    for (int off = 128; off > 0; off >>= 1) {
        if (tid < off) { rs[tid] += rs[tid+off]; rq[tid] += rq[tid+off]; }
        __syncthreads();
    }
    float mean = rs[0] * (1.f/CDIM);
    float var  = rq[0] * (1.f/CDIM) - mean*mean;
    float rstd = rsqrtf(var + 1e-5f);
#pragma unroll
    for (int t = 0; t < 4; t++) {
        int c = tid + t*256;
        float o = (v[t] - mean) * rstd * g[c] + b[c];
        if (out)   out  [(size_t)row * CDIM + c] = o;
        if (out_r) out_r[(size_t)row * CDIM + c] = rnd_tf32(o);
    }
}

// ---------------- fused x2 = outx/size, then LN2 -> rounded h2 ----------------
__global__ __launch_bounds__(256) void divln_kernel(
    const float* __restrict__ g, const float* __restrict__ b, int M)
{
    int row = blockIdx.x;
    if (row >= M) return;
    int tid = threadIdx.x;
    float sdiv = g_outs[row];
    float v[4];
    float s = 0.f, sq = 0.f;
#pragma unroll
    for (int t = 0; t < 4; t++) {
        float vv = g_outx[(size_t)row * CDIM + tid + t*256] / sdiv;
        v[t] = vv; s += vv; sq += vv*vv;
        g_x2[(size_t)row * CDIM + tid + t*256] = vv;
    }
    __shared__ float rs[256], rq[256];
    rs[tid] = s; rq[tid] = sq;
    __syncthreads();
    for (int off = 128; off > 0; off >>= 1) {
        if (tid < off) { rs[tid] += rs[tid+off]; rq[tid] += rq[tid+off]; }
        __syncthreads();
    }
    float mean = rs[0] * (1.f/CDIM);
    float var  = rq[0] * (1.f/CDIM) - mean*mean;
    float rstd = rsqrtf(var + 1e-5f);
#pragma unroll
    for (int t = 0; t < 4; t++) {
        int c = tid + t*256;
        float o = (v[t] - mean) * rstd * g[c] + b[c];
        g_h2[(size_t)row * CDIM + c] = rnd_tf32(o);
    }
}

// ---------------- TF32 tensor-core GEMM, cp.async 4-stage, 64x64 warp tiles --
// 128 threads = 4 warps in 2x2; warp computes 64x64 via 4x8 m16n8k8 frags.
// Inputs must be tf32-representable fp32 (pre-rounded) -> truncation exact.
// EPI: 0 = A@B ; 1 = +bias ; 2 = gelu(+bias) ; 3 = +bias +res
// RND: round output to tf32 (when it feeds another GEMM)
#define GSTAGES 4
#define AS_WORDS (GSTAGES*128*20)
#define BS_WORDS (GSTAGES*16*136)
#define GEMM_SMEM ((AS_WORDS + BS_WORDS) * 4)

template <int EPI, int RND>
__global__ __launch_bounds__(128) void gemm_tf32(
    const float* __restrict__ A, const float* __restrict__ B,
    const float* __restrict__ bias, const float* __restrict__ res,
    float* __restrict__ C, int M, int N, int K)
{
    extern __shared__ uint32_t gsm[];
    uint32_t* As = gsm;              // [s][128][20]
    uint32_t* Bs = gsm + AS_WORDS;   // [s][16][136]

    int tid  = threadIdx.x;
    int lane = tid & 31, wid = tid >> 5;   // 4 warps
    int wm = wid >> 1, wn = wid & 1;       // 2x2
    int g  = lane >> 2, qd = lane & 3;
    int m0 = blockIdx.y * 128, n0 = blockIdx.x * 128;

    float acc[4][8][4];
#pragma unroll
    for (int i = 0; i < 4; i++)
#pragma unroll
        for (int j = 0; j < 8; j++)
#pragma unroll
            for (int r = 0; r < 4; r++) acc[i][j][r] = 0.f;

    const int nT = K >> 4;

    // per-thread global-load coordinates: 4 float4 each for A and B per tile
    int ar[4], ac[4], br[4], bc[4], aSz[4];
#pragma unroll
    for (int u = 0; u < 4; u++) {
        int idx = u*128 + tid;
        ar[u] = idx >> 2;  ac[u] = (idx & 3) * 4;
        br[u] = idx >> 5;  bc[u] = (idx & 31) * 4;
        aSz[u] = (m0 + ar[u] < M) ? 16 : 0;
    }
    uint32_t asBase = (uint32_t)__cvta_generic_to_shared(As);
    uint32_t bsBase = (uint32_t)__cvta_generic_to_shared(Bs);

    // prologue: issue first GSTAGES-1 tiles
#pragma unroll
    for (int t = 0; t < GSTAGES-1; t++) {
        int k0 = t * 16;
#pragma unroll
        for (int u = 0; u < 4; u++) {
            cp_async16(asBase + (uint32_t)(((t*128 + ar[u])*20 + ac[u]) * 4),
                       A + (size_t)(m0 + ar[u]) * K + k0 + ac[u], aSz[u]);
            cp_async16(bsBase + (uint32_t)(((t*16 + br[u])*136 + bc[u]) * 4),
                       B + (size_t)(k0 + br[u]) * N + n0 + bc[u], 16);
        }
        cp_commit();
    }

    for (int t = 0; t < nT; t++) {
        cp_wait<GSTAGES-2>();
        __syncthreads();

        int nxt = t + GSTAGES - 1;
        if (nxt < nT) {
            int s  = nxt % GSTAGES;
            int k0 = nxt * 16;
#pragma unroll
            for (int u = 0; u < 4; u++) {
                cp_async16(asBase + (uint32_t)(((s*128 + ar[u])*20 + ac[u]) * 4),
                           A + (size_t)(m0 + ar[u]) * K + k0 + ac[u], aSz[u]);
                cp_async16(bsBase + (uint32_t)(((s*16 + br[u])*136 + bc[u]) * 4),
                           B + (size_t)(k0 + br[u]) * N + n0 + bc[u], 16);
            }
        }
        cp_commit();

        const uint32_t* Ab = As + (t % GSTAGES) * 128 * 20;
        const uint32_t* Bb = Bs + (t % GSTAGES) * 16 * 136;
#pragma unroll
        for (int ks = 0; ks < 2; ks++) {
            int kb = ks * 8;
            uint32_t af[4][4], bf[8][2];
#pragma unroll
            for (int mf = 0; mf < 4; mf++) {
                int r = wm*64 + mf*16 + g;
                af[mf][0] = Ab[(r    )*20 + kb + qd];
                af[mf][1] = Ab[(r + 8)*20 + kb + qd];
                af[mf][2] = Ab[(r    )*20 + kb + qd + 4];
                af[mf][3] = Ab[(r + 8)*20 + kb + qd + 4];
            }
#pragma unroll
            for (int nf = 0; nf < 8; nf++) {
                int c = wn*64 + nf*8 + g;
                bf[nf][0] = Bb[(kb + qd    )*136 + c];
                bf[nf][1] = Bb[(kb + qd + 4)*136 + c];
            }
#pragma unroll
            for (int mf = 0; mf < 4; mf++)
#pragma unroll
                for (int nf = 0; nf < 8; nf++)
                    mma_tf32(acc[mf][nf], af[mf], bf[nf]);
        }
    }

#pragma unroll
    for (int mf = 0; mf < 4; mf++) {
        int rbase = m0 + wm*64 + mf*16 + g;
#pragma unroll
        for (int half = 0; half < 2; half++) {
            int row = rbase + half*8;
            if (row >= M) continue;
#pragma unroll
            for (int nf = 0; nf < 8; nf++) {
                int col = n0 + wn*64 + nf*8 + 2*qd;
                float v0 = acc[mf][nf][half*2 + 0];
                float v1 = acc[mf][nf][half*2 + 1];
                if (EPI >= 1) { v0 += bias[col]; v1 += bias[col+1]; }
                if (EPI == 2) { v0 = gelu_exact(v0); v1 = gelu_exact(v1); }
                if (EPI == 3) {
                    v0 += res[(size_t)row * N + col];
                    v1 += res[(size_t)row * N + col + 1];
                }
                if (RND) { v0 = rnd_tf32(v0); v1 = rnd_tf32(v1); }
                float2 o; o.x = v0; o.y = v1;
                *(float2*)(C + (size_t)row * N + col) = o;
            }
        }
    }
}

// ---------------- fp32 merge-metric path (exactness firewall) ----------------
__global__ __launch_bounds__(256) void wkavg_kernel(const float* __restrict__ qkv_w)
{
    int idx = blockIdx.x * 256 + threadIdx.x;
    if (idx >= CDIM*DH) return;
    int c = idx >> 6, d = idx & 63;
    const float* base = qkv_w + (size_t)c * (3*CDIM) + CDIM + d;
    float s = 0.f;
#pragma unroll
    for (int h = 0; h < HEADS; h++) s += base[h * DH];
    g_wkavg[idx] = s * (1.f / HEADS);
}

// partial metric = h @ wkavg over K chunk of 128  (split-K x8, fp32 SIMT)
__global__ __launch_bounds__(256) void metric_gemm_kernel()
{
    __shared__ float AsT[32][68];   // [k][tok]
    __shared__ float Bs [32][68];   // [k][d]
    int tid = threadIdx.x;
    int tx = tid & 15, ty = tid >> 4;
    int m0 = blockIdx.x * 64;
    int kb = blockIdx.y * 128;

    float acc[4][4];
#pragma unroll
    for (int i = 0; i < 4; i++)
#pragma unroll
        for (int j = 0; j < 4; j++) acc[i][j] = 0.f;

    for (int k0 = kb; k0 < kb + 128; k0 += 32) {
        __syncthreads();
#pragma unroll
        for (int u = 0; u < 2; u++) {
            int idx = tid*2 + u;
            int tok = idx >> 3, kc = (idx & 7) * 4;
            float4 v = *(const float4*)(g_h + (size_t)(m0 + tok) * CDIM + k0 + kc);
            AsT[kc+0][tok] = v.x; AsT[kc+1][tok] = v.y;
            AsT[kc+2][tok] = v.z; AsT[kc+3][tok] = v.w;
            int kr = idx >> 4, d = (idx & 15) * 4;
            *(float4*)&Bs[kr][d] = *(const float4*)(g_wkavg + (size_t)(k0 + kr) * DH + d);
        }
        __syncthreads();
#pragma unroll
        for (int k = 0; k < 32; k++) {
            float4 a = *(float4*)&AsT[k][ty*4];
            float4 b = *(float4*)&Bs[k][tx*4];
            float aa[4] = {a.x, a.y, a.z, a.w};
            float bb[4] = {b.x, b.y, b.z, b.w};
#pragma unroll
            for (int i = 0; i < 4; i++)
#pragma unroll
                for (int j = 0; j < 4; j++)
                    acc[i][j] = fmaf(aa[i], bb[j], acc[i][j]);
        }
    }
    float* dst = g_mpart + (size_t)blockIdx.y * NTOK * DH;
#pragma unroll
    for (int i = 0; i < 4; i++)
#pragma unroll
        for (int j = 0; j < 4; j++)
            dst[(size_t)(m0 + ty*4 + i) * DH + tx*4 + j] = acc[i][j];
}

// sum 8 partials (fixed order) + row-normalize -> g_nmet
__global__ __launch_bounds__(256) void metric_norm_kernel()
{
    int row = blockIdx.x * 8 + (threadIdx.x >> 5);
    int lane = threadIdx.x & 31;
    size_t off = (size_t)row * DH + lane*2;
    float2 v = *(float2*)&g_mpart[off];
#pragma unroll
    for (int p = 1; p < 8; p++) {
        float2 u = *(float2*)&g_mpart[(size_t)p * NTOK * DH + off];
        v.x += u.x; v.y += u.y;
    }
    float sq = v.x*v.x + v.y*v.y;
#pragma unroll
    for (int o = 16; o > 0; o >>= 1)
        sq += __shfl_xor_sync(0xffffffffu, sq, o);
    float nrm = sqrtf(sq);
    v.x /= nrm; v.y /= nrm;
    *(float2*)&g_nmet[off] = v;
}

// ---------------- tensor-core flash attention (128q x 64k, dh=64) ------------
// 256 threads / 8 warps; warp w owns q rows [w*16, w*16+16). K/V tiles shared.
#define ATP 68   // smem pitch (words): conflict-free fragment loads

__global__ __launch_bounds__(256) void attn_tc_kernel(
    const float* __restrict__ qkv, const float* __restrict__ sizev,
    float* __restrict__ xa)
{
    extern __shared__ uint32_t smu[];
    uint32_t* Qs   = smu;                    // [128][ATP] tf32 (scaled 0.125)
    uint32_t* Ks   = smu + 128*ATP;          // [64][ATP] tf32 (token-major)
    uint32_t* VsT  = smu + 192*ATP;          // [64][ATP] tf32 (d-major)
    uint32_t* Ps   = smu + 256*ATP;          // [128][ATP] tf32
    float*    logs = (float*)(smu + 384*ATP); // [64]

    int tid  = threadIdx.x;
    int lane = tid & 31, w = tid >> 5;       // 8 warps
    int g = lane >> 2, qd = lane & 3;
    int h = blockIdx.y;
    int q0 = blockIdx.x * 128;
    int wq = w * 16;
    int qrow0 = (wq + g) * ATP, qrow1 = (wq + g + 8) * ATP;

    { // load Q tile (128 rows; tf32, pre-scaled)
        int tok = tid & 127, chunk = tid >> 7;
        const float* src = qkv + (size_t)(q0 + tok) * (3*CDIM) + h*DH + chunk*32;
#pragma unroll
        for (int f = 0; f < 8; f++) {
            float4 v = *(const float4*)(src + f*4);
            uint4 u;
            u.x = f2tf32(v.x * 0.125f); u.y = f2tf32(v.y * 0.125f);
            u.z = f2tf32(v.z * 0.125f); u.w = f2tf32(v.w * 0.125f);
            *(uint4*)&Qs[tok*ATP + chunk*32 + f*4] = u;
        }
    }

    float O[8][4];
#pragma unroll
    for (int dt = 0; dt < 8; dt++)
#pragma unroll
        for (int r = 0; r < 4; r++) O[dt][r] = 0.f;
    float rm0 = -3.0e38f, rm1 = -3.0e38f, rl0 = 0.f, rl1 = 0.f;

    for (int kt = 0; kt < NTOK/64; kt++) {
        int k0 = kt * 64;
        __syncthreads();
        { // load K/V tile: 256 threads, each 4 float4
            int tok = tid & 63, chunk = (tid >> 6) & 1, fh = tid >> 7;
            const float* ksrc = qkv + (size_t)(k0 + tok)*(3*CDIM) + CDIM + h*DH + chunk*32;
            const float* vsrc = ksrc + CDIM;
#pragma unroll
            for (int f = 0; f < 4; f++) {
                int ff = fh*4 + f;
                float4 kv = *(const float4*)(ksrc + ff*4);
                uint4 u;
                u.x = f2tf32(kv.x); u.y = f2tf32(kv.y);
                u.z = f2tf32(kv.z); u.w = f2tf32(kv.w);
                *(uint4*)&Ks[tok*ATP + chunk*32 + ff*4] = u;
                float4 vv = *(const float4*)(vsrc + ff*4);
                int d = chunk*32 + ff*4;
                VsT[(d+0)*ATP + tok] = f2tf32(vv.x);
                VsT[(d+1)*ATP + tok] = f2tf32(vv.y);
                VsT[(d+2)*ATP + tok] = f2tf32(vv.z);
                VsT[(d+3)*ATP + tok] = f2tf32(vv.w);
            }
            if (tid < 64) logs[tid] = __logf(sizev[k0 + tid]);
        }
        __syncthreads();

        float S[8][4];
#pragma unroll
        for (int nt = 0; nt < 8; nt++)
#pragma unroll
            for (int r = 0; r < 4; r++) S[nt][r] = 0.f;
#pragma unroll
        for (int kb = 0; kb < 8; kb++) {
            uint32_t a[4];
            a[0] = Qs[qrow0 + kb*8 + qd];
            a[1] = Qs[qrow1 + kb*8 + qd];
            a[2] = Qs[qrow0 + kb*8 + qd + 4];
            a[3] = Qs[qrow1 + kb*8 + qd + 4];
#pragma unroll
            for (int nt = 0; nt < 8; nt++) {
                uint32_t b[2];
                b[0] = Ks[(nt*8 + g)*ATP + kb*8 + qd];
                b[1] = Ks[(nt*8 + g)*ATP + kb*8 + qd + 4];
                mma_tf32(S[nt], a, b);
            }
        }

        float m0 = -3.0e38f, m1 = -3.0e38f;
#pragma unroll
        for (int nt = 0; nt < 8; nt++) {
            float l0 = logs[nt*8 + 2*qd], l1 = logs[nt*8 + 2*qd + 1];
            S[nt][0] += l0; S[nt][1] += l1;
            S[nt][2] += l0; S[nt][3] += l1;
            m0 = fmaxf(m0, fmaxf(S[nt][0], S[nt][1]));
            m1 = fmaxf(m1, fmaxf(S[nt][2], S[nt][3]));
        }
#pragma unroll
        for (int off = 1; off < 4; off <<= 1) {
            m0 = fmaxf(m0, __shfl_xor_sync(0xffffffffu, m0, off));
            m1 = fmaxf(m1, __shfl_xor_sync(0xffffffffu, m1, off));
        }
        float n0 = fmaxf(rm0, m0), n1 = fmaxf(rm1, m1);
        float c0 = __expf(rm0 - n0), c1 = __expf(rm1 - n1);
        float s0 = 0.f, s1 = 0.f;
#pragma unroll
        for (int nt = 0; nt < 8; nt++) {
            S[nt][0] = __expf(S[nt][0] - n0);
            S[nt][1] = __expf(S[nt][1] - n0);
            S[nt][2] = __expf(S[nt][2] - n1);
            S[nt][3] = __expf(S[nt][3] - n1);
            s0 += S[nt][0] + S[nt][1];
            s1 += S[nt][2] + S[nt][3];
        }
#pragma unroll
        for (int off = 1; off < 4; off <<= 1) {
            s0 += __shfl_xor_sync(0xffffffffu, s0, off);
            s1 += __shfl_xor_sync(0xffffffffu, s1, off);
        }
        rl0 = rl0 * c0 + s0;  rl1 = rl1 * c1 + s1;
        rm0 = n0; rm1 = n1;
#pragma unroll
        for (int dt = 0; dt < 8; dt++) {
            O[dt][0] *= c0; O[dt][1] *= c0;
            O[dt][2] *= c1; O[dt][3] *= c1;
        }

#pragma unroll
        for (int nt = 0; nt < 8; nt++) {
            uint2 u01, u23;
            u01.x = f2tf32(S[nt][0]); u01.y = f2tf32(S[nt][1]);
            u23.x = f2tf32(S[nt][2]); u23.y = f2tf32(S[nt][3]);
            *(uint2*)&Ps[qrow0 + nt*8 + 2*qd] = u01;
            *(uint2*)&Ps[qrow1 + nt*8 + 2*qd] = u23;
        }
        __syncwarp();

#pragma unroll
        for (int kb = 0; kb < 8; kb++) {
            uint32_t a[4];
            a[0] = Ps[qrow0 + kb*8 + qd];
            a[1] = Ps[qrow1 + kb*8 + qd];
            a[2] = Ps[qrow0 + kb*8 + qd + 4];
            a[3] = Ps[qrow1 + kb*8 + qd + 4];
#pragma unroll
            for (int dt = 0; dt < 8; dt++) {
                uint32_t b[2];
                b[0] = VsT[(dt*8 + g)*ATP + kb*8 + qd];
                b[1] = VsT[(dt*8 + g)*ATP + kb*8 + qd + 4];
                mma_tf32(O[dt], a, b);
            }
        }
    }

    // epilogue: write tf32-rounded xa (feeds proj GEMM)
    float i0 = 1.f / rl0, i1 = 1.f / rl1;
    int row0 = q0 + wq + g, row1 = row0 + 8;
#pragma unroll
    for (int dt = 0; dt < 8; dt++) {
        int col = h*DH + dt*8 + 2*qd;
        float2 o0; o0.x = rnd_tf32(O[dt][0]*i0); o0.y = rnd_tf32(O[dt][1]*i0);
        float2 o1; o1.x = rnd_tf32(O[dt][2]*i1); o1.y = rnd_tf32(O[dt][3]*i1);
        *(float2*)&xa[(size_t)row0 * CDIM + col] = o0;
        *(float2*)&xa[(size_t)row1 * CDIM + col] = o1;
    }
}

// ---------------- merge scoring: tiled max/argmax over dst -------------------
// 64 blocks x 16 src each; src row in registers, dst staged in 64x64 smem tiles.
__global__ __launch_bounds__(256) void merge_score_kernel(const float* __restrict__ thr)
{
    __shared__ float dstm[64*65];
    int tid = threadIdx.x;
    int sl = tid >> 4;        // src local 0..15
    int tg = tid & 15;        // dst group
    int i  = blockIdx.x * 16 + sl;

    float sv[64];
    {
        const float4* sr = (const float4*)(g_nmet + (size_t)(2*i)*DH);
#pragma unroll
        for (int d4 = 0; d4 < 16; d4++) {
            float4 v = sr[d4];
            sv[d4*4+0] = v.x; sv[d4*4+1] = v.y;
            sv[d4*4+2] = v.z; sv[d4*4+3] = v.w;
        }
    }

    float best = -3.0e38f; int bestj = 0;
    for (int jt = 0; jt < NSRC/64; jt++) {
        __syncthreads();
        for (int u = 0; u < 4; u++) {
            int idx = u*256 + tid;            // 0..1023
            int r = idx >> 4, dc = (idx & 15) * 4;
            const float4 v = *(const float4*)(g_nmet + (size_t)(2*(jt*64 + r) + 1)*DH + dc);
            float* dst = &dstm[r*65 + dc];
            dst[0] = v.x; dst[1] = v.y; dst[2] = v.z; dst[3] = v.w;
        }
        __syncthreads();
#pragma unroll
        for (int jj = 0; jj < 4; jj++) {
            int rloc = jj*16 + tg;
            const float* dv = &dstm[rloc*65];
            float dot = 0.f;
#pragma unroll
            for (int d = 0; d < 64; d++) dot = fmaf(sv[d], dv[d], dot);
            int j = jt*64 + rloc;
            if (dot > best || (dot == best && j < bestj)) { best = dot; bestj = j; }
        }
    }
    // reduce across the 16 tg lanes (xor stays within 16-lane half-warp)
#pragma unroll
    for (int off = 1; off < 16; off <<= 1) {
        float ov = __shfl_xor_sync(0xffffffffu, best, off);
        int   oj = __shfl_xor_sync(0xffffffffu, bestj, off);
        if (ov > best || (ov == best && oj < bestj)) { best = ov; bestj = oj; }
    }
    if (tg == 0) {
        if (i == 0) { g_mask[0] = 0; g_node[0] = 0; }   // row 0 forced -inf
        else { g_mask[i] = (best > thr[0]) ? 1 : 0; g_node[i] = bestj; }
    }
}

// ---------------- exclusive prefix scan of !mask -----------------------------
__global__ __launch_bounds__(1024) void scan_kernel()
{
    __shared__ int s[NSRC];
    int tid = threadIdx.x;
    int f = g_mask[tid] ? 0 : 1;
    s[tid] = f;
    __syncthreads();
    for (int off = 1; off < NSRC; off <<= 1) {
        int v = 0;
        if (tid >= off) v = s[tid - off];
        __syncthreads();
        s[tid] += v;
        __syncthreads();
    }
    g_pref[tid] = s[tid] - f;
    if (tid == NSRC-1) g_nUnm[0] = s[NSRC-1];
}

// ---------------- build unmerged rows ----------------------------------------
__global__ __launch_bounds__(256) void unm_kernel(const float* __restrict__ sizev)
{
    int i = blockIdx.x;
    if (g_mask[i]) return;
    int r = g_pref[i];
    float s = sizev[2*i];
    const float* xr = g_x1 + (size_t)(2*i) * CDIM;
    float* orow = g_outx + (size_t)r * CDIM;
    for (int c = threadIdx.x; c < CDIM; c += 256) orow[c] = xr[c] * s;
    if (threadIdx.x == 0) g_outs[r] = s;
}

// ---------------- build dst rows (deterministic gather of merges) ------------
__global__ __launch_bounds__(256) void dst_build_kernel(const float* __restrict__ sizev)
{
    __shared__ int smask[NSRC];
    __shared__ int snode[NSRC];
    int j = blockIdx.x, tid = threadIdx.x;
    for (int i = tid; i < NSRC; i += 256) {
        smask[i] = g_mask[i];
        snode[i] = g_node[i];
    }
    __syncthreads();

    int nU = g_nUnm[0];
    float s0 = sizev[2*j + 1];
    const float* dr = g_x1 + (size_t)(2*j + 1) * CDIM;
    float a0 = dr[tid]       * s0;
    float a1 = dr[tid + 256] * s0;
    float a2 = dr[tid + 512] * s0;
    float a3 = dr[tid + 768] * s0;
    float stot = s0;
    for (int i = 0; i < NSRC; i++) {
        if (smask[i] && snode[i] == j) {
            float si = sizev[2*i];
            const float* xr = g_x1 + (size_t)(2*i) * CDIM;
            a0 += xr[tid]       * si;
            a1 += xr[tid + 256] * si;
            a2 += xr[tid + 512] * si;
            a3 += xr[tid + 768] * si;
            stot += si;
        }
    }
    size_t r = (size_t)(nU + j) * CDIM;
    g_outx[r + tid]       = a0;
    g_outx[r + tid + 256] = a1;
    g_outx[r + tid + 512] = a2;
    g_outx[r + tid + 768] = a3;
    if (tid == 0) g_outs[nU + j] = stot;
}

// ---------------- size tail --------------------------------------------------
__global__ __launch_bounds__(256) void size_tail_kernel(float* __restrict__ out, int Nout)
{
    int i = blockIdx.x * 256 + threadIdx.x;
    if (i < Nout) out[(size_t)Nout * CDIM + i] = g_outs[i];
}

// ---------------- launcher ---------------------------------------------------
extern "C" void kernel_launch(void* const* d_in, const int* in_sizes, int n_in,
                              void* d_out, int out_size)
{
    const float* x      = (const float*)d_in[0];
    const float* sizev  = (const float*)d_in[1];
    const float* qkv_w  = (const float*)d_in[2];
    const float* proj_w = (const float*)d_in[3];
    const float* proj_b = (const float*)d_in[4];
    const float* ln1_g  = (const float*)d_in[5];
    const float* ln1_b  = (const float*)d_in[6];
    const float* ln2_g  = (const float*)d_in[7];
    const float* ln2_b  = (const float*)d_in[8];
    const float* fc1_w  = (const float*)d_in[9];
    const float* fc1_b  = (const float*)d_in[10];
    const float* fc2_w  = (const float*)d_in[11];
    const float* fc2_b  = (const float*)d_in[12];
    const float* thr    = (const float*)d_in[13];
    float* out = (float*)d_out;

    int Nout, packSize;
    if (out_size % (CDIM + 1) == 0) { Nout = out_size / (CDIM + 1); packSize = 1; }
    else                            { Nout = out_size / CDIM;       packSize = 0; }
    if (Nout > NTOK) Nout = NTOK;

    float *p_h, *p_hr, *p_qkv, *p_xa, *p_x1, *p_x2, *p_h2, *p_ff;
    float *p_wqkv, *p_wproj, *p_wfc1, *p_wfc2;
    cudaGetSymbolAddress((void**)&p_h,    g_h);
    cudaGetSymbolAddress((void**)&p_hr,   g_hr);
    cudaGetSymbolAddress((void**)&p_qkv,  g_qkv);
    cudaGetSymbolAddress((void**)&p_xa,   g_xa);
    cudaGetSymbolAddress((void**)&p_x1,   g_x1);
    cudaGetSymbolAddress((void**)&p_x2,   g_x2);
    cudaGetSymbolAddress((void**)&p_h2,   g_h2);
    cudaGetSymbolAddress((void**)&p_ff,   g_ff);
    cudaGetSymbolAddress((void**)&p_wqkv, g_wqkv);
    cudaGetSymbolAddress((void**)&p_wproj,g_wproj);
    cudaGetSymbolAddress((void**)&p_wfc1, g_wfc1);
    cudaGetSymbolAddress((void**)&p_wfc2, g_wfc2);

    const int ATTN_SMEM = (384*ATP + 64) * (int)sizeof(uint32_t);
    cudaFuncSetAttribute(attn_tc_kernel, cudaFuncAttributeMaxDynamicSharedMemorySize, ATTN_SMEM);
    cudaFuncSetAttribute(gemm_tf32<0,0>, cudaFuncAttributeMaxDynamicSharedMemorySize, GEMM_SMEM);
    cudaFuncSetAttribute(gemm_tf32<2,1>, cudaFuncAttributeMaxDynamicSharedMemorySize, GEMM_SMEM);
    cudaFuncSetAttribute(gemm_tf32<3,0>, cudaFuncAttributeMaxDynamicSharedMemorySize, GEMM_SMEM);

    // 0. pre-round weights to tf32-representable fp32
    round_kernel<<<(CDIM*3*CDIM/4 + 255)/256, 256>>>(qkv_w,  p_wqkv,  CDIM*3*CDIM/4);
    round_kernel<<<(CDIM*CDIM/4   + 255)/256, 256>>>(proj_w, p_wproj, CDIM*CDIM/4);
    round_kernel<<<(CDIM*FF/4     + 255)/256, 256>>>(fc1_w,  p_wfc1,  CDIM*FF/4);
    round_kernel<<<(FF*CDIM/4     + 255)/256, 256>>>(fc2_w,  p_wfc2,  FF*CDIM/4);
    // 1. LN1: exact h (metric) + rounded hr (GEMM)
    ln_kernel<<<NTOK, 256>>>(x, ln1_g, ln1_b, p_h, p_hr, NTOK);
    // 2a. averaged K-weights (fp32 merge-metric firewall)
    wkavg_kernel<<<(CDIM*DH + 255)/256, 256>>>(qkv_w);
    // 2b. QKV = hr @ wqkv  (tf32, cp.async, 64x64 warp tiles)
    gemm_tf32<0,0><<<dim3(3*CDIM/128, NTOK/128), 128, GEMM_SMEM>>>(
        p_hr, p_wqkv, nullptr, nullptr, p_qkv, NTOK, 3*CDIM, CDIM);
    // 3. metric = normalize(h @ wkavg)  (fp32 split-K x8, exact mask decisions)
    metric_gemm_kernel<<<dim3(NTOK/64, 8), 256>>>();
    metric_norm_kernel<<<NTOK/8, 256>>>();
    // 4. attention -> xa (rounded)  (tf32 tensor cores, 128q/CTA)
    attn_tc_kernel<<<dim3(NTOK/128, HEADS), 256, ATTN_SMEM>>>(p_qkv, sizev, p_xa);
    // 5. x1 = x + xa @ wproj + proj_b  (tf32)
    gemm_tf32<3,0><<<dim3(CDIM/128, NTOK/128), 128, GEMM_SMEM>>>(
        p_xa, p_wproj, proj_b, x, p_x1, NTOK, CDIM, CDIM);
    // 6. merge scores (tiled)
    merge_score_kernel<<<NSRC/16, 256>>>(thr);
    // 7. prefix scan
    scan_kernel<<<1, 1024>>>();
    // 8. unmerged rows
    unm_kernel<<<NSRC, 256>>>(sizev);
    // 9. dst rows
    dst_build_kernel<<<NSRC, 256>>>(sizev);
    // 10+11. fused x2 = outx/size, LN2 -> rounded h2
    divln_kernel<<<Nout, 256>>>(ln2_g, ln2_b, Nout);
    // 12. ff = round(gelu(h2 @ wfc1 + fc1_b))  (tf32)
    gemm_tf32<2,1><<<dim3(FF/128, (Nout + 127)/128), 128, GEMM_SMEM>>>(
        p_h2, p_wfc1, fc1_b, nullptr, p_ff, Nout, FF, CDIM);
    // 13. out = x2 + ff @ wfc2 + fc2_b  (tf32, writes d_out directly)
    gemm_tf32<3,0><<<dim3(CDIM/128, (Nout + 127)/128), 128, GEMM_SMEM>>>(
        p_ff, p_wfc2, fc2_b, p_x2, out, Nout, CDIM, FF);
    // 14. append sizes
    if (packSize)
        size_tail_kernel<<<(Nout + 255)/256, 256>>>(out, Nout);
}

// round 10
// speedup vs baseline: 3.8394x; 1.0359x over previous
#include <cuda_runtime.h>
#include <math.h>
#include <stdint.h>

// Problem constants (fixed shapes from setup_inputs)
#define NTOK 2048
#define CDIM 1024
#define HEADS 16
#define DH 64
#define FF 4096
#define NSRC 1024   // NTOK/2

// ---------------- scratch (device globals; no allocation allowed) ------------
__device__ float g_h    [NTOK*CDIM];
__device__ float g_hr   [NTOK*CDIM];    // tf32-rounded h (GEMM input)
__device__ float g_qkv  [NTOK*3*CDIM];  // tf32-rounded (QKV GEMM RND=1)
__device__ float g_wkavg[CDIM*DH];
__device__ float g_mpart[8*NTOK*DH];
__device__ float g_nmet [NTOK*DH];
__device__ float g_xa   [NTOK*CDIM];    // rounded at attn epilogue
__device__ float g_x1   [NTOK*CDIM];
__device__ int   g_mask [NSRC];
__device__ int   g_node [NSRC];
__device__ int   g_pref [NSRC];
__device__ int   g_nUnm [1];
__device__ float g_outx [NTOK*CDIM];
__device__ float g_outs [NTOK];
__device__ float g_x2   [NTOK*CDIM];
__device__ float g_h2   [NTOK*CDIM];    // rounded at fused div+LN2
__device__ float g_ff   [NTOK*FF];      // rounded at fc1 epilogue
// tf32-rounded weight copies
__device__ float g_wqkv [CDIM*3*CDIM];
__device__ float g_wproj[CDIM*CDIM];
__device__ float g_wfc1 [CDIM*FF];
__device__ float g_wfc2 [FF*CDIM];

// ---------------- helpers ----------------------------------------------------
__device__ __forceinline__ uint32_t f2tf32(float v) {
    uint32_t r;
    asm("cvt.rna.tf32.f32 %0, %1;" : "=r"(r) : "f"(v));
    return r;
}
__device__ __forceinline__ float rnd_tf32(float v) {
    return __uint_as_float(f2tf32(v));
}

__device__ __forceinline__ void mma_tf32(float c[4], const uint32_t a[4],
                                         const uint32_t b[2]) {
    asm volatile(
        "mma.sync.aligned.m16n8k8.row.col.f32.tf32.tf32.f32 "
        "{%0,%1,%2,%3}, {%4,%5,%6,%7}, {%8,%9}, {%0,%1,%2,%3};\n"
        : "+f"(c[0]), "+f"(c[1]), "+f"(c[2]), "+f"(c[3])
        : "r"(a[0]), "r"(a[1]), "r"(a[2]), "r"(a[3]), "r"(b[0]), "r"(b[1]));
}

__device__ __forceinline__ void cp_async16(uint32_t dst, const void* src, int szbytes) {
    asm volatile("cp.async.cg.shared.global [%0], [%1], 16, %2;\n"
                 :: "r"(dst), "l"(src), "r"(szbytes));
}
__device__ __forceinline__ void cp_commit() {
    asm volatile("cp.async.commit_group;\n");
}
template <int N>
__device__ __forceinline__ void cp_wait() {
    asm volatile("cp.async.wait_group %0;\n" :: "n"(N));
}

__device__ __forceinline__ float gelu_exact(float v) {
    return 0.5f * v * (1.0f + erff(v * 0.70710678118654752440f));
}

// ---------------- tf32 pre-rounding of a buffer ------------------------------
__global__ __launch_bounds__(256) void round_kernel(
    const float* __restrict__ in, float* __restrict__ out, int n4)
{
    int i = blockIdx.x * 256 + threadIdx.x;
    if (i >= n4) return;
    float4 v = ((const float4*)in)[i];
    v.x = rnd_tf32(v.x); v.y = rnd_tf32(v.y);
    v.z = rnd_tf32(v.z); v.w = rnd_tf32(v.w);
    ((float4*)out)[i] = v;
}

// ---------------- layernorm (exact + rounded outputs) ------------------------
__global__ __launch_bounds__(256) void ln_kernel(
    const float* __restrict__ x, const float* __restrict__ g,
    const float* __restrict__ b, float* __restrict__ out,
    float* __restrict__ out_r, int M)
{
    int row = blockIdx.x;
    if (row >= M) return;
    const float* xr = x + (size_t)row * CDIM;
    int tid = threadIdx.x;
    float v[4];
    float s = 0.f, sq = 0.f;
#pragma unroll
    for (int t = 0; t < 4; t++) {
        float vv = xr[tid + t*256];
        v[t] = vv; s += vv; sq += vv*vv;
    }
    __shared__ float rs[256], rq[256];
    rs[tid] = s; rq[tid] = sq;
    __syncthreads();
    for (int off = 128; off > 0; off >>= 1) {
        if (tid < off) { rs[tid] += rs[tid+off]; rq[tid] += rq[tid+off]; }
        __syncthreads();
    }
    float mean = rs[0] * (1.f/CDIM);
    float var  = rq[0] * (1.f/CDIM) - mean*mean;
    float rstd = rsqrtf(var + 1e-5f);
#pragma unroll
    for (int t = 0; t < 4; t++) {
        int c = tid + t*256;
        float o = (v[t] - mean) * rstd * g[c] + b[c];
        if (out)   out  [(size_t)row * CDIM + c] = o;
        if (out_r) out_r[(size_t)row * CDIM + c] = rnd_tf32(o);
    }
}

// ---------------- fused x2 = outx/size, then LN2 -> rounded h2 ----------------
__global__ __launch_bounds__(256) void divln_kernel(
    const float* __restrict__ g, const float* __restrict__ b, int M)
{
    int row = blockIdx.x;
    if (row >= M) return;
    int tid = threadIdx.x;
    float sdiv = g_outs[row];
    float v[4];
    float s = 0.f, sq = 0.f;
#pragma unroll
    for (int t = 0; t < 4; t++) {
        float vv = g_outx[(size_t)row * CDIM + tid + t*256] / sdiv;
        v[t] = vv; s += vv; sq += vv*vv;
        g_x2[(size_t)row * CDIM + tid + t*256] = vv;
    }
    __shared__ float rs[256], rq[256];
    rs[tid] = s; rq[tid] = sq;
    __syncthreads();
    for (int off = 128; off > 0; off >>= 1) {
        if (tid < off) { rs[tid] += rs[tid+off]; rq[tid] += rq[tid+off]; }
        __syncthreads();
    }
    float mean = rs[0] * (1.f/CDIM);
    float var  = rq[0] * (1.f/CDIM) - mean*mean;
    float rstd = rsqrtf(var + 1e-5f);
#pragma unroll
    for (int t = 0; t < 4; t++) {
        int c = tid + t*256;
        float o = (v[t] - mean) * rstd * g[c] + b[c];
        g_h2[(size_t)row * CDIM + c] = rnd_tf32(o);
    }
}

// ---------------- TF32 tensor-core GEMM, cp.async 4-stage, 64x64 warp tiles --
// 128 threads = 4 warps in 2x2; warp computes 64x64 via 4x8 m16n8k8 frags.
// Inputs must be tf32-representable fp32 (pre-rounded) -> truncation exact.
// EPI: 0 = A@B ; 1 = +bias ; 2 = gelu(+bias) ; 3 = +bias +res
// RND: round output to tf32 (when it feeds another GEMM / attention)
#define GSTAGES 4
#define AS_WORDS (GSTAGES*128*20)
#define BS_WORDS (GSTAGES*16*136)
#define GEMM_SMEM ((AS_WORDS + BS_WORDS) * 4)

template <int EPI, int RND>
__global__ __launch_bounds__(128) void gemm_tf32(
    const float* __restrict__ A, const float* __restrict__ B,
    const float* __restrict__ bias, const float* __restrict__ res,
    float* __restrict__ C, int M, int N, int K)
{
    extern __shared__ uint32_t gsm[];
    uint32_t* As = gsm;              // [s][128][20]
    uint32_t* Bs = gsm + AS_WORDS;   // [s][16][136]

    int tid  = threadIdx.x;
    int lane = tid & 31, wid = tid >> 5;   // 4 warps
    int wm = wid >> 1, wn = wid & 1;       // 2x2
    int g  = lane >> 2, qd = lane & 3;
    int m0 = blockIdx.y * 128, n0 = blockIdx.x * 128;

    float acc[4][8][4];
#pragma unroll
    for (int i = 0; i < 4; i++)
#pragma unroll
        for (int j = 0; j < 8; j++)
#pragma unroll
            for (int r = 0; r < 4; r++) acc[i][j][r] = 0.f;

    const int nT = K >> 4;

    int ar[4], ac[4], br[4], bc[4], aSz[4];
#pragma unroll
    for (int u = 0; u < 4; u++) {
        int idx = u*128 + tid;
        ar[u] = idx >> 2;  ac[u] = (idx & 3) * 4;
        br[u] = idx >> 5;  bc[u] = (idx & 31) * 4;
        aSz[u] = (m0 + ar[u] < M) ? 16 : 0;
    }
    uint32_t asBase = (uint32_t)__cvta_generic_to_shared(As);
    uint32_t bsBase = (uint32_t)__cvta_generic_to_shared(Bs);

#pragma unroll
    for (int t = 0; t < GSTAGES-1; t++) {
        int k0 = t * 16;
#pragma unroll
        for (int u = 0; u < 4; u++) {
            cp_async16(asBase + (uint32_t)(((t*128 + ar[u])*20 + ac[u]) * 4),
                       A + (size_t)(m0 + ar[u]) * K + k0 + ac[u], aSz[u]);
            cp_async16(bsBase + (uint32_t)(((t*16 + br[u])*136 + bc[u]) * 4),
                       B + (size_t)(k0 + br[u]) * N + n0 + bc[u], 16);
        }
        cp_commit();
    }

    for (int t = 0; t < nT; t++) {
        cp_wait<GSTAGES-2>();
        __syncthreads();

        int nxt = t + GSTAGES - 1;
        if (nxt < nT) {
            int s  = nxt % GSTAGES;
            int k0 = nxt * 16;
#pragma unroll
            for (int u = 0; u < 4; u++) {
                cp_async16(asBase + (uint32_t)(((s*128 + ar[u])*20 + ac[u]) * 4),
                           A + (size_t)(m0 + ar[u]) * K + k0 + ac[u], aSz[u]);
                cp_async16(bsBase + (uint32_t)(((s*16 + br[u])*136 + bc[u]) * 4),
                           B + (size_t)(k0 + br[u]) * N + n0 + bc[u], 16);
            }
        }
        cp_commit();

        const uint32_t* Ab = As + (t % GSTAGES) * 128 * 20;
        const uint32_t* Bb = Bs + (t % GSTAGES) * 16 * 136;
#pragma unroll
        for (int ks = 0; ks < 2; ks++) {
            int kb = ks * 8;
            uint32_t af[4][4], bf[8][2];
#pragma unroll
            for (int mf = 0; mf < 4; mf++) {
                int r = wm*64 + mf*16 + g;
                af[mf][0] = Ab[(r    )*20 + kb + qd];
                af[mf][1] = Ab[(r + 8)*20 + kb + qd];
                af[mf][2] = Ab[(r    )*20 + kb + qd + 4];
                af[mf][3] = Ab[(r + 8)*20 + kb + qd + 4];
            }
#pragma unroll
            for (int nf = 0; nf < 8; nf++) {
                int c = wn*64 + nf*8 + g;
                bf[nf][0] = Bb[(kb + qd    )*136 + c];
                bf[nf][1] = Bb[(kb + qd + 4)*136 + c];
            }
#pragma unroll
            for (int mf = 0; mf < 4; mf++)
#pragma unroll
                for (int nf = 0; nf < 8; nf++)
                    mma_tf32(acc[mf][nf], af[mf], bf[nf]);
        }
    }

#pragma unroll
    for (int mf = 0; mf < 4; mf++) {
        int rbase = m0 + wm*64 + mf*16 + g;
#pragma unroll
        for (int half = 0; half < 2; half++) {
            int row = rbase + half*8;
            if (row >= M) continue;
#pragma unroll
            for (int nf = 0; nf < 8; nf++) {
                int col = n0 + wn*64 + nf*8 + 2*qd;
                float v0 = acc[mf][nf][half*2 + 0];
                float v1 = acc[mf][nf][half*2 + 1];
                if (EPI >= 1) { v0 += bias[col]; v1 += bias[col+1]; }
                if (EPI == 2) { v0 = gelu_exact(v0); v1 = gelu_exact(v1); }
                if (EPI == 3) {
                    v0 += res[(size_t)row * N + col];
                    v1 += res[(size_t)row * N + col + 1];
                }
                if (RND) { v0 = rnd_tf32(v0); v1 = rnd_tf32(v1); }
                float2 o; o.x = v0; o.y = v1;
                *(float2*)(C + (size_t)row * N + col) = o;
            }
        }
    }
}

// ---------------- fp32 merge-metric path (exactness firewall) ----------------
__global__ __launch_bounds__(256) void wkavg_kernel(const float* __restrict__ qkv_w)
{
    int idx = blockIdx.x * 256 + threadIdx.x;
    if (idx >= CDIM*DH) return;
    int c = idx >> 6, d = idx & 63;
    const float* base = qkv_w + (size_t)c * (3*CDIM) + CDIM + d;
    float s = 0.f;
#pragma unroll
    for (int h = 0; h < HEADS; h++) s += base[h * DH];
    g_wkavg[idx] = s * (1.f / HEADS);
}

// partial metric = h @ wkavg over K chunk of 128  (split-K x8, fp32 SIMT)
__global__ __launch_bounds__(256) void metric_gemm_kernel()
{
    __shared__ float AsT[32][68];   // [k][tok]
    __shared__ float Bs [32][68];   // [k][d]
    int tid = threadIdx.x;
    int tx = tid & 15, ty = tid >> 4;
    int m0 = blockIdx.x * 64;
    int kb = blockIdx.y * 128;

    float acc[4][4];
#pragma unroll
    for (int i = 0; i < 4; i++)
#pragma unroll
        for (int j = 0; j < 4; j++) acc[i][j] = 0.f;

    for (int k0 = kb; k0 < kb + 128; k0 += 32) {
        __syncthreads();
#pragma unroll
        for (int u = 0; u < 2; u++) {
            int idx = tid*2 + u;
            int tok = idx >> 3, kc = (idx & 7) * 4;
            float4 v = *(const float4*)(g_h + (size_t)(m0 + tok) * CDIM + k0 + kc);
            AsT[kc+0][tok] = v.x; AsT[kc+1][tok] = v.y;
            AsT[kc+2][tok] = v.z; AsT[kc+3][tok] = v.w;
            int kr = idx >> 4, d = (idx & 15) * 4;
            *(float4*)&Bs[kr][d] = *(const float4*)(g_wkavg + (size_t)(k0 + kr) * DH + d);
        }
        __syncthreads();
#pragma unroll
        for (int k = 0; k < 32; k++) {
            float4 a = *(float4*)&AsT[k][ty*4];
            float4 b = *(float4*)&Bs[k][tx*4];
            float aa[4] = {a.x, a.y, a.z, a.w};
            float bb[4] = {b.x, b.y, b.z, b.w};
#pragma unroll
            for (int i = 0; i < 4; i++)
#pragma unroll
                for (int j = 0; j < 4; j++)
                    acc[i][j] = fmaf(aa[i], bb[j], acc[i][j]);
        }
    }
    float* dst = g_mpart + (size_t)blockIdx.y * NTOK * DH;
#pragma unroll
    for (int i = 0; i < 4; i++)
#pragma unroll
        for (int j = 0; j < 4; j++)
            dst[(size_t)(m0 + ty*4 + i) * DH + tx*4 + j] = acc[i][j];
}

// sum 8 partials (fixed order) + row-normalize -> g_nmet
__global__ __launch_bounds__(256) void metric_norm_kernel()
{
    int row = blockIdx.x * 8 + (threadIdx.x >> 5);
    int lane = threadIdx.x & 31;
    size_t off = (size_t)row * DH + lane*2;
    float2 v = *(float2*)&g_mpart[off];
#pragma unroll
    for (int p = 1; p < 8; p++) {
        float2 u = *(float2*)&g_mpart[(size_t)p * NTOK * DH + off];
        v.x += u.x; v.y += u.y;
    }
    float sq = v.x*v.x + v.y*v.y;
#pragma unroll
    for (int o = 16; o > 0; o >>= 1)
        sq += __shfl_xor_sync(0xffffffffu, sq, o);
    float nrm = sqrtf(sq);
    v.x /= nrm; v.y /= nrm;
    *(float2*)&g_nmet[off] = v;
}

// ---------------- tensor-core flash attention (128q x 64k, dh=64) ------------
// 256 threads / 8 warps; warp w owns q rows [w*16, w*16+16).
// K/V tiles stream gmem->smem via cp.async (values already tf32 via QKV RND=1),
// 2-stage double buffer: tile kt+1 loads while tile kt computes.
#define ATP 68   // K/Q/P pitch: frag addr%32 = 4g+qd -> conflict-free
#define VTP 72   // V pitch (token-major): frag addr%32 = 8qd+g -> conflict-free
#define AQ_WORDS (128*ATP)
#define AK_WORDS (64*ATP)
#define AV_WORDS (64*VTP)
#define ATTN_SMEM_B ((AQ_WORDS + 2*AK_WORDS + 2*AV_WORDS + 128*ATP) * 4 + 2*64*4)

__global__ __launch_bounds__(256) void attn_tc_kernel(
    const float* __restrict__ qkv, const float* __restrict__ sizev,
    float* __restrict__ xa)
{
    extern __shared__ uint32_t smu[];
    uint32_t* Qs = smu;                                   // [128][ATP] (scaled 0.125)
    uint32_t* Ks = smu + AQ_WORDS;                        // [2][64][ATP] token-major
    uint32_t* Vs = smu + AQ_WORDS + 2*AK_WORDS;           // [2][64][VTP] token-major
    uint32_t* Ps = smu + AQ_WORDS + 2*AK_WORDS + 2*AV_WORDS; // [128][ATP]
    float* logs  = (float*)(Ps + 128*ATP);                // [2][64]

    int tid  = threadIdx.x;
    int lane = tid & 31, w = tid >> 5;       // 8 warps
    int g = lane >> 2, qd = lane & 3;
    int h = blockIdx.y;
    int q0 = blockIdx.x * 128;
    int wq = w * 16;
    int qrow0 = (wq + g) * ATP, qrow1 = (wq + g + 8) * ATP;

    uint32_t ksBase = (uint32_t)__cvta_generic_to_shared(Ks);
    uint32_t vsBase = (uint32_t)__cvta_generic_to_shared(Vs);

    { // load Q tile (128 rows; values are tf32 already; fold 0.125 then re-round = exact)
        int tok = tid & 127, chunk = tid >> 7;
        const float* src = qkv + (size_t)(q0 + tok) * (3*CDIM) + h*DH + chunk*32;
#pragma unroll
        for (int f = 0; f < 8; f++) {
            float4 v = *(const float4*)(src + f*4);
            uint4 u;
            u.x = f2tf32(v.x * 0.125f); u.y = f2tf32(v.y * 0.125f);
            u.z = f2tf32(v.z * 0.125f); u.w = f2tf32(v.w * 0.125f);
            *(uint4*)&Qs[tok*ATP + chunk*32 + f*4] = u;
        }
    }

    // issue K/V tile kt into stage kt&1 (async) + logs (sync smem store)
    auto issue_tile = [&](int kt) {
        int s = kt & 1;
        int k0 = kt * 64;
        int tok = tid & 63, quad = tid >> 6;
        const float* kbase = qkv + (size_t)(k0 + tok)*(3*CDIM) + CDIM + h*DH;
        const float* vbase = kbase + CDIM;
        uint32_t kdst = ksBase + (uint32_t)((s*AK_WORDS + tok*ATP)*4);
        uint32_t vdst = vsBase + (uint32_t)((s*AV_WORDS + tok*VTP)*4);
#pragma unroll
        for (int f = 0; f < 4; f++) {
            int d0 = quad*16 + f*4;
            cp_async16(kdst + d0*4, kbase + d0, 16);
            cp_async16(vdst + d0*4, vbase + d0, 16);
        }
        cp_commit();
        if (tid < 64) logs[s*64 + tid] = __logf(sizev[k0 + tid]);
    };

    float O[8][4];
#pragma unroll
    for (int dt = 0; dt < 8; dt++)
#pragma unroll
        for (int r = 0; r < 4; r++) O[dt][r] = 0.f;
    float rm0 = -3.0e38f, rm1 = -3.0e38f, rl0 = 0.f, rl1 = 0.f;

    issue_tile(0);

    for (int kt = 0; kt < NTOK/64; kt++) {
        cp_wait<0>();
        __syncthreads();            // tile kt resident; prior-iter reads done
        if (kt + 1 < NTOK/64) issue_tile(kt + 1);

        const uint32_t* Kb = Ks + (kt & 1) * AK_WORDS;
        const uint32_t* Vb = Vs + (kt & 1) * AV_WORDS;
        const float*    lg = logs + (kt & 1) * 64;

        // ---- S = Q @ K^T ----
        float S[8][4];
#pragma unroll
        for (int nt = 0; nt < 8; nt++)
#pragma unroll
            for (int r = 0; r < 4; r++) S[nt][r] = 0.f;
#pragma unroll
        for (int kb = 0; kb < 8; kb++) {
            uint32_t a[4];
            a[0] = Qs[qrow0 + kb*8 + qd];
            a[1] = Qs[qrow1 + kb*8 + qd];
            a[2] = Qs[qrow0 + kb*8 + qd + 4];
            a[3] = Qs[qrow1 + kb*8 + qd + 4];
#pragma unroll
            for (int nt = 0; nt < 8; nt++) {
                uint32_t b[2];
                b[0] = Kb[(nt*8 + g)*ATP + kb*8 + qd];
                b[1] = Kb[(nt*8 + g)*ATP + kb*8 + qd + 4];
                mma_tf32(S[nt], a, b);
            }
        }

        // ---- register online softmax ----
        float m0 = -3.0e38f, m1 = -3.0e38f;
#pragma unroll
        for (int nt = 0; nt < 8; nt++) {
            float l0 = lg[nt*8 + 2*qd], l1 = lg[nt*8 + 2*qd + 1];
            S[nt][0] += l0; S[nt][1] += l1;
            S[nt][2] += l0; S[nt][3] += l1;
            m0 = fmaxf(m0, fmaxf(S[nt][0], S[nt][1]));
            m1 = fmaxf(m1, fmaxf(S[nt][2], S[nt][3]));
        }
#pragma unroll
        for (int off = 1; off < 4; off <<= 1) {
            m0 = fmaxf(m0, __shfl_xor_sync(0xffffffffu, m0, off));
            m1 = fmaxf(m1, __shfl_xor_sync(0xffffffffu, m1, off));
        }
        float n0 = fmaxf(rm0, m0), n1 = fmaxf(rm1, m1);
        float c0 = __expf(rm0 - n0), c1 = __expf(rm1 - n1);
        float s0 = 0.f, s1 = 0.f;
#pragma unroll
        for (int nt = 0; nt < 8; nt++) {
            S[nt][0] = __expf(S[nt][0] - n0);
            S[nt][1] = __expf(S[nt][1] - n0);
            S[nt][2] = __expf(S[nt][2] - n1);
            S[nt][3] = __expf(S[nt][3] - n1);
            s0 += S[nt][0] + S[nt][1];
            s1 += S[nt][2] + S[nt][3];
        }
#pragma unroll
        for (int off = 1; off < 4; off <<= 1) {
            s0 += __shfl_xor_sync(0xffffffffu, s0, off);
            s1 += __shfl_xor_sync(0xffffffffu, s1, off);
        }
        rl0 = rl0 * c0 + s0;  rl1 = rl1 * c1 + s1;
        rm0 = n0; rm1 = n1;
#pragma unroll
        for (int dt = 0; dt < 8; dt++) {
            O[dt][0] *= c0; O[dt][1] *= c0;
            O[dt][2] *= c1; O[dt][3] *= c1;
        }

        // stash P (tf32); consumed only by own warp -> syncwarp suffices
#pragma unroll
        for (int nt = 0; nt < 8; nt++) {
            uint2 u01, u23;
            u01.x = f2tf32(S[nt][0]); u01.y = f2tf32(S[nt][1]);
            u23.x = f2tf32(S[nt][2]); u23.y = f2tf32(S[nt][3]);
            *(uint2*)&Ps[qrow0 + nt*8 + 2*qd] = u01;
            *(uint2*)&Ps[qrow1 + nt*8 + 2*qd] = u23;
        }
        __syncwarp();

        // ---- O += P @ V ----  (V token-major: b[k][n] at (kb*8+qd)*VTP + dt*8+g)
#pragma unroll
        for (int kb = 0; kb < 8; kb++) {
            uint32_t a[4];
            a[0] = Ps[qrow0 + kb*8 + qd];
            a[1] = Ps[qrow1 + kb*8 + qd];
            a[2] = Ps[qrow0 + kb*8 + qd + 4];
            a[3] = Ps[qrow1 + kb*8 + qd + 4];
#pragma unroll
            for (int dt = 0; dt < 8; dt++) {
                uint32_t b[2];
                b[0] = Vb[(kb*8 + qd    )*VTP + dt*8 + g];
                b[1] = Vb[(kb*8 + qd + 4)*VTP + dt*8 + g];
                mma_tf32(O[dt], a, b);
            }
        }
    }

    // epilogue: write tf32-rounded xa (feeds proj GEMM)
    float i0 = 1.f / rl0, i1 = 1.f / rl1;
    int row0 = q0 + wq + g, row1 = row0 + 8;
#pragma unroll
    for (int dt = 0; dt < 8; dt++) {
        int col = h*DH + dt*8 + 2*qd;
        float2 o0; o0.x = rnd_tf32(O[dt][0]*i0); o0.y = rnd_tf32(O[dt][1]*i0);
        float2 o1; o1.x = rnd_tf32(O[dt][2]*i1); o1.y = rnd_tf32(O[dt][3]*i1);
        *(float2*)&xa[(size_t)row0 * CDIM + col] = o0;
        *(float2*)&xa[(size_t)row1 * CDIM + col] = o1;
    }
}

// ---------------- merge scoring: tiled max/argmax over dst -------------------
__global__ __launch_bounds__(256) void merge_score_kernel(const float* __restrict__ thr)
{
    __shared__ float dstm[64*65];
    int tid = threadIdx.x;
    int sl = tid >> 4;        // src local 0..15
    int tg = tid & 15;        // dst group
    int i  = blockIdx.x * 16 + sl;

    float sv[64];
    {
        const float4* sr = (const float4*)(g_nmet + (size_t)(2*i)*DH);
#pragma unroll
        for (int d4 = 0; d4 < 16; d4++) {
            float4 v = sr[d4];
            sv[d4*4+0] = v.x; sv[d4*4+1] = v.y;
            sv[d4*4+2] = v.z; sv[d4*4+3] = v.w;
        }
    }

    float best = -3.0e38f; int bestj = 0;
    for (int jt = 0; jt < NSRC/64; jt++) {
        __syncthreads();
        for (int u = 0; u < 4; u++) {
            int idx = u*256 + tid;
            int r = idx >> 4, dc = (idx & 15) * 4;
            const float4 v = *(const float4*)(g_nmet + (size_t)(2*(jt*64 + r) + 1)*DH + dc);
            float* dst = &dstm[r*65 + dc];
            dst[0] = v.x; dst[1] = v.y; dst[2] = v.z; dst[3] = v.w;
        }
        __syncthreads();
#pragma unroll
        for (int jj = 0; jj < 4; jj++) {
            int rloc = jj*16 + tg;
            const float* dv = &dstm[rloc*65];
            float dot = 0.f;
#pragma unroll
            for (int d = 0; d < 64; d++) dot = fmaf(sv[d], dv[d], dot);
            int j = jt*64 + rloc;
            if (dot > best || (dot == best && j < bestj)) { best = dot; bestj = j; }
        }
    }
#pragma unroll
    for (int off = 1; off < 16; off <<= 1) {
        float ov = __shfl_xor_sync(0xffffffffu, best, off);
        int   oj = __shfl_xor_sync(0xffffffffu, bestj, off);
        if (ov > best || (ov == best && oj < bestj)) { best = ov; bestj = oj; }
    }
    if (tg == 0) {
        if (i == 0) { g_mask[0] = 0; g_node[0] = 0; }   // row 0 forced -inf
        else { g_mask[i] = (best > thr[0]) ? 1 : 0; g_node[i] = bestj; }
    }
}

// ---------------- exclusive prefix scan of !mask -----------------------------
__global__ __launch_bounds__(1024) void scan_kernel()
{
    __shared__ int s[NSRC];
    int tid = threadIdx.x;
    int f = g_mask[tid] ? 0 : 1;
    s[tid] = f;
    __syncthreads();
    for (int off = 1; off < NSRC; off <<= 1) {
        int v = 0;
        if (tid >= off) v = s[tid - off];
        __syncthreads();
        s[tid] += v;
        __syncthreads();
    }
    g_pref[tid] = s[tid] - f;
    if (tid == NSRC-1) g_nUnm[0] = s[NSRC-1];
}

// ---------------- build unmerged rows ----------------------------------------
__global__ __launch_bounds__(256) void unm_kernel(const float* __restrict__ sizev)
{
    int i = blockIdx.x;
    if (g_mask[i]) return;
    int r = g_pref[i];
    float s = sizev[2*i];
    const float* xr = g_x1 + (size_t)(2*i) * CDIM;
    float* orow = g_outx + (size_t)r * CDIM;
    for (int c = threadIdx.x; c < CDIM; c += 256) orow[c] = xr[c] * s;
    if (threadIdx.x == 0) g_outs[r] = s;
}

// ---------------- build dst rows (deterministic gather of merges) ------------
__global__ __launch_bounds__(256) void dst_build_kernel(const float* __restrict__ sizev)
{
    __shared__ int smask[NSRC];
    __shared__ int snode[NSRC];
    int j = blockIdx.x, tid = threadIdx.x;
    for (int i = tid; i < NSRC; i += 256) {
        smask[i] = g_mask[i];
        snode[i] = g_node[i];
    }
    __syncthreads();

    int nU = g_nUnm[0];
    float s0 = sizev[2*j + 1];
    const float* dr = g_x1 + (size_t)(2*j + 1) * CDIM;
    float a0 = dr[tid]       * s0;
    float a1 = dr[tid + 256] * s0;
    float a2 = dr[tid + 512] * s0;
    float a3 = dr[tid + 768] * s0;
    float stot = s0;
    for (int i = 0; i < NSRC; i++) {
        if (smask[i] && snode[i] == j) {
            float si = sizev[2*i];
            const float* xr = g_x1 + (size_t)(2*i) * CDIM;
            a0 += xr[tid]       * si;
            a1 += xr[tid + 256] * si;
            a2 += xr[tid + 512] * si;
            a3 += xr[tid + 768] * si;
            stot += si;
        }
    }
    size_t r = (size_t)(nU + j) * CDIM;
    g_outx[r + tid]       = a0;
    g_outx[r + tid + 256] = a1;
    g_outx[r + tid + 512] = a2;
    g_outx[r + tid + 768] = a3;
    if (tid == 0) g_outs[nU + j] = stot;
}

// ---------------- size tail --------------------------------------------------
__global__ __launch_bounds__(256) void size_tail_kernel(float* __restrict__ out, int Nout)
{
    int i = blockIdx.x * 256 + threadIdx.x;
    if (i < Nout) out[(size_t)Nout * CDIM + i] = g_outs[i];
}

// ---------------- launcher ---------------------------------------------------
extern "C" void kernel_launch(void* const* d_in, const int* in_sizes, int n_in,
                              void* d_out, int out_size)
{
    const float* x      = (const float*)d_in[0];
    const float* sizev  = (const float*)d_in[1];
    const float* qkv_w  = (const float*)d_in[2];
    const float* proj_w = (const float*)d_in[3];
    const float* proj_b = (const float*)d_in[4];
    const float* ln1_g  = (const float*)d_in[5];
    const float* ln1_b  = (const float*)d_in[6];
    const float* ln2_g  = (const float*)d_in[7];
    const float* ln2_b  = (const float*)d_in[8];
    const float* fc1_w  = (const float*)d_in[9];
    const float* fc1_b  = (const float*)d_in[10];
    const float* fc2_w  = (const float*)d_in[11];
    const float* fc2_b  = (const float*)d_in[12];
    const float* thr    = (const float*)d_in[13];
    float* out = (float*)d_out;

    int Nout, packSize;
    if (out_size % (CDIM + 1) == 0) { Nout = out_size / (CDIM + 1); packSize = 1; }
    else                            { Nout = out_size / CDIM;       packSize = 0; }
    if (Nout > NTOK) Nout = NTOK;

    float *p_h, *p_hr, *p_qkv, *p_xa, *p_x1, *p_x2, *p_h2, *p_ff;
    float *p_wqkv, *p_wproj, *p_wfc1, *p_wfc2;
    cudaGetSymbolAddress((void**)&p_h,    g_h);
    cudaGetSymbolAddress((void**)&p_hr,   g_hr);
    cudaGetSymbolAddress((void**)&p_qkv,  g_qkv);
    cudaGetSymbolAddress((void**)&p_xa,   g_xa);
    cudaGetSymbolAddress((void**)&p_x1,   g_x1);
    cudaGetSymbolAddress((void**)&p_x2,   g_x2);
    cudaGetSymbolAddress((void**)&p_h2,   g_h2);
    cudaGetSymbolAddress((void**)&p_ff,   g_ff);
    cudaGetSymbolAddress((void**)&p_wqkv, g_wqkv);
    cudaGetSymbolAddress((void**)&p_wproj,g_wproj);
    cudaGetSymbolAddress((void**)&p_wfc1, g_wfc1);
    cudaGetSymbolAddress((void**)&p_wfc2, g_wfc2);

    cudaFuncSetAttribute(attn_tc_kernel, cudaFuncAttributeMaxDynamicSharedMemorySize, ATTN_SMEM_B);
    cudaFuncSetAttribute(gemm_tf32<0,1>, cudaFuncAttributeMaxDynamicSharedMemorySize, GEMM_SMEM);
    cudaFuncSetAttribute(gemm_tf32<2,1>, cudaFuncAttributeMaxDynamicSharedMemorySize, GEMM_SMEM);
    cudaFuncSetAttribute(gemm_tf32<3,0>, cudaFuncAttributeMaxDynamicSharedMemorySize, GEMM_SMEM);

    // 0. pre-round weights to tf32-representable fp32
    round_kernel<<<(CDIM*3*CDIM/4 + 255)/256, 256>>>(qkv_w,  p_wqkv,  CDIM*3*CDIM/4);
    round_kernel<<<(CDIM*CDIM/4   + 255)/256, 256>>>(proj_w, p_wproj, CDIM*CDIM/4);
    round_kernel<<<(CDIM*FF/4     + 255)/256, 256>>>(fc1_w,  p_wfc1,  CDIM*FF/4);
    round_kernel<<<(FF*CDIM/4     + 255)/256, 256>>>(fc2_w,  p_wfc2,  FF*CDIM/4);
    // 1. LN1: exact h (metric) + rounded hr (GEMM)
    ln_kernel<<<NTOK, 256>>>(x, ln1_g, ln1_b, p_h, p_hr, NTOK);
    // 2a. averaged K-weights (fp32 merge-metric firewall)
    wkavg_kernel<<<(CDIM*DH + 255)/256, 256>>>(qkv_w);
    // 2b. QKV = hr @ wqkv, output rounded to tf32 (identical numerics; enables
    //     raw cp.async K/V in attention)
    gemm_tf32<0,1><<<dim3(3*CDIM/128, NTOK/128), 128, GEMM_SMEM>>>(
        p_hr, p_wqkv, nullptr, nullptr, p_qkv, NTOK, 3*CDIM, CDIM);
    // 3. metric = normalize(h @ wkavg)  (fp32 split-K x8, exact mask decisions)
    metric_gemm_kernel<<<dim3(NTOK/64, 8), 256>>>();
    metric_norm_kernel<<<NTOK/8, 256>>>();
    // 4. attention -> xa (rounded)  (tf32 TC, cp.async double-buffered K/V)
    attn_tc_kernel<<<dim3(NTOK/128, HEADS), 256, ATTN_SMEM_B>>>(p_qkv, sizev, p_xa);
    // 5. x1 = x + xa @ wproj + proj_b  (tf32)
    gemm_tf32<3,0><<<dim3(CDIM/128, NTOK/128), 128, GEMM_SMEM>>>(
        p_xa, p_wproj, proj_b, x, p_x1, NTOK, CDIM, CDIM);
    // 6. merge scores (tiled)
    merge_score_kernel<<<NSRC/16, 256>>>(thr);
    // 7. prefix scan
    scan_kernel<<<1, 1024>>>();
    // 8. unmerged rows
    unm_kernel<<<NSRC, 256>>>(sizev);
    // 9. dst rows
    dst_build_kernel<<<NSRC, 256>>>(sizev);
    // 10+11. fused x2 = outx/size, LN2 -> rounded h2
    divln_kernel<<<Nout, 256>>>(ln2_g, ln2_b, Nout);
    // 12. ff = round(gelu(h2 @ wfc1 + fc1_b))  (tf32)
    gemm_tf32<2,1><<<dim3(FF/128, (Nout + 127)/128), 128, GEMM_SMEM>>>(
        p_h2, p_wfc1, fc1_b, nullptr, p_ff, Nout, FF, CDIM);
    // 13. out = x2 + ff @ wfc2 + fc2_b  (tf32, writes d_out directly)
    gemm_tf32<3,0><<<dim3(CDIM/128, (Nout + 127)/128), 128, GEMM_SMEM>>>(
        p_ff, p_wfc2, fc2_b, p_x2, out, Nout, CDIM, FF);
    // 14. append sizes
    if (packSize)
        size_tail_kernel<<<(Nout + 255)/256, 256>>>(out, Nout);
}

// round 11
// speedup vs baseline: 3.9055x; 1.0172x over previous
#include <cuda_runtime.h>
#include <math.h>
#include <stdint.h>

// Problem constants (fixed shapes from setup_inputs)
#define NTOK 2048
#define CDIM 1024
#define HEADS 16
#define DH 64
#define FF 4096
#define NSRC 1024   // NTOK/2

// ---------------- scratch (device globals; no allocation allowed) ------------
__device__ float g_h    [NTOK*CDIM];
__device__ float g_hr   [NTOK*CDIM];    // tf32-rounded h (GEMM input)
__device__ float g_qkv  [NTOK*3*CDIM];  // tf32-rounded (QKV GEMM RND=1)
__device__ float g_wkavg[CDIM*DH];
__device__ float g_mpart[8*NTOK*DH];
__device__ float g_nmet [NTOK*DH];
__device__ float g_xa   [NTOK*CDIM];    // rounded at attn epilogue
__device__ float g_x1   [NTOK*CDIM];
__device__ int   g_mask [NSRC];
__device__ int   g_node [NSRC];
__device__ int   g_pref [NSRC];
__device__ int   g_nUnm [1];
__device__ float g_outx [NTOK*CDIM];
__device__ float g_outs [NTOK];
__device__ float g_x2   [NTOK*CDIM];
__device__ float g_h2   [NTOK*CDIM];    // rounded at fused div+LN2
__device__ float g_ff   [NTOK*FF];      // rounded at fc1 epilogue
// tf32-rounded weight copies
__device__ float g_wqkv [CDIM*3*CDIM];
__device__ float g_wproj[CDIM*CDIM];
__device__ float g_wfc1 [CDIM*FF];
__device__ float g_wfc2 [FF*CDIM];

// ---------------- helpers ----------------------------------------------------
__device__ __forceinline__ uint32_t f2tf32(float v) {
    uint32_t r;
    asm("cvt.rna.tf32.f32 %0, %1;" : "=r"(r) : "f"(v));
    return r;
}
__device__ __forceinline__ float rnd_tf32(float v) {
    return __uint_as_float(f2tf32(v));
}

__device__ __forceinline__ void mma_tf32(float c[4], const uint32_t a[4],
                                         const uint32_t b[2]) {
    asm volatile(
        "mma.sync.aligned.m16n8k8.row.col.f32.tf32.tf32.f32 "
        "{%0,%1,%2,%3}, {%4,%5,%6,%7}, {%8,%9}, {%0,%1,%2,%3};\n"
        : "+f"(c[0]), "+f"(c[1]), "+f"(c[2]), "+f"(c[3])
        : "r"(a[0]), "r"(a[1]), "r"(a[2]), "r"(a[3]), "r"(b[0]), "r"(b[1]));
}

__device__ __forceinline__ void cp_async16(uint32_t dst, const void* src, int szbytes) {
    asm volatile("cp.async.cg.shared.global [%0], [%1], 16, %2;\n"
                 :: "r"(dst), "l"(src), "r"(szbytes));
}
__device__ __forceinline__ void cp_commit() {
    asm volatile("cp.async.commit_group;\n");
}
template <int N>
__device__ __forceinline__ void cp_wait() {
    asm volatile("cp.async.wait_group %0;\n" :: "n"(N));
}

__device__ __forceinline__ float gelu_exact(float v) {
    return 0.5f * v * (1.0f + erff(v * 0.70710678118654752440f));
}

// ---------------- fused tf32 pre-rounding of all four weight buffers ---------
#define N4_QKV (CDIM*3*CDIM/4)
#define N4_PRJ (CDIM*CDIM/4)
#define N4_FC1 (CDIM*FF/4)
#define N4_FC2 (FF*CDIM/4)
#define N4_ALL (N4_QKV + N4_PRJ + N4_FC1 + N4_FC2)

__global__ __launch_bounds__(256) void round4_kernel(
    const float* __restrict__ w0, const float* __restrict__ w1,
    const float* __restrict__ w2, const float* __restrict__ w3)
{
    int i = blockIdx.x * 256 + threadIdx.x;
    if (i >= N4_ALL) return;
    const float4* src; float4* dst; int off;
    if (i < N4_QKV) {
        src = (const float4*)w0; dst = (float4*)g_wqkv; off = i;
    } else if (i < N4_QKV + N4_PRJ) {
        src = (const float4*)w1; dst = (float4*)g_wproj; off = i - N4_QKV;
    } else if (i < N4_QKV + N4_PRJ + N4_FC1) {
        src = (const float4*)w2; dst = (float4*)g_wfc1; off = i - N4_QKV - N4_PRJ;
    } else {
        src = (const float4*)w3; dst = (float4*)g_wfc2; off = i - N4_QKV - N4_PRJ - N4_FC1;
    }
    float4 v = src[off];
    v.x = rnd_tf32(v.x); v.y = rnd_tf32(v.y);
    v.z = rnd_tf32(v.z); v.w = rnd_tf32(v.w);
    dst[off] = v;
}

// ---------------- layernorm (exact + rounded outputs) ------------------------
__global__ __launch_bounds__(256) void ln_kernel(
    const float* __restrict__ x, const float* __restrict__ g,
    const float* __restrict__ b, float* __restrict__ out,
    float* __restrict__ out_r, int M)
{
    int row = blockIdx.x;
    if (row >= M) return;
    const float* xr = x + (size_t)row * CDIM;
    int tid = threadIdx.x;
    float v[4];
    float s = 0.f, sq = 0.f;
#pragma unroll
    for (int t = 0; t < 4; t++) {
        float vv = xr[tid + t*256];
        v[t] = vv; s += vv; sq += vv*vv;
    }
    __shared__ float rs[256], rq[256];
    rs[tid] = s; rq[tid] = sq;
    __syncthreads();
    for (int off = 128; off > 0; off >>= 1) {
        if (tid < off) { rs[tid] += rs[tid+off]; rq[tid] += rq[tid+off]; }
        __syncthreads();
    }
    float mean = rs[0] * (1.f/CDIM);
    float var  = rq[0] * (1.f/CDIM) - mean*mean;
    float rstd = rsqrtf(var + 1e-5f);
#pragma unroll
    for (int t = 0; t < 4; t++) {
        int c = tid + t*256;
        float o = (v[t] - mean) * rstd * g[c] + b[c];
        if (out)   out  [(size_t)row * CDIM + c] = o;
        if (out_r) out_r[(size_t)row * CDIM + c] = rnd_tf32(o);
    }
}

// ---------------- fused x2 = outx/size, then LN2 -> rounded h2 ----------------
__global__ __launch_bounds__(256) void divln_kernel(
    const float* __restrict__ g, const float* __restrict__ b, int M)
{
    int row = blockIdx.x;
    if (row >= M) return;
    int tid = threadIdx.x;
    float sdiv = g_outs[row];
    float v[4];
    float s = 0.f, sq = 0.f;
#pragma unroll
    for (int t = 0; t < 4; t++) {
        float vv = g_outx[(size_t)row * CDIM + tid + t*256] / sdiv;
        v[t] = vv; s += vv; sq += vv*vv;
        g_x2[(size_t)row * CDIM + tid + t*256] = vv;
    }
    __shared__ float rs[256], rq[256];
    rs[tid] = s; rq[tid] = sq;
    __syncthreads();
    for (int off = 128; off > 0; off >>= 1) {
        if (tid < off) { rs[tid] += rs[tid+off]; rq[tid] += rq[tid+off]; }
        __syncthreads();
    }
    float mean = rs[0] * (1.f/CDIM);
    float var  = rq[0] * (1.f/CDIM) - mean*mean;
    float rstd = rsqrtf(var + 1e-5f);
#pragma unroll
    for (int t = 0; t < 4; t++) {
        int c = tid + t*256;
        float o = (v[t] - mean) * rstd * g[c] + b[c];
        g_h2[(size_t)row * CDIM + c] = rnd_tf32(o);
    }
}

// ---------------- TF32 tensor-core GEMM, cp.async 3-stage, 64x64 warp tiles --
// 128 threads = 4 warps in 2x2; warp computes 64x64 via 4x8 m16n8k8 frags.
// 3 stages -> 56.8KB smem -> 4 CTAs/SM = 592 slots: every GEMM is single-wave.
// Inputs must be tf32-representable fp32 (pre-rounded) -> truncation exact.
// EPI: 0 = A@B ; 1 = +bias ; 2 = gelu(+bias) ; 3 = +bias +res
// RND: round output to tf32 (when it feeds another GEMM / attention)
#define GSTAGES 3
#define AS_WORDS (GSTAGES*128*20)
#define BS_WORDS (GSTAGES*16*136)
#define GEMM_SMEM ((AS_WORDS + BS_WORDS) * 4)

template <int EPI, int RND>
__global__ __launch_bounds__(128) void gemm_tf32(
    const float* __restrict__ A, const float* __restrict__ B,
    const float* __restrict__ bias, const float* __restrict__ res,
    float* __restrict__ C, int M, int N, int K)
{
    extern __shared__ uint32_t gsm[];
    uint32_t* As = gsm;              // [s][128][20]
    uint32_t* Bs = gsm + AS_WORDS;   // [s][16][136]

    int tid  = threadIdx.x;
    int lane = tid & 31, wid = tid >> 5;   // 4 warps
    int wm = wid >> 1, wn = wid & 1;       // 2x2
    int g  = lane >> 2, qd = lane & 3;
    int m0 = blockIdx.y * 128, n0 = blockIdx.x * 128;

    float acc[4][8][4];
#pragma unroll
    for (int i = 0; i < 4; i++)
#pragma unroll
        for (int j = 0; j < 8; j++)
#pragma unroll
            for (int r = 0; r < 4; r++) acc[i][j][r] = 0.f;

    const int nT = K >> 4;

    int ar[4], ac[4], br[4], bc[4], aSz[4];
#pragma unroll
    for (int u = 0; u < 4; u++) {
        int idx = u*128 + tid;
        ar[u] = idx >> 2;  ac[u] = (idx & 3) * 4;
        br[u] = idx >> 5;  bc[u] = (idx & 31) * 4;
        aSz[u] = (m0 + ar[u] < M) ? 16 : 0;
    }
    uint32_t asBase = (uint32_t)__cvta_generic_to_shared(As);
    uint32_t bsBase = (uint32_t)__cvta_generic_to_shared(Bs);

#pragma unroll
    for (int t = 0; t < GSTAGES-1; t++) {
        int k0 = t * 16;
#pragma unroll
        for (int u = 0; u < 4; u++) {
            cp_async16(asBase + (uint32_t)(((t*128 + ar[u])*20 + ac[u]) * 4),
                       A + (size_t)(m0 + ar[u]) * K + k0 + ac[u], aSz[u]);
            cp_async16(bsBase + (uint32_t)(((t*16 + br[u])*136 + bc[u]) * 4),
                       B + (size_t)(k0 + br[u]) * N + n0 + bc[u], 16);
        }
        cp_commit();
    }

    for (int t = 0; t < nT; t++) {
        cp_wait<GSTAGES-2>();
        __syncthreads();

        int nxt = t + GSTAGES - 1;
        if (nxt < nT) {
            int s  = nxt % GSTAGES;
            int k0 = nxt * 16;
#pragma unroll
            for (int u = 0; u < 4; u++) {
                cp_async16(asBase + (uint32_t)(((s*128 + ar[u])*20 + ac[u]) * 4),
                           A + (size_t)(m0 + ar[u]) * K + k0 + ac[u], aSz[u]);
                cp_async16(bsBase + (uint32_t)(((s*16 + br[u])*136 + bc[u]) * 4),
                           B + (size_t)(k0 + br[u]) * N + n0 + bc[u], 16);
            }
        }
        cp_commit();

        const uint32_t* Ab = As + (t % GSTAGES) * 128 * 20;
        const uint32_t* Bb = Bs + (t % GSTAGES) * 16 * 136;
#pragma unroll
        for (int ks = 0; ks < 2; ks++) {
            int kb = ks * 8;
            uint32_t af[4][4], bf[8][2];
#pragma unroll
            for (int mf = 0; mf < 4; mf++) {
                int r = wm*64 + mf*16 + g;
                af[mf][0] = Ab[(r    )*20 + kb + qd];
                af[mf][1] = Ab[(r + 8)*20 + kb + qd];
                af[mf][2] = Ab[(r    )*20 + kb + qd + 4];
                af[mf][3] = Ab[(r + 8)*20 + kb + qd + 4];
            }
#pragma unroll
            for (int nf = 0; nf < 8; nf++) {
                int c = wn*64 + nf*8 + g;
                bf[nf][0] = Bb[(kb + qd    )*136 + c];
                bf[nf][1] = Bb[(kb + qd + 4)*136 + c];
            }
#pragma unroll
            for (int mf = 0; mf < 4; mf++)
#pragma unroll
                for (int nf = 0; nf < 8; nf++)
                    mma_tf32(acc[mf][nf], af[mf], bf[nf]);
        }
    }

#pragma unroll
    for (int mf = 0; mf < 4; mf++) {
        int rbase = m0 + wm*64 + mf*16 + g;
#pragma unroll
        for (int half = 0; half < 2; half++) {
            int row = rbase + half*8;
            if (row >= M) continue;
#pragma unroll
            for (int nf = 0; nf < 8; nf++) {
                int col = n0 + wn*64 + nf*8 + 2*qd;
                float v0 = acc[mf][nf][half*2 + 0];
                float v1 = acc[mf][nf][half*2 + 1];
                if (EPI >= 1) { v0 += bias[col]; v1 += bias[col+1]; }
                if (EPI == 2) { v0 = gelu_exact(v0); v1 = gelu_exact(v1); }
                if (EPI == 3) {
                    v0 += res[(size_t)row * N + col];
                    v1 += res[(size_t)row * N + col + 1];
                }
                if (RND) { v0 = rnd_tf32(v0); v1 = rnd_tf32(v1); }
                float2 o; o.x = v0; o.y = v1;
                *(float2*)(C + (size_t)row * N + col) = o;
            }
        }
    }
}

// ---------------- fp32 merge-metric path (exactness firewall) ----------------
__global__ __launch_bounds__(256) void wkavg_kernel(const float* __restrict__ qkv_w)
{
    int idx = blockIdx.x * 256 + threadIdx.x;
    if (idx >= CDIM*DH) return;
    int c = idx >> 6, d = idx & 63;
    const float* base = qkv_w + (size_t)c * (3*CDIM) + CDIM + d;
    float s = 0.f;
#pragma unroll
    for (int h = 0; h < HEADS; h++) s += base[h * DH];
    g_wkavg[idx] = s * (1.f / HEADS);
}

// partial metric = h @ wkavg over K chunk of 128  (split-K x8, fp32 SIMT)
__global__ __launch_bounds__(256) void metric_gemm_kernel()
{
    __shared__ float AsT[32][68];   // [k][tok]
    __shared__ float Bs [32][68];   // [k][d]
    int tid = threadIdx.x;
    int tx = tid & 15, ty = tid >> 4;
    int m0 = blockIdx.x * 64;
    int kb = blockIdx.y * 128;

    float acc[4][4];
#pragma unroll
    for (int i = 0; i < 4; i++)
#pragma unroll
        for (int j = 0; j < 4; j++) acc[i][j] = 0.f;

    for (int k0 = kb; k0 < kb + 128; k0 += 32) {
        __syncthreads();
#pragma unroll
        for (int u = 0; u < 2; u++) {
            int idx = tid*2 + u;
            int tok = idx >> 3, kc = (idx & 7) * 4;
            float4 v = *(const float4*)(g_h + (size_t)(m0 + tok) * CDIM + k0 + kc);
            AsT[kc+0][tok] = v.x; AsT[kc+1][tok] = v.y;
            AsT[kc+2][tok] = v.z; AsT[kc+3][tok] = v.w;
            int kr = idx >> 4, d = (idx & 15) * 4;
            *(float4*)&Bs[kr][d] = *(const float4*)(g_wkavg + (size_t)(k0 + kr) * DH + d);
        }
        __syncthreads();
#pragma unroll
        for (int k = 0; k < 32; k++) {
            float4 a = *(float4*)&AsT[k][ty*4];
            float4 b = *(float4*)&Bs[k][tx*4];
            float aa[4] = {a.x, a.y, a.z, a.w};
            float bb[4] = {b.x, b.y, b.z, b.w};
#pragma unroll
            for (int i = 0; i < 4; i++)
#pragma unroll
                for (int j = 0; j < 4; j++)
                    acc[i][j] = fmaf(aa[i], bb[j], acc[i][j]);
        }
    }
    float* dst = g_mpart + (size_t)blockIdx.y * NTOK * DH;
#pragma unroll
    for (int i = 0; i < 4; i++)
#pragma unroll
        for (int j = 0; j < 4; j++)
            dst[(size_t)(m0 + ty*4 + i) * DH + tx*4 + j] = acc[i][j];
}

// sum 8 partials (fixed order) + row-normalize -> g_nmet
__global__ __launch_bounds__(256) void metric_norm_kernel()
{
    int row = blockIdx.x * 8 + (threadIdx.x >> 5);
    int lane = threadIdx.x & 31;
    size_t off = (size_t)row * DH + lane*2;
    float2 v = *(float2*)&g_mpart[off];
#pragma unroll
    for (int p = 1; p < 8; p++) {
        float2 u = *(float2*)&g_mpart[(size_t)p * NTOK * DH + off];
        v.x += u.x; v.y += u.y;
    }
    float sq = v.x*v.x + v.y*v.y;
#pragma unroll
    for (int o = 16; o > 0; o >>= 1)
        sq += __shfl_xor_sync(0xffffffffu, sq, o);
    float nrm = sqrtf(sq);
    v.x /= nrm; v.y /= nrm;
    *(float2*)&g_nmet[off] = v;
}

// ---------------- tensor-core flash attention (128q x 64k, dh=64) ------------
// 256 threads / 8 warps; warp w owns q rows [w*16, w*16+16).
// K/V tiles stream gmem->smem via cp.async (values already tf32 via QKV RND=1),
// 2-stage double buffer: tile kt+1 loads while tile kt computes.
#define ATP 68   // K/Q/P pitch: frag addr%32 = 4g+qd -> conflict-free
#define VTP 72   // V pitch (token-major): frag addr%32 = 8qd+g -> conflict-free
#define AQ_WORDS (128*ATP)
#define AK_WORDS (64*ATP)
#define AV_WORDS (64*VTP)
#define ATTN_SMEM_B ((AQ_WORDS + 2*AK_WORDS + 2*AV_WORDS + 128*ATP) * 4 + 2*64*4)

__global__ __launch_bounds__(256) void attn_tc_kernel(
    const float* __restrict__ qkv, const float* __restrict__ sizev,
    float* __restrict__ xa)
{
    extern __shared__ uint32_t smu[];
    uint32_t* Qs = smu;                                   // [128][ATP] (scaled 0.125)
    uint32_t* Ks = smu + AQ_WORDS;                        // [2][64][ATP] token-major
    uint32_t* Vs = smu + AQ_WORDS + 2*AK_WORDS;           // [2][64][VTP] token-major
    uint32_t* Ps = smu + AQ_WORDS + 2*AK_WORDS + 2*AV_WORDS; // [128][ATP]
    float* logs  = (float*)(Ps + 128*ATP);                // [2][64]

    int tid  = threadIdx.x;
    int lane = tid & 31, w = tid >> 5;       // 8 warps
    int g = lane >> 2, qd = lane & 3;
    int h = blockIdx.y;
    int q0 = blockIdx.x * 128;
    int wq = w * 16;
    int qrow0 = (wq + g) * ATP, qrow1 = (wq + g + 8) * ATP;

    uint32_t ksBase = (uint32_t)__cvta_generic_to_shared(Ks);
    uint32_t vsBase = (uint32_t)__cvta_generic_to_shared(Vs);

    { // load Q tile (values tf32 already; fold 0.125 then re-round = exact)
        int tok = tid & 127, chunk = tid >> 7;
        const float* src = qkv + (size_t)(q0 + tok) * (3*CDIM) + h*DH + chunk*32;
#pragma unroll
        for (int f = 0; f < 8; f++) {
            float4 v = *(const float4*)(src + f*4);
            uint4 u;
            u.x = f2tf32(v.x * 0.125f); u.y = f2tf32(v.y * 0.125f);
            u.z = f2tf32(v.z * 0.125f); u.w = f2tf32(v.w * 0.125f);
            *(uint4*)&Qs[tok*ATP + chunk*32 + f*4] = u;
        }
    }

    auto issue_tile = [&](int kt) {
        int s = kt & 1;
        int k0 = kt * 64;
        int tok = tid & 63, quad = tid >> 6;
        const float* kbase = qkv + (size_t)(k0 + tok)*(3*CDIM) + CDIM + h*DH;
        const float* vbase = kbase + CDIM;
        uint32_t kdst = ksBase + (uint32_t)((s*AK_WORDS + tok*ATP)*4);
        uint32_t vdst = vsBase + (uint32_t)((s*AV_WORDS + tok*VTP)*4);
#pragma unroll
        for (int f = 0; f < 4; f++) {
            int d0 = quad*16 + f*4;
            cp_async16(kdst + d0*4, kbase + d0, 16);
            cp_async16(vdst + d0*4, vbase + d0, 16);
        }
        cp_commit();
        if (tid < 64) logs[s*64 + tid] = __logf(sizev[k0 + tid]);
    };

    float O[8][4];
#pragma unroll
    for (int dt = 0; dt < 8; dt++)
#pragma unroll
        for (int r = 0; r < 4; r++) O[dt][r] = 0.f;
    float rm0 = -3.0e38f, rm1 = -3.0e38f, rl0 = 0.f, rl1 = 0.f;

    issue_tile(0);

    for (int kt = 0; kt < NTOK/64; kt++) {
        cp_wait<0>();
        __syncthreads();
        if (kt + 1 < NTOK/64) issue_tile(kt + 1);

        const uint32_t* Kb = Ks + (kt & 1) * AK_WORDS;
        const uint32_t* Vb = Vs + (kt & 1) * AV_WORDS;
        const float*    lg = logs + (kt & 1) * 64;

        // ---- S = Q @ K^T ----
        float S[8][4];
#pragma unroll
        for (int nt = 0; nt < 8; nt++)
#pragma unroll
            for (int r = 0; r < 4; r++) S[nt][r] = 0.f;
#pragma unroll
        for (int kb = 0; kb < 8; kb++) {
            uint32_t a[4];
            a[0] = Qs[qrow0 + kb*8 + qd];
            a[1] = Qs[qrow1 + kb*8 + qd];
            a[2] = Qs[qrow0 + kb*8 + qd + 4];
            a[3] = Qs[qrow1 + kb*8 + qd + 4];
#pragma unroll
            for (int nt = 0; nt < 8; nt++) {
                uint32_t b[2];
                b[0] = Kb[(nt*8 + g)*ATP + kb*8 + qd];
                b[1] = Kb[(nt*8 + g)*ATP + kb*8 + qd + 4];
                mma_tf32(S[nt], a, b);
            }
        }

        // ---- register online softmax ----
        float m0 = -3.0e38f, m1 = -3.0e38f;
#pragma unroll
        for (int nt = 0; nt < 8; nt++) {
            float l0 = lg[nt*8 + 2*qd], l1 = lg[nt*8 + 2*qd + 1];
            S[nt][0] += l0; S[nt][1] += l1;
            S[nt][2] += l0; S[nt][3] += l1;
            m0 = fmaxf(m0, fmaxf(S[nt][0], S[nt][1]));
            m1 = fmaxf(m1, fmaxf(S[nt][2], S[nt][3]));
        }
#pragma unroll
        for (int off = 1; off < 4; off <<= 1) {
            m0 = fmaxf(m0, __shfl_xor_sync(0xffffffffu, m0, off));
            m1 = fmaxf(m1, __shfl_xor_sync(0xffffffffu, m1, off));
        }
        float n0 = fmaxf(rm0, m0), n1 = fmaxf(rm1, m1);
        float c0 = __expf(rm0 - n0), c1 = __expf(rm1 - n1);
        float s0 = 0.f, s1 = 0.f;
#pragma unroll
        for (int nt = 0; nt < 8; nt++) {
            S[nt][0] = __expf(S[nt][0] - n0);
            S[nt][1] = __expf(S[nt][1] - n0);
            S[nt][2] = __expf(S[nt][2] - n1);
            S[nt][3] = __expf(S[nt][3] - n1);
            s0 += S[nt][0] + S[nt][1];
            s1 += S[nt][2] + S[nt][3];
        }
#pragma unroll
        for (int off = 1; off < 4; off <<= 1) {
            s0 += __shfl_xor_sync(0xffffffffu, s0, off);
            s1 += __shfl_xor_sync(0xffffffffu, s1, off);
        }
        rl0 = rl0 * c0 + s0;  rl1 = rl1 * c1 + s1;
        rm0 = n0; rm1 = n1;
#pragma unroll
        for (int dt = 0; dt < 8; dt++) {
            O[dt][0] *= c0; O[dt][1] *= c0;
            O[dt][2] *= c1; O[dt][3] *= c1;
        }

#pragma unroll
        for (int nt = 0; nt < 8; nt++) {
            uint2 u01, u23;
            u01.x = f2tf32(S[nt][0]); u01.y = f2tf32(S[nt][1]);
            u23.x = f2tf32(S[nt][2]); u23.y = f2tf32(S[nt][3]);
            *(uint2*)&Ps[qrow0 + nt*8 + 2*qd] = u01;
            *(uint2*)&Ps[qrow1 + nt*8 + 2*qd] = u23;
        }
        __syncwarp();

        // ---- O += P @ V ----
#pragma unroll
        for (int kb = 0; kb < 8; kb++) {
            uint32_t a[4];
            a[0] = Ps[qrow0 + kb*8 + qd];
            a[1] = Ps[qrow1 + kb*8 + qd];
            a[2] = Ps[qrow0 + kb*8 + qd + 4];
            a[3] = Ps[qrow1 + kb*8 + qd + 4];
#pragma unroll
            for (int dt = 0; dt < 8; dt++) {
                uint32_t b[2];
                b[0] = Vb[(kb*8 + qd    )*VTP + dt*8 + g];
                b[1] = Vb[(kb*8 + qd + 4)*VTP + dt*8 + g];
                mma_tf32(O[dt], a, b);
            }
        }
    }

    // epilogue: write tf32-rounded xa (feeds proj GEMM)
    float i0 = 1.f / rl0, i1 = 1.f / rl1;
    int row0 = q0 + wq + g, row1 = row0 + 8;
#pragma unroll
    for (int dt = 0; dt < 8; dt++) {
        int col = h*DH + dt*8 + 2*qd;
        float2 o0; o0.x = rnd_tf32(O[dt][0]*i0); o0.y = rnd_tf32(O[dt][1]*i0);
        float2 o1; o1.x = rnd_tf32(O[dt][2]*i1); o1.y = rnd_tf32(O[dt][3]*i1);
        *(float2*)&xa[(size_t)row0 * CDIM + col] = o0;
        *(float2*)&xa[(size_t)row1 * CDIM + col] = o1;
    }
}

// ---------------- merge scoring: tiled max/argmax over dst -------------------
__global__ __launch_bounds__(256) void merge_score_kernel(const float* __restrict__ thr)
{
    __shared__ float dstm[64*65];
    int tid = threadIdx.x;
    int sl = tid >> 4;        // src local 0..15
    int tg = tid & 15;        // dst group
    int i  = blockIdx.x * 16 + sl;

    float sv[64];
    {
        const float4* sr = (const float4*)(g_nmet + (size_t)(2*i)*DH);
#pragma unroll
        for (int d4 = 0; d4 < 16; d4++) {
            float4 v = sr[d4];
            sv[d4*4+0] = v.x; sv[d4*4+1] = v.y;
            sv[d4*4+2] = v.z; sv[d4*4+3] = v.w;
        }
    }

    float best = -3.0e38f; int bestj = 0;
    for (int jt = 0; jt < NSRC/64; jt++) {
        __syncthreads();
        for (int u = 0; u < 4; u++) {
            int idx = u*256 + tid;
            int r = idx >> 4, dc = (idx & 15) * 4;
            const float4 v = *(const float4*)(g_nmet + (size_t)(2*(jt*64 + r) + 1)*DH + dc);
            float* dst = &dstm[r*65 + dc];
            dst[0] = v.x; dst[1] = v.y; dst[2] = v.z; dst[3] = v.w;
        }
        __syncthreads();
#pragma unroll
        for (int jj = 0; jj < 4; jj++) {
            int rloc = jj*16 + tg;
            const float* dv = &dstm[rloc*65];
            float dot = 0.f;
#pragma unroll
            for (int d = 0; d < 64; d++) dot = fmaf(sv[d], dv[d], dot);
            int j = jt*64 + rloc;
            if (dot > best || (dot == best && j < bestj)) { best = dot; bestj = j; }
        }
    }
#pragma unroll
    for (int off = 1; off < 16; off <<= 1) {
        float ov = __shfl_xor_sync(0xffffffffu, best, off);
        int   oj = __shfl_xor_sync(0xffffffffu, bestj, off);
        if (ov > best || (ov == best && oj < bestj)) { best = ov; bestj = oj; }
    }
    if (tg == 0) {
        if (i == 0) { g_mask[0] = 0; g_node[0] = 0; }   // row 0 forced -inf
        else { g_mask[i] = (best > thr[0]) ? 1 : 0; g_node[i] = bestj; }
    }
}

// ---------------- exclusive prefix scan of !mask -----------------------------
__global__ __launch_bounds__(1024) void scan_kernel()
{
    __shared__ int s[NSRC];
    int tid = threadIdx.x;
    int f = g_mask[tid] ? 0 : 1;
    s[tid] = f;
    __syncthreads();
    for (int off = 1; off < NSRC; off <<= 1) {
        int v = 0;
        if (tid >= off) v = s[tid - off];
        __syncthreads();
        s[tid] += v;
        __syncthreads();
    }
    g_pref[tid] = s[tid] - f;
    if (tid == NSRC-1) g_nUnm[0] = s[NSRC-1];
}

// ---------------- build unmerged rows ----------------------------------------
__global__ __launch_bounds__(256) void unm_kernel(const float* __restrict__ sizev)
{
    int i = blockIdx.x;
    if (g_mask[i]) return;
    int r = g_pref[i];
    float s = sizev[2*i];
    const float* xr = g_x1 + (size_t)(2*i) * CDIM;
    float* orow = g_outx + (size_t)r * CDIM;
    for (int c = threadIdx.x; c < CDIM; c += 256) orow[c] = xr[c] * s;
    if (threadIdx.x == 0) g_outs[r] = s;
}

// ---------------- build dst rows (deterministic gather of merges) ------------
__global__ __launch_bounds__(256) void dst_build_kernel(const float* __restrict__ sizev)
{
    __shared__ int smask[NSRC];
    __shared__ int snode[NSRC];
    int j = blockIdx.x, tid = threadIdx.x;
    for (int i = tid; i < NSRC; i += 256) {
        smask[i] = g_mask[i];
        snode[i] = g_node[i];
    }
    __syncthreads();

    int nU = g_nUnm[0];
    float s0 = sizev[2*j + 1];
    const float* dr = g_x1 + (size_t)(2*j + 1) * CDIM;
    float a0 = dr[tid]       * s0;
    float a1 = dr[tid + 256] * s0;
    float a2 = dr[tid + 512] * s0;
    float a3 = dr[tid + 768] * s0;
    float stot = s0;
    for (int i = 0; i < NSRC; i++) {
        if (smask[i] && snode[i] == j) {
            float si = sizev[2*i];
            const float* xr = g_x1 + (size_t)(2*i) * CDIM;
            a0 += xr[tid]       * si;
            a1 += xr[tid + 256] * si;
            a2 += xr[tid + 512] * si;
            a3 += xr[tid + 768] * si;
            stot += si;
        }
    }
    size_t r = (size_t)(nU + j) * CDIM;
    g_outx[r + tid]       = a0;
    g_outx[r + tid + 256] = a1;
    g_outx[r + tid + 512] = a2;
    g_outx[r + tid + 768] = a3;
    if (tid == 0) g_outs[nU + j] = stot;
}

// ---------------- size tail --------------------------------------------------
__global__ __launch_bounds__(256) void size_tail_kernel(float* __restrict__ out, int Nout)
{
    int i = blockIdx.x * 256 + threadIdx.x;
    if (i < Nout) out[(size_t)Nout * CDIM + i] = g_outs[i];
}

// ---------------- launcher ---------------------------------------------------
extern "C" void kernel_launch(void* const* d_in, const int* in_sizes, int n_in,
                              void* d_out, int out_size)
{
    const float* x      = (const float*)d_in[0];
    const float* sizev  = (const float*)d_in[1];
    const float* qkv_w  = (const float*)d_in[2];
    const float* proj_w = (const float*)d_in[3];
    const float* proj_b = (const float*)d_in[4];
    const float* ln1_g  = (const float*)d_in[5];
    const float* ln1_b  = (const float*)d_in[6];
    const float* ln2_g  = (const float*)d_in[7];
    const float* ln2_b  = (const float*)d_in[8];
    const float* fc1_w  = (const float*)d_in[9];
    const float* fc1_b  = (const float*)d_in[10];
    const float* fc2_w  = (const float*)d_in[11];
    const float* fc2_b  = (const float*)d_in[12];
    const float* thr    = (const float*)d_in[13];
    float* out = (float*)d_out;

    int Nout, packSize;
    if (out_size % (CDIM + 1) == 0) { Nout = out_size / (CDIM + 1); packSize = 1; }
    else                            { Nout = out_size / CDIM;       packSize = 0; }
    if (Nout > NTOK) Nout = NTOK;

    float *p_h, *p_hr, *p_qkv, *p_xa, *p_x1, *p_x2, *p_h2, *p_ff;
    float *p_wqkv, *p_wproj, *p_wfc1, *p_wfc2;
    cudaGetSymbolAddress((void**)&p_h,    g_h);
    cudaGetSymbolAddress((void**)&p_hr,   g_hr);
    cudaGetSymbolAddress((void**)&p_qkv,  g_qkv);
    cudaGetSymbolAddress((void**)&p_xa,   g_xa);
    cudaGetSymbolAddress((void**)&p_x1,   g_x1);
    cudaGetSymbolAddress((void**)&p_x2,   g_x2);
    cudaGetSymbolAddress((void**)&p_h2,   g_h2);
    cudaGetSymbolAddress((void**)&p_ff,   g_ff);
    cudaGetSymbolAddress((void**)&p_wqkv, g_wqkv);
    cudaGetSymbolAddress((void**)&p_wproj,g_wproj);
    cudaGetSymbolAddress((void**)&p_wfc1, g_wfc1);
    cudaGetSymbolAddress((void**)&p_wfc2, g_wfc2);

    cudaFuncSetAttribute(attn_tc_kernel, cudaFuncAttributeMaxDynamicSharedMemorySize, ATTN_SMEM_B);
    cudaFuncSetAttribute(gemm_tf32<0,1>, cudaFuncAttributeMaxDynamicSharedMemorySize, GEMM_SMEM);
    cudaFuncSetAttribute(gemm_tf32<2,1>, cudaFuncAttributeMaxDynamicSharedMemorySize, GEMM_SMEM);
    cudaFuncSetAttribute(gemm_tf32<3,0>, cudaFuncAttributeMaxDynamicSharedMemorySize, GEMM_SMEM);

    // 0. pre-round all four weight matrices (single fused launch)
    round4_kernel<<<(N4_ALL + 255)/256, 256>>>(qkv_w, proj_w, fc1_w, fc2_w);
    // 1. LN1: exact h (metric) + rounded hr (GEMM)
    ln_kernel<<<NTOK, 256>>>(x, ln1_g, ln1_b, p_h, p_hr, NTOK);
    // 2a. averaged K-weights (fp32 merge-metric firewall)
    wkavg_kernel<<<(CDIM*DH + 255)/256, 256>>>(qkv_w);
    // 2b. QKV = hr @ wqkv, output rounded to tf32
    gemm_tf32<0,1><<<dim3(3*CDIM/128, NTOK/128), 128, GEMM_SMEM>>>(
        p_hr, p_wqkv, nullptr, nullptr, p_qkv, NTOK, 3*CDIM, CDIM);
    // 3. metric = normalize(h @ wkavg)  (fp32 split-K x8, exact mask decisions)
    metric_gemm_kernel<<<dim3(NTOK/64, 8), 256>>>();
    metric_norm_kernel<<<NTOK/8, 256>>>();
    // 4. attention -> xa (rounded)  (tf32 TC, cp.async double-buffered K/V)
    attn_tc_kernel<<<dim3(NTOK/128, HEADS), 256, ATTN_SMEM_B>>>(p_qkv, sizev, p_xa);
    // 5. x1 = x + xa @ wproj + proj_b  (tf32)
    gemm_tf32<3,0><<<dim3(CDIM/128, NTOK/128), 128, GEMM_SMEM>>>(
        p_xa, p_wproj, proj_b, x, p_x1, NTOK, CDIM, CDIM);
    // 6. merge scores (tiled)
    merge_score_kernel<<<NSRC/16, 256>>>(thr);
    // 7. prefix scan
    scan_kernel<<<1, 1024>>>();
    // 8. unmerged rows
    unm_kernel<<<NSRC, 256>>>(sizev);
    // 9. dst rows
    dst_build_kernel<<<NSRC, 256>>>(sizev);
    // 10+11. fused x2 = outx/size, LN2 -> rounded h2
    divln_kernel<<<Nout, 256>>>(ln2_g, ln2_b, Nout);
    // 12. ff = round(gelu(h2 @ wfc1 + fc1_b))  (tf32)
    gemm_tf32<2,1><<<dim3(FF/128, (Nout + 127)/128), 128, GEMM_SMEM>>>(
        p_h2, p_wfc1, fc1_b, nullptr, p_ff, Nout, FF, CDIM);
    // 13. out = x2 + ff @ wfc2 + fc2_b  (tf32, writes d_out directly)
    gemm_tf32<3,0><<<dim3(CDIM/128, (Nout + 127)/128), 128, GEMM_SMEM>>>(
        p_ff, p_wfc2, fc2_b, p_x2, out, Nout, CDIM, FF);
    // 14. append sizes
    if (packSize)
        size_tail_kernel<<<(Nout + 255)/256, 256>>>(out, Nout);
}